// round 11
// baseline (speedup 1.0000x reference)
#include <cuda_runtime.h>
#include <cuda_bf16.h>
#include <math.h>
#include <stdint.h>

#define NROWS 8192
#define DDIM  512
#define EPS   1e-5f

// ================= PTX helpers =================
__device__ __forceinline__ uint32_t smem_u32(const void* p) {
    uint32_t a;
    asm("{ .reg .u64 t; cvta.to.shared.u64 t, %1; cvt.u32.u64 %0, t; }" : "=r"(a) : "l"(p));
    return a;
}
#define CP_ASYNC16(smem, gptr) \
    asm volatile("cp.async.cg.shared.global [%0], [%1], 16;" :: "r"(smem), "l"(gptr))
#define CP_COMMIT() asm volatile("cp.async.commit_group;" ::: "memory")
#define CP_WAIT(n)  asm volatile("cp.async.wait_group %0;" :: "n"(n) : "memory")

#define LDMX4(r, addr) \
    asm volatile("ldmatrix.sync.aligned.m8n8.x4.shared.b16 {%0,%1,%2,%3}, [%4];" \
        : "=r"((r)[0]), "=r"((r)[1]), "=r"((r)[2]), "=r"((r)[3]) : "r"(addr))

#define MMA16816(d, a, b0, b1) \
    asm volatile("mma.sync.aligned.m16n8k16.row.col.f32.bf16.bf16.f32 " \
        "{%0,%1,%2,%3}, {%4,%5,%6,%7}, {%8,%9}, {%0,%1,%2,%3};" \
        : "+f"((d)[0]), "+f"((d)[1]), "+f"((d)[2]), "+f"((d)[3]) \
        : "r"((a)[0]), "r"((a)[1]), "r"((a)[2]), "r"((a)[3]), "r"(b0), "r"(b1))

// ================= scratch =================
__device__ float g_q  [NROWS * DDIM];
__device__ float g_k  [NROWS * DDIM];
__device__ __nv_bfloat16 g_sh1[NROWS * DDIM];
__device__ __nv_bfloat16 g_sl1[NROWS * DDIM];
__device__ __nv_bfloat16 g_sh2[NROWS * DDIM];
__device__ __nv_bfloat16 g_sl2[NROWS * DDIM];
__device__ __nv_bfloat16 g_wh[4][DDIM * DDIM];
__device__ __nv_bfloat16 g_wl[4][DDIM * DDIM];
__device__ int   g_segs[NROWS];
__device__ int   g_sege[NROWS];

// ================= reductions =================
__device__ __forceinline__ float warpSum(float v) {
    #pragma unroll
    for (int o = 16; o > 0; o >>= 1) v += __shfl_xor_sync(0xffffffffu, v, o);
    return v;
}

// ================= split helpers =================
__device__ __forceinline__ void split2(float v, __nv_bfloat16& hi, __nv_bfloat16& lo) {
    hi = __float2bfloat16(v);
    lo = __float2bfloat16(v - __bfloat162float(hi));
}

// ================= fused weight-split + segment kernel =================
// blocks [0,1024): weight fp32->bf16 hi/lo for all 4 weights
// blocks [1024,1056): segment bounds via binary search on batch
__global__ __launch_bounds__(256) void wsplit_seg(const float* __restrict__ W1,
                                                  const float* __restrict__ W2,
                                                  const float* __restrict__ W3,
                                                  const float* __restrict__ W4,
                                                  __nv_bfloat16* __restrict__ wh,
                                                  __nv_bfloat16* __restrict__ wl,
                                                  const int* __restrict__ p) {
    if (blockIdx.x < 1024) {
        int id = blockIdx.x * 256 + threadIdx.x;
        int w = id >> 16;
        int j = id & 65535;
        const float* src = (w == 0) ? W1 : (w == 1) ? W2 : (w == 2) ? W3 : W4;
        float4 v = ((const float4*)src)[j];
        __nv_bfloat16 h0, l0, h1, l1, h2, l2, h3, l3;
        split2(v.x, h0, l0); split2(v.y, h1, l1);
        split2(v.z, h2, l2); split2(v.w, h3, l3);
        size_t base = (size_t)w * DDIM * DDIM + (size_t)j * 4;
        __nv_bfloat162* ph = (__nv_bfloat162*)(wh + base);
        __nv_bfloat162* pl = (__nv_bfloat162*)(wl + base);
        ph[0] = __nv_bfloat162(h0, h1); ph[1] = __nv_bfloat162(h2, h3);
        pl[0] = __nv_bfloat162(l0, l1); pl[1] = __nv_bfloat162(l2, l3);
    } else {
        int i = (blockIdx.x - 1024) * 256 + threadIdx.x;
        if (i >= NROWS) return;
        const int is64 = (__ldg(p + (NROWS - 1)) == 0);
        #define GETB(idx) (is64 ? __ldg(p + 2 * (idx)) : __ldg(p + (idx)))
        int v = GETB(i);
        int lo = 0, hi = NROWS;
        while (lo < hi) { int mid = (lo + hi) >> 1; if (GETB(mid) < v) lo = mid + 1; else hi = mid; }
        g_segs[i] = lo;
        lo = 0; hi = NROWS;
        while (lo < hi) { int mid = (lo + hi) >> 1; if (GETB(mid) <= v) lo = mid + 1; else hi = mid; }
        g_sege[i] = lo;
        #undef GETB
    }
}

// ================= LayerNorm+split (both inputs, gridDim.y=2) =================
__global__ __launch_bounds__(256) void ln_split2(const float* __restrict__ xa,
                                                 const float* __restrict__ wa,
                                                 const float* __restrict__ ba,
                                                 __nv_bfloat16* __restrict__ sha,
                                                 __nv_bfloat16* __restrict__ sla,
                                                 const float* __restrict__ xb,
                                                 const float* __restrict__ wb,
                                                 const float* __restrict__ bb,
                                                 __nv_bfloat16* __restrict__ shb,
                                                 __nv_bfloat16* __restrict__ slb) {
    const float* x = (blockIdx.y == 0) ? xa : xb;
    const float* w = (blockIdx.y == 0) ? wa : wb;
    const float* b = (blockIdx.y == 0) ? ba : bb;
    __nv_bfloat16* sh_ = (blockIdx.y == 0) ? sha : shb;
    __nv_bfloat16* sl_ = (blockIdx.y == 0) ? sla : slb;

    __shared__ float red[2][4];
    const int half = threadIdx.x >> 7;
    const int t    = threadIdx.x & 127;
    const int lane = threadIdx.x & 31;
    const int w4   = (threadIdx.x >> 5) & 3;
    const int row  = blockIdx.x * 2 + half;
    float4 v = ((const float4*)(x + (size_t)row * DDIM))[t];
    float ps = warpSum(v.x + v.y + v.z + v.w);
    if (lane == 0) red[half][w4] = ps;
    __syncthreads();
    float mu = (red[half][0] + red[half][1] + red[half][2] + red[half][3]) * (1.0f / DDIM);
    __syncthreads();
    float dx = v.x - mu, dy = v.y - mu, dz = v.z - mu, dw = v.w - mu;
    float pv = warpSum(dx * dx + dy * dy + dz * dz + dw * dw);
    if (lane == 0) red[half][w4] = pv;
    __syncthreads();
    float var = (red[half][0] + red[half][1] + red[half][2] + red[half][3]) * (1.0f / DDIM);
    float r = rsqrtf(var + EPS);
    float4 wv = ((const float4*)w)[t];
    float4 bv = ((const float4*)b)[t];
    float y0 = dx * r * wv.x + bv.x;
    float y1 = dy * r * wv.y + bv.y;
    float y2 = dz * r * wv.z + bv.z;
    float y3 = dw * r * wv.w + bv.w;
    __nv_bfloat16 h0, l0, h1, l1, h2, l2, h3, l3;
    split2(y0, h0, l0); split2(y1, h1, l1);
    split2(y2, h2, l2); split2(y3, h3, l3);
    size_t o = (size_t)row * DDIM + t * 4;
    __nv_bfloat162* ph = (__nv_bfloat162*)(sh_ + o);
    __nv_bfloat162* pl = (__nv_bfloat162*)(sl_ + o);
    ph[0] = __nv_bfloat162(h0, h1); ph[1] = __nv_bfloat162(h2, h3);
    pl[0] = __nv_bfloat162(l0, l1); pl[1] = __nv_bfloat162(l2, l3);
}

__global__ __launch_bounds__(256) void ln_kernel(const float* __restrict__ x,
                                                 const float* __restrict__ w,
                                                 const float* __restrict__ b,
                                                 float* __restrict__ y) {
    __shared__ float red[2][4];
    const int half = threadIdx.x >> 7;
    const int t    = threadIdx.x & 127;
    const int lane = threadIdx.x & 31;
    const int w4   = (threadIdx.x >> 5) & 3;
    const int row  = blockIdx.x * 2 + half;
    float4 v = ((const float4*)(x + (size_t)row * DDIM))[t];
    float ps = warpSum(v.x + v.y + v.z + v.w);
    if (lane == 0) red[half][w4] = ps;
    __syncthreads();
    float mu = (red[half][0] + red[half][1] + red[half][2] + red[half][3]) * (1.0f / DDIM);
    __syncthreads();
    float dx = v.x - mu, dy = v.y - mu, dz = v.z - mu, dw = v.w - mu;
    float pv = warpSum(dx * dx + dy * dy + dz * dz + dw * dw);
    if (lane == 0) red[half][w4] = pv;
    __syncthreads();
    float var = (red[half][0] + red[half][1] + red[half][2] + red[half][3]) * (1.0f / DDIM);
    float r = rsqrtf(var + EPS);
    float4 wv = ((const float4*)w)[t];
    float4 bv = ((const float4*)b)[t];
    float4 o;
    o.x = dx * r * wv.x + bv.x;
    o.y = dy * r * wv.y + bv.y;
    o.z = dz * r * wv.z + bv.z;
    o.w = dw * r * wv.w + bv.w;
    ((float4*)(y + (size_t)row * DDIM))[t] = o;
}

// ================= mma.sync bf16-split GEMM (BK=64, 16 warps, merged z) =================
#define GM_STAGE 65536
#define GM_SMEM  (3 * GM_STAGE)

__device__ __forceinline__ uint32_t swz(int row, int c16) {
    return (uint32_t)(row * 128 + ((c16 ^ (row & 7)) << 4));
}
__device__ __forceinline__ float silu_f(float v) { return v / (1.0f + expf(-v)); }

__global__ __launch_bounds__(512, 1) void gemm_mma(const __nv_bfloat16* Ah,
                                                   const __nv_bfloat16* Al,
                                                   const __nv_bfloat16* Bh,
                                                   const __nv_bfloat16* Bl,
                                                   float* C,
                                                   const __nv_bfloat16* Ah2,
                                                   const __nv_bfloat16* Al2,
                                                   const __nv_bfloat16* Bh2,
                                                   const __nv_bfloat16* Bl2,
                                                   float* C2,
                                                   const float* bias,
                                                   __nv_bfloat16* oh,
                                                   __nv_bfloat16* ol,
                                                   int mode) {
    if (blockIdx.z == 1) { Ah = Ah2; Al = Al2; Bh = Bh2; Bl = Bl2; C = C2; }
    extern __shared__ char smem[];
    const uint32_t sbase = smem_u32(smem);
    const int tid  = threadIdx.x;
    const int lane = tid & 31;
    const int wid  = tid >> 5;
    const int wm   = wid >> 2;
    const int wn   = wid & 3;
    const int bm   = blockIdx.y * 128;
    const int bn   = blockIdx.x * 128;

    float acc[2][4][4];
    #pragma unroll
    for (int mi = 0; mi < 2; mi++)
        #pragma unroll
        for (int nj = 0; nj < 4; nj++)
            #pragma unroll
            for (int c = 0; c < 4; c++) acc[mi][nj][c] = 0.0f;

    const int lr0 = tid >> 3,         lc0 = tid & 7;
    const int lr1 = (tid + 512) >> 3, lc1 = (tid + 512) & 7;
    const uint32_t so0 = swz(lr0, lc0), so1 = swz(lr1, lc1);

    const int arow = (lane & 15);
    const int acol = (lane >> 4);
    const int brow = (lane & 7) + ((lane >> 4) & 1) * 8;
    const int bcol = (lane >> 3) & 1;

    #define GM_ISSUE(st, kt) do { \
        uint32_t sb_ = sbase + (st) * GM_STAGE; \
        int k0_ = (kt) * 64; \
        size_t ga0 = (size_t)(bm + lr0) * DDIM + k0_ + lc0 * 8; \
        size_t gb0 = (size_t)(bn + lr0) * DDIM + k0_ + lc0 * 8; \
        size_t ga1 = (size_t)(bm + lr1) * DDIM + k0_ + lc1 * 8; \
        size_t gb1 = (size_t)(bn + lr1) * DDIM + k0_ + lc1 * 8; \
        CP_ASYNC16(sb_ + so0,          Ah + ga0); \
        CP_ASYNC16(sb_ + 16384 + so0,  Al + ga0); \
        CP_ASYNC16(sb_ + 32768 + so0,  Bh + gb0); \
        CP_ASYNC16(sb_ + 49152 + so0,  Bl + gb0); \
        CP_ASYNC16(sb_ + so1,          Ah + ga1); \
        CP_ASYNC16(sb_ + 16384 + so1,  Al + ga1); \
        CP_ASYNC16(sb_ + 32768 + so1,  Bh + gb1); \
        CP_ASYNC16(sb_ + 49152 + so1,  Bl + gb1); \
    } while (0)

    GM_ISSUE(0, 0); CP_COMMIT();
    GM_ISSUE(1, 1); CP_COMMIT();

    for (int kt = 0; kt < 8; kt++) {
        if (kt < 6) CP_WAIT(1); else CP_WAIT(0);
        __syncthreads();
        const uint32_t sb = sbase + (kt % 3) * GM_STAGE;

        #pragma unroll
        for (int ks = 0; ks < 4; ks++) {
            uint32_t fah[2][4], fal[2][4];
            #pragma unroll
            for (int mi = 0; mi < 2; mi++) {
                uint32_t off = swz(wm * 32 + mi * 16 + arow, ks * 2 + acol);
                LDMX4(fah[mi], sb + off);
                LDMX4(fal[mi], sb + 16384 + off);
            }
            #pragma unroll
            for (int njp = 0; njp < 4; njp += 2) {
                uint32_t off = swz(wn * 32 + njp * 8 + brow, ks * 2 + bcol);
                uint32_t fbh[4], fbl[4];
                LDMX4(fbh, sb + 32768 + off);
                LDMX4(fbl, sb + 49152 + off);
                #pragma unroll
                for (int mi = 0; mi < 2; mi++) {
                    MMA16816(acc[mi][njp],     fah[mi], fbh[0], fbh[1]);
                    MMA16816(acc[mi][njp + 1], fah[mi], fbh[2], fbh[3]);
                    MMA16816(acc[mi][njp],     fah[mi], fbl[0], fbl[1]);
                    MMA16816(acc[mi][njp + 1], fah[mi], fbl[2], fbl[3]);
                    MMA16816(acc[mi][njp],     fal[mi], fbh[0], fbh[1]);
                    MMA16816(acc[mi][njp + 1], fal[mi], fbh[2], fbh[3]);
                }
            }
        }
        if (kt + 2 < 8) { GM_ISSUE((kt + 2) % 3, kt + 2); CP_COMMIT(); }
    }

    const int erow = lane >> 2;
    const int ecol = (lane & 3) * 2;
    #pragma unroll
    for (int mi = 0; mi < 2; mi++) {
        #pragma unroll
        for (int nj = 0; nj < 4; nj++) {
            int m0 = bm + wm * 32 + mi * 16 + erow;
            int n0 = bn + wn * 32 + nj * 8 + ecol;
            float2 v0 = make_float2(acc[mi][nj][0], acc[mi][nj][1]);
            float2 v1 = make_float2(acc[mi][nj][2], acc[mi][nj][3]);
            if (mode == 0) {
                *(float2*)(C + (size_t)m0 * DDIM + n0)       = v0;
                *(float2*)(C + (size_t)(m0 + 8) * DDIM + n0) = v1;
            } else {
                float2 bv = *(const float2*)(bias + n0);
                v0.x = silu_f(v0.x + bv.x); v0.y = silu_f(v0.y + bv.y);
                v1.x = silu_f(v1.x + bv.x); v1.y = silu_f(v1.y + bv.y);
                if (mode == 2) {
                    *(float2*)(C + (size_t)m0 * DDIM + n0)       = v0;
                    *(float2*)(C + (size_t)(m0 + 8) * DDIM + n0) = v1;
                } else {
                    __nv_bfloat16 h0, l0, h1, l1;
                    split2(v0.x, h0, l0); split2(v0.y, h1, l1);
                    *(__nv_bfloat162*)(oh + (size_t)m0 * DDIM + n0) = __nv_bfloat162(h0, h1);
                    *(__nv_bfloat162*)(ol + (size_t)m0 * DDIM + n0) = __nv_bfloat162(l0, l1);
                    split2(v1.x, h0, l0); split2(v1.y, h1, l1);
                    *(__nv_bfloat162*)(oh + (size_t)(m0 + 8) * DDIM + n0) = __nv_bfloat162(h0, h1);
                    *(__nv_bfloat162*)(ol + (size_t)(m0 + 8) * DDIM + n0) = __nv_bfloat162(l0, l1);
                }
            }
        }
    }
}

// ================= tiled attention =================
#define AT_TILE  32
#define AT_SMEM  (AT_TILE * DDIM * 4)

__global__ __launch_bounds__(512) void attn_softmax16(const float* __restrict__ q,
                                                      const float* __restrict__ kmat,
                                                      float* __restrict__ attn) {
    extern __shared__ float ktile[];
    const int tid = threadIdx.x, wid = tid >> 5, lane = tid & 31;
    const int i = blockIdx.x * 16 + wid;
    const int s = g_segs[i], e = g_sege[i];
    const int sb = g_segs[blockIdx.x * 16];
    const int eb = g_sege[blockIdx.x * 16 + 15];

    float* row = attn + (size_t)i * NROWS;

    // zero-fill outside [s, e): float4 body + scalar edges; drains behind compute
    {
        const float4 z4 = make_float4(0.f, 0.f, 0.f, 0.f);
        int s4 = s >> 2;
        for (int j = lane; j < s4; j += 32) ((float4*)row)[j] = z4;
        for (int j = (s4 << 2) + lane; j < s; j += 32) row[j] = 0.0f;
        int e4 = (e + 3) >> 2;
        for (int j = e + lane; j < (e4 << 2); j += 32) row[j] = 0.0f;
        for (int j = e4 + lane; j < (NROWS >> 2); j += 32) ((float4*)row)[j] = z4;
    }

    const float* qr = q + (size_t)i * DDIM;
    float4 qv[4];
    #pragma unroll
    for (int c = 0; c < 4; c++) qv[c] = *(const float4*)(qr + c * 128 + lane * 4);

    float m = 0.0f;
    for (int t = sb; t < eb; t += AT_TILE) {
        const int tn = min(AT_TILE, eb - t);
        __syncthreads();
        for (int idx = tid; idx < tn * 128; idx += 512) {
            int r = idx >> 7, c = idx & 127;
            *(float4*)(ktile + r * DDIM + c * 4) = *(const float4*)(kmat + (size_t)(t + r) * DDIM + c * 4);
        }
        __syncthreads();
        const int j0 = max(s, t), j1 = min(e, t + tn);
        int j = j0;
        // unroll x2: two independent dot+warpSum chains hide SHFL latency
        for (; j + 1 < j1; j += 2) {
            const float* kr0 = ktile + (j - t) * DDIM;
            const float* kr1 = kr0 + DDIM;
            float d0, d1;
            {
                float4 a0 = *(const float4*)(kr0 + 0 * 128 + lane * 4);
                float4 a1 = *(const float4*)(kr0 + 1 * 128 + lane * 4);
                float4 a2 = *(const float4*)(kr0 + 2 * 128 + lane * 4);
                float4 a3 = *(const float4*)(kr0 + 3 * 128 + lane * 4);
                d0 = qv[0].x * a0.x;
                d0 = fmaf(qv[0].y, a0.y, d0); d0 = fmaf(qv[0].z, a0.z, d0); d0 = fmaf(qv[0].w, a0.w, d0);
                d0 = fmaf(qv[1].x, a1.x, d0); d0 = fmaf(qv[1].y, a1.y, d0); d0 = fmaf(qv[1].z, a1.z, d0); d0 = fmaf(qv[1].w, a1.w, d0);
                d0 = fmaf(qv[2].x, a2.x, d0); d0 = fmaf(qv[2].y, a2.y, d0); d0 = fmaf(qv[2].z, a2.z, d0); d0 = fmaf(qv[2].w, a2.w, d0);
                d0 = fmaf(qv[3].x, a3.x, d0); d0 = fmaf(qv[3].y, a3.y, d0); d0 = fmaf(qv[3].z, a3.z, d0); d0 = fmaf(qv[3].w, a3.w, d0);
            }
            {
                float4 a0 = *(const float4*)(kr1 + 0 * 128 + lane * 4);
                float4 a1 = *(const float4*)(kr1 + 1 * 128 + lane * 4);
                float4 a2 = *(const float4*)(kr1 + 2 * 128 + lane * 4);
                float4 a3 = *(const float4*)(kr1 + 3 * 128 + lane * 4);
                d1 = qv[0].x * a0.x;
                d1 = fmaf(qv[0].y, a0.y, d1); d1 = fmaf(qv[0].z, a0.z, d1); d1 = fmaf(qv[0].w, a0.w, d1);
                d1 = fmaf(qv[1].x, a1.x, d1); d1 = fmaf(qv[1].y, a1.y, d1); d1 = fmaf(qv[1].z, a1.z, d1); d1 = fmaf(qv[1].w, a1.w, d1);
                d1 = fmaf(qv[2].x, a2.x, d1); d1 = fmaf(qv[2].y, a2.y, d1); d1 = fmaf(qv[2].z, a2.z, d1); d1 = fmaf(qv[2].w, a2.w, d1);
                d1 = fmaf(qv[3].x, a3.x, d1); d1 = fmaf(qv[3].y, a3.y, d1); d1 = fmaf(qv[3].z, a3.z, d1); d1 = fmaf(qv[3].w, a3.w, d1);
            }
            d0 = warpSum(d0);
            d1 = warpSum(d1);
            if (lane == 0) { row[j] = d0; row[j + 1] = d1; }
            m = fmaxf(m, fmaxf(d0, d1));
        }
        if (j < j1) {
            const float* kr = ktile + (j - t) * DDIM;
            float4 a0 = *(const float4*)(kr + 0 * 128 + lane * 4);
            float4 a1 = *(const float4*)(kr + 1 * 128 + lane * 4);
            float4 a2 = *(const float4*)(kr + 2 * 128 + lane * 4);
            float4 a3 = *(const float4*)(kr + 3 * 128 + lane * 4);
            float d = qv[0].x * a0.x;
            d = fmaf(qv[0].y, a0.y, d); d = fmaf(qv[0].z, a0.z, d); d = fmaf(qv[0].w, a0.w, d);
            d = fmaf(qv[1].x, a1.x, d); d = fmaf(qv[1].y, a1.y, d); d = fmaf(qv[1].z, a1.z, d); d = fmaf(qv[1].w, a1.w, d);
            d = fmaf(qv[2].x, a2.x, d); d = fmaf(qv[2].y, a2.y, d); d = fmaf(qv[2].z, a2.z, d); d = fmaf(qv[2].w, a2.w, d);
            d = fmaf(qv[3].x, a3.x, d); d = fmaf(qv[3].y, a3.y, d); d = fmaf(qv[3].z, a3.z, d); d = fmaf(qv[3].w, a3.w, d);
            d = warpSum(d);
            if (lane == 0) row[j] = d;
            m = fmaxf(m, d);
        }
    }
    m = fmaxf(m, 0.0f);   // reference: max over dot*mask includes zeros

    float ssum = 0.0f;
    for (int j = s + lane; j < e; j += 32) {
        float ev = expf(row[j] - m);
        ssum += ev;
        row[j] = ev;
    }
    ssum = warpSum(ssum);
    float inv = 1.0f / ssum;
    for (int j = s + lane; j < e; j += 32) row[j] *= inv;
}

__global__ __launch_bounds__(512) void attn_apply16(const float* __restrict__ attn,
                                                    const float* __restrict__ xc,
                                                    __nv_bfloat16* __restrict__ sh_,
                                                    __nv_bfloat16* __restrict__ sl_) {
    extern __shared__ float xtile[];
    const int tid = threadIdx.x, wid = tid >> 5, lane = tid & 31;
    const int i = blockIdx.x * 16 + wid;
    const int s = g_segs[i], e = g_sege[i];
    const int sb = g_segs[blockIdx.x * 16];
    const int eb = g_sege[blockIdx.x * 16 + 15];
    const float* row = attn + (size_t)i * NROWS;

    float4 acc[4];
    #pragma unroll
    for (int c = 0; c < 4; c++) acc[c] = make_float4(0.f, 0.f, 0.f, 0.f);

    for (int t = sb; t < eb; t += AT_TILE) {
        const int tn = min(AT_TILE, eb - t);
        __syncthreads();
        for (int idx = tid; idx < tn * 128; idx += 512) {
            int r = idx >> 7, c = idx & 127;
            *(float4*)(xtile + r * DDIM + c * 4) = *(const float4*)(xc + (size_t)(t + r) * DDIM + c * 4);
        }
        __syncthreads();
        const int j0 = max(s, t), j1 = min(e, t + tn);
        for (int j = j0; j < j1; j++) {
            float a = __ldg(row + j);
            const float* xr = xtile + (j - t) * DDIM;
            #pragma unroll
            for (int c = 0; c < 4; c++) {
                float4 v = *(const float4*)(xr + c * 128 + lane * 4);
                acc[c].x = fmaf(a, v.x, acc[c].x);
                acc[c].y = fmaf(a, v.y, acc[c].y);
                acc[c].z = fmaf(a, v.z, acc[c].z);
                acc[c].w = fmaf(a, v.w, acc[c].w);
            }
        }
    }

    size_t base = (size_t)i * DDIM;
    #pragma unroll
    for (int c = 0; c < 4; c++) {
        size_t o = base + c * 128 + lane * 4;
        __nv_bfloat16 h, l;
        split2(acc[c].x, h, l); sh_[o + 0] = h; sl_[o + 0] = l;
        split2(acc[c].y, h, l); sh_[o + 1] = h; sl_[o + 1] = l;
        split2(acc[c].z, h, l); sh_[o + 2] = h; sl_[o + 2] = l;
        split2(acc[c].w, h, l); sh_[o + 3] = h; sl_[o + 3] = l;
    }
}

// ================= launch =================
extern "C" void kernel_launch(void* const* d_in, const int* in_sizes, int n_in,
                              void* d_out, int out_size) {
    const float* x_mole  = (const float*)d_in[0];
    const float* x_conf  = (const float*)d_in[1];
    const float* W1      = (const float*)d_in[2];
    const float* W2      = (const float*)d_in[3];
    const float* phi1_w  = (const float*)d_in[4];
    const float* phi1_b  = (const float*)d_in[5];
    const float* phi2_w  = (const float*)d_in[6];
    const float* phi2_b  = (const float*)d_in[7];
    const float* rho_w1  = (const float*)d_in[8];
    const float* rho_b1  = (const float*)d_in[9];
    const float* rho_w2  = (const float*)d_in[10];
    const float* rho_b2  = (const float*)d_in[11];
    const float* rho_ln_w = (const float*)d_in[12];
    const float* rho_ln_b = (const float*)d_in[13];
    const int*   batch   = (const int*)d_in[14];

    float* out_enc  = (float*)d_out;
    float* out_attn = (float*)d_out + (size_t)NROWS * DDIM;

    float *q, *k;
    __nv_bfloat16 *sh1, *sl1, *sh2, *sl2, *wh, *wl;
    cudaGetSymbolAddress((void**)&q,   g_q);
    cudaGetSymbolAddress((void**)&k,   g_k);
    cudaGetSymbolAddress((void**)&sh1, g_sh1);
    cudaGetSymbolAddress((void**)&sl1, g_sl1);
    cudaGetSymbolAddress((void**)&sh2, g_sh2);
    cudaGetSymbolAddress((void**)&sl2, g_sl2);
    cudaGetSymbolAddress((void**)&wh,  g_wh);
    cudaGetSymbolAddress((void**)&wl,  g_wl);
    const size_t WSZ = (size_t)DDIM * DDIM;

    cudaFuncSetAttribute(gemm_mma, cudaFuncAttributeMaxDynamicSharedMemorySize, GM_SMEM);
    cudaFuncSetAttribute(attn_softmax16, cudaFuncAttributeMaxDynamicSharedMemorySize, AT_SMEM);
    cudaFuncSetAttribute(attn_apply16, cudaFuncAttributeMaxDynamicSharedMemorySize, AT_SMEM);

    dim3 ggrid1(DDIM / 128, NROWS / 128, 1);
    dim3 ggrid2(DDIM / 128, NROWS / 128, 2);
    dim3 lgrid(NROWS / 2, 2, 1);

    // 1: weight splits + segments (fused)
    wsplit_seg<<<1024 + 32, 256>>>(W1, W2, rho_w1, rho_w2, wh, wl, batch);
    // 2: both LayerNorm+splits in one launch
    ln_split2<<<lgrid, 256>>>(x_mole, phi1_w, phi1_b, sh1, sl1,
                              x_conf, phi2_w, phi2_b, sh2, sl2);
    // 3: q + k projections (merged)
    gemm_mma<<<ggrid2, 512, GM_SMEM>>>(sh1, sl1, wh + 0 * WSZ, wl + 0 * WSZ, q,
                                       sh2, sl2, wh + 1 * WSZ, wl + 1 * WSZ, k,
                                       nullptr, nullptr, nullptr, 0);
    // 4: tiled masked softmax (ncu-captured position)
    attn_softmax16<<<NROWS / 16, 512, AT_SMEM>>>(q, k, out_attn);
    // 5: tiled apply
    attn_apply16<<<NROWS / 16, 512, AT_SMEM>>>(out_attn, x_conf, sh1, sl1);

    // 6,7: rho MLP (epilogues fused)
    gemm_mma<<<ggrid1, 512, GM_SMEM>>>(sh1, sl1, wh + 2 * WSZ, wl + 2 * WSZ, nullptr,
                                       nullptr, nullptr, nullptr, nullptr, nullptr,
                                       rho_b1, sh2, sl2, 1);
    gemm_mma<<<ggrid1, 512, GM_SMEM>>>(sh2, sl2, wh + 3 * WSZ, wl + 3 * WSZ, k,
                                       nullptr, nullptr, nullptr, nullptr, nullptr,
                                       rho_b2, nullptr, nullptr, 2);

    // 8: final LayerNorm into output
    ln_kernel<<<NROWS / 2, 256>>>(k, rho_ln_w, rho_ln_b, out_enc);
}

// round 12
// speedup vs baseline: 1.2744x; 1.2744x over previous
#include <cuda_runtime.h>
#include <cuda_bf16.h>
#include <math.h>
#include <stdint.h>

#define NROWS 8192
#define DDIM  512
#define EPS   1e-5f

// ================= PTX helpers =================
__device__ __forceinline__ uint32_t smem_u32(const void* p) {
    uint32_t a;
    asm("{ .reg .u64 t; cvta.to.shared.u64 t, %1; cvt.u32.u64 %0, t; }" : "=r"(a) : "l"(p));
    return a;
}
#define CP_ASYNC16(smem, gptr) \
    asm volatile("cp.async.cg.shared.global [%0], [%1], 16;" :: "r"(smem), "l"(gptr))
#define CP_COMMIT() asm volatile("cp.async.commit_group;" ::: "memory")
#define CP_WAIT(n)  asm volatile("cp.async.wait_group %0;" :: "n"(n) : "memory")

#define LDMX4(r, addr) \
    asm volatile("ldmatrix.sync.aligned.m8n8.x4.shared.b16 {%0,%1,%2,%3}, [%4];" \
        : "=r"((r)[0]), "=r"((r)[1]), "=r"((r)[2]), "=r"((r)[3]) : "r"(addr))

#define MMA16816(d, a, b0, b1) \
    asm volatile("mma.sync.aligned.m16n8k16.row.col.f32.bf16.bf16.f32 " \
        "{%0,%1,%2,%3}, {%4,%5,%6,%7}, {%8,%9}, {%0,%1,%2,%3};" \
        : "+f"((d)[0]), "+f"((d)[1]), "+f"((d)[2]), "+f"((d)[3]) \
        : "r"((a)[0]), "r"((a)[1]), "r"((a)[2]), "r"((a)[3]), "r"(b0), "r"(b1))

// ================= scratch =================
__device__ float g_k  [NROWS * DDIM];
__device__ __nv_bfloat16 g_sh1[NROWS * DDIM];
__device__ __nv_bfloat16 g_sl1[NROWS * DDIM];
__device__ __nv_bfloat16 g_sh2[NROWS * DDIM];
__device__ __nv_bfloat16 g_sl2[NROWS * DDIM];
__device__ __nv_bfloat16 g_qh[NROWS * DDIM];
__device__ __nv_bfloat16 g_ql[NROWS * DDIM];
__device__ __nv_bfloat16 g_kh[NROWS * DDIM];
__device__ __nv_bfloat16 g_kl[NROWS * DDIM];
__device__ __nv_bfloat16 g_wh[4][DDIM * DDIM];
__device__ __nv_bfloat16 g_wl[4][DDIM * DDIM];
__device__ int   g_segs[NROWS];
__device__ int   g_sege[NROWS];

// ================= reductions =================
__device__ __forceinline__ float warpSum(float v) {
    #pragma unroll
    for (int o = 16; o > 0; o >>= 1) v += __shfl_xor_sync(0xffffffffu, v, o);
    return v;
}

// ================= split helpers =================
__device__ __forceinline__ void split2(float v, __nv_bfloat16& hi, __nv_bfloat16& lo) {
    hi = __float2bfloat16(v);
    lo = __float2bfloat16(v - __bfloat162float(hi));
}

// ================= fused weight-split + segment kernel =================
__global__ __launch_bounds__(256) void wsplit_seg(const float* __restrict__ W1,
                                                  const float* __restrict__ W2,
                                                  const float* __restrict__ W3,
                                                  const float* __restrict__ W4,
                                                  __nv_bfloat16* __restrict__ wh,
                                                  __nv_bfloat16* __restrict__ wl,
                                                  const int* __restrict__ p) {
    if (blockIdx.x < 1024) {
        int id = blockIdx.x * 256 + threadIdx.x;
        int w = id >> 16;
        int j = id & 65535;
        const float* src = (w == 0) ? W1 : (w == 1) ? W2 : (w == 2) ? W3 : W4;
        float4 v = ((const float4*)src)[j];
        __nv_bfloat16 h0, l0, h1, l1, h2, l2, h3, l3;
        split2(v.x, h0, l0); split2(v.y, h1, l1);
        split2(v.z, h2, l2); split2(v.w, h3, l3);
        size_t base = (size_t)w * DDIM * DDIM + (size_t)j * 4;
        __nv_bfloat162* ph = (__nv_bfloat162*)(wh + base);
        __nv_bfloat162* pl = (__nv_bfloat162*)(wl + base);
        ph[0] = __nv_bfloat162(h0, h1); ph[1] = __nv_bfloat162(h2, h3);
        pl[0] = __nv_bfloat162(l0, l1); pl[1] = __nv_bfloat162(l2, l3);
    } else {
        int i = (blockIdx.x - 1024) * 256 + threadIdx.x;
        if (i >= NROWS) return;
        const int is64 = (__ldg(p + (NROWS - 1)) == 0);
        #define GETB(idx) (is64 ? __ldg(p + 2 * (idx)) : __ldg(p + (idx)))
        int v = GETB(i);
        int lo = 0, hi = NROWS;
        while (lo < hi) { int mid = (lo + hi) >> 1; if (GETB(mid) < v) lo = mid + 1; else hi = mid; }
        g_segs[i] = lo;
        lo = 0; hi = NROWS;
        while (lo < hi) { int mid = (lo + hi) >> 1; if (GETB(mid) <= v) lo = mid + 1; else hi = mid; }
        g_sege[i] = lo;
        #undef GETB
    }
}

// ================= LayerNorm+split (both inputs, gridDim.y=2) =================
__global__ __launch_bounds__(256) void ln_split2(const float* __restrict__ xa,
                                                 const float* __restrict__ wa,
                                                 const float* __restrict__ ba,
                                                 __nv_bfloat16* __restrict__ sha,
                                                 __nv_bfloat16* __restrict__ sla,
                                                 const float* __restrict__ xb,
                                                 const float* __restrict__ wb,
                                                 const float* __restrict__ bb,
                                                 __nv_bfloat16* __restrict__ shb,
                                                 __nv_bfloat16* __restrict__ slb) {
    const float* x = (blockIdx.y == 0) ? xa : xb;
    const float* w = (blockIdx.y == 0) ? wa : wb;
    const float* b = (blockIdx.y == 0) ? ba : bb;
    __nv_bfloat16* sh_ = (blockIdx.y == 0) ? sha : shb;
    __nv_bfloat16* sl_ = (blockIdx.y == 0) ? sla : slb;

    __shared__ float red[2][4];
    const int half = threadIdx.x >> 7;
    const int t    = threadIdx.x & 127;
    const int lane = threadIdx.x & 31;
    const int w4   = (threadIdx.x >> 5) & 3;
    const int row  = blockIdx.x * 2 + half;
    float4 v = ((const float4*)(x + (size_t)row * DDIM))[t];
    float ps = warpSum(v.x + v.y + v.z + v.w);
    if (lane == 0) red[half][w4] = ps;
    __syncthreads();
    float mu = (red[half][0] + red[half][1] + red[half][2] + red[half][3]) * (1.0f / DDIM);
    __syncthreads();
    float dx = v.x - mu, dy = v.y - mu, dz = v.z - mu, dw = v.w - mu;
    float pv = warpSum(dx * dx + dy * dy + dz * dz + dw * dw);
    if (lane == 0) red[half][w4] = pv;
    __syncthreads();
    float var = (red[half][0] + red[half][1] + red[half][2] + red[half][3]) * (1.0f / DDIM);
    float r = rsqrtf(var + EPS);
    float4 wv = ((const float4*)w)[t];
    float4 bv = ((const float4*)b)[t];
    float y0 = dx * r * wv.x + bv.x;
    float y1 = dy * r * wv.y + bv.y;
    float y2 = dz * r * wv.z + bv.z;
    float y3 = dw * r * wv.w + bv.w;
    __nv_bfloat16 h0, l0, h1, l1, h2, l2, h3, l3;
    split2(y0, h0, l0); split2(y1, h1, l1);
    split2(y2, h2, l2); split2(y3, h3, l3);
    size_t o = (size_t)row * DDIM + t * 4;
    __nv_bfloat162* ph = (__nv_bfloat162*)(sh_ + o);
    __nv_bfloat162* pl = (__nv_bfloat162*)(sl_ + o);
    ph[0] = __nv_bfloat162(h0, h1); ph[1] = __nv_bfloat162(h2, h3);
    pl[0] = __nv_bfloat162(l0, l1); pl[1] = __nv_bfloat162(l2, l3);
}

__global__ __launch_bounds__(256) void ln_kernel(const float* __restrict__ x,
                                                 const float* __restrict__ w,
                                                 const float* __restrict__ b,
                                                 float* __restrict__ y) {
    __shared__ float red[2][4];
    const int half = threadIdx.x >> 7;
    const int t    = threadIdx.x & 127;
    const int lane = threadIdx.x & 31;
    const int w4   = (threadIdx.x >> 5) & 3;
    const int row  = blockIdx.x * 2 + half;
    float4 v = ((const float4*)(x + (size_t)row * DDIM))[t];
    float ps = warpSum(v.x + v.y + v.z + v.w);
    if (lane == 0) red[half][w4] = ps;
    __syncthreads();
    float mu = (red[half][0] + red[half][1] + red[half][2] + red[half][3]) * (1.0f / DDIM);
    __syncthreads();
    float dx = v.x - mu, dy = v.y - mu, dz = v.z - mu, dw = v.w - mu;
    float pv = warpSum(dx * dx + dy * dy + dz * dz + dw * dw);
    if (lane == 0) red[half][w4] = pv;
    __syncthreads();
    float var = (red[half][0] + red[half][1] + red[half][2] + red[half][3]) * (1.0f / DDIM);
    float r = rsqrtf(var + EPS);
    float4 wv = ((const float4*)w)[t];
    float4 bv = ((const float4*)b)[t];
    float4 o;
    o.x = dx * r * wv.x + bv.x;
    o.y = dy * r * wv.y + bv.y;
    o.z = dz * r * wv.z + bv.z;
    o.w = dw * r * wv.w + bv.w;
    ((float4*)(y + (size_t)row * DDIM))[t] = o;
}

// ================= mma.sync bf16-split GEMM (BK=64, 16 warps, merged z) =================
// modes: 0 = fp32 C. 1 = bias+SiLU -> bf16 split. 2 = bias+SiLU -> fp32.
//        3 = raw bf16 split (oh/ol; oh2/ol2 for z=1).
#define GM_STAGE 65536
#define GM_SMEM  (3 * GM_STAGE)

__device__ __forceinline__ uint32_t swz(int row, int c16) {
    return (uint32_t)(row * 128 + ((c16 ^ (row & 7)) << 4));
}
__device__ __forceinline__ float silu_f(float v) { return v / (1.0f + expf(-v)); }

__global__ __launch_bounds__(512, 1) void gemm_mma(const __nv_bfloat16* Ah,
                                                   const __nv_bfloat16* Al,
                                                   const __nv_bfloat16* Bh,
                                                   const __nv_bfloat16* Bl,
                                                   float* C,
                                                   const __nv_bfloat16* Ah2,
                                                   const __nv_bfloat16* Al2,
                                                   const __nv_bfloat16* Bh2,
                                                   const __nv_bfloat16* Bl2,
                                                   const float* bias,
                                                   __nv_bfloat16* oh,
                                                   __nv_bfloat16* ol,
                                                   __nv_bfloat16* oh2,
                                                   __nv_bfloat16* ol2,
                                                   int mode) {
    if (blockIdx.z == 1) { Ah = Ah2; Al = Al2; Bh = Bh2; Bl = Bl2; oh = oh2; ol = ol2; }
    extern __shared__ char smem[];
    const uint32_t sbase = smem_u32(smem);
    const int tid  = threadIdx.x;
    const int lane = tid & 31;
    const int wid  = tid >> 5;
    const int wm   = wid >> 2;
    const int wn   = wid & 3;
    const int bm   = blockIdx.y * 128;
    const int bn   = blockIdx.x * 128;

    float acc[2][4][4];
    #pragma unroll
    for (int mi = 0; mi < 2; mi++)
        #pragma unroll
        for (int nj = 0; nj < 4; nj++)
            #pragma unroll
            for (int c = 0; c < 4; c++) acc[mi][nj][c] = 0.0f;

    const int lr0 = tid >> 3,         lc0 = tid & 7;
    const int lr1 = (tid + 512) >> 3, lc1 = (tid + 512) & 7;
    const uint32_t so0 = swz(lr0, lc0), so1 = swz(lr1, lc1);

    const int arow = (lane & 15);
    const int acol = (lane >> 4);
    const int brow = (lane & 7) + ((lane >> 4) & 1) * 8;
    const int bcol = (lane >> 3) & 1;

    #define GM_ISSUE(st, kt) do { \
        uint32_t sb_ = sbase + (st) * GM_STAGE; \
        int k0_ = (kt) * 64; \
        size_t ga0 = (size_t)(bm + lr0) * DDIM + k0_ + lc0 * 8; \
        size_t gb0 = (size_t)(bn + lr0) * DDIM + k0_ + lc0 * 8; \
        size_t ga1 = (size_t)(bm + lr1) * DDIM + k0_ + lc1 * 8; \
        size_t gb1 = (size_t)(bn + lr1) * DDIM + k0_ + lc1 * 8; \
        CP_ASYNC16(sb_ + so0,          Ah + ga0); \
        CP_ASYNC16(sb_ + 16384 + so0,  Al + ga0); \
        CP_ASYNC16(sb_ + 32768 + so0,  Bh + gb0); \
        CP_ASYNC16(sb_ + 49152 + so0,  Bl + gb0); \
        CP_ASYNC16(sb_ + so1,          Ah + ga1); \
        CP_ASYNC16(sb_ + 16384 + so1,  Al + ga1); \
        CP_ASYNC16(sb_ + 32768 + so1,  Bh + gb1); \
        CP_ASYNC16(sb_ + 49152 + so1,  Bl + gb1); \
    } while (0)

    GM_ISSUE(0, 0); CP_COMMIT();
    GM_ISSUE(1, 1); CP_COMMIT();

    for (int kt = 0; kt < 8; kt++) {
        if (kt < 6) CP_WAIT(1); else CP_WAIT(0);
        __syncthreads();
        const uint32_t sb = sbase + (kt % 3) * GM_STAGE;

        #pragma unroll
        for (int ks = 0; ks < 4; ks++) {
            uint32_t fah[2][4], fal[2][4];
            #pragma unroll
            for (int mi = 0; mi < 2; mi++) {
                uint32_t off = swz(wm * 32 + mi * 16 + arow, ks * 2 + acol);
                LDMX4(fah[mi], sb + off);
                LDMX4(fal[mi], sb + 16384 + off);
            }
            #pragma unroll
            for (int njp = 0; njp < 4; njp += 2) {
                uint32_t off = swz(wn * 32 + njp * 8 + brow, ks * 2 + bcol);
                uint32_t fbh[4], fbl[4];
                LDMX4(fbh, sb + 32768 + off);
                LDMX4(fbl, sb + 49152 + off);
                #pragma unroll
                for (int mi = 0; mi < 2; mi++) {
                    MMA16816(acc[mi][njp],     fah[mi], fbh[0], fbh[1]);
                    MMA16816(acc[mi][njp + 1], fah[mi], fbh[2], fbh[3]);
                    MMA16816(acc[mi][njp],     fah[mi], fbl[0], fbl[1]);
                    MMA16816(acc[mi][njp + 1], fah[mi], fbl[2], fbl[3]);
                    MMA16816(acc[mi][njp],     fal[mi], fbh[0], fbh[1]);
                    MMA16816(acc[mi][njp + 1], fal[mi], fbh[2], fbh[3]);
                }
            }
        }
        if (kt + 2 < 8) { GM_ISSUE((kt + 2) % 3, kt + 2); CP_COMMIT(); }
    }
    #undef GM_ISSUE

    const int erow = lane >> 2;
    const int ecol = (lane & 3) * 2;
    #pragma unroll
    for (int mi = 0; mi < 2; mi++) {
        #pragma unroll
        for (int nj = 0; nj < 4; nj++) {
            int m0 = bm + wm * 32 + mi * 16 + erow;
            int n0 = bn + wn * 32 + nj * 8 + ecol;
            float2 v0 = make_float2(acc[mi][nj][0], acc[mi][nj][1]);
            float2 v1 = make_float2(acc[mi][nj][2], acc[mi][nj][3]);
            if (mode == 0) {
                *(float2*)(C + (size_t)m0 * DDIM + n0)       = v0;
                *(float2*)(C + (size_t)(m0 + 8) * DDIM + n0) = v1;
            } else if (mode == 3) {
                __nv_bfloat16 h0, l0, h1, l1;
                split2(v0.x, h0, l0); split2(v0.y, h1, l1);
                *(__nv_bfloat162*)(oh + (size_t)m0 * DDIM + n0) = __nv_bfloat162(h0, h1);
                *(__nv_bfloat162*)(ol + (size_t)m0 * DDIM + n0) = __nv_bfloat162(l0, l1);
                split2(v1.x, h0, l0); split2(v1.y, h1, l1);
                *(__nv_bfloat162*)(oh + (size_t)(m0 + 8) * DDIM + n0) = __nv_bfloat162(h0, h1);
                *(__nv_bfloat162*)(ol + (size_t)(m0 + 8) * DDIM + n0) = __nv_bfloat162(l0, l1);
            } else {
                float2 bv = *(const float2*)(bias + n0);
                v0.x = silu_f(v0.x + bv.x); v0.y = silu_f(v0.y + bv.y);
                v1.x = silu_f(v1.x + bv.x); v1.y = silu_f(v1.y + bv.y);
                if (mode == 2) {
                    *(float2*)(C + (size_t)m0 * DDIM + n0)       = v0;
                    *(float2*)(C + (size_t)(m0 + 8) * DDIM + n0) = v1;
                } else {
                    __nv_bfloat16 h0, l0, h1, l1;
                    split2(v0.x, h0, l0); split2(v0.y, h1, l1);
                    *(__nv_bfloat162*)(oh + (size_t)m0 * DDIM + n0) = __nv_bfloat162(h0, h1);
                    *(__nv_bfloat162*)(ol + (size_t)m0 * DDIM + n0) = __nv_bfloat162(l0, l1);
                    split2(v1.x, h0, l0); split2(v1.y, h1, l1);
                    *(__nv_bfloat162*)(oh + (size_t)(m0 + 8) * DDIM + n0) = __nv_bfloat162(h0, h1);
                    *(__nv_bfloat162*)(ol + (size_t)(m0 + 8) * DDIM + n0) = __nv_bfloat162(l0, l1);
                }
            }
        }
    }
}

// ================= tensorized masked softmax =================
// Block = 64 rows, 512 thr (16 warps, warp tile 16x32). kv chunks of 128 over
// [sbA, eb) where sbA = segs[r0] & ~3 (alignment). S = q@k^T via 3-term
// bf16-split mma, masked epilogue -> attn, rowmax via smem atomicMax (init 0
// = reference's mask-zero clamp), then exp/sum/normalize + tail zero-fill.
#define AS_STAGE 49152
#define AS_SMEM  (512 + 3 * AS_STAGE)

__global__ __launch_bounds__(512, 1) void attn_softmax_mma(const __nv_bfloat16* __restrict__ qh,
                                                           const __nv_bfloat16* __restrict__ ql,
                                                           const __nv_bfloat16* __restrict__ kh,
                                                           const __nv_bfloat16* __restrict__ kl,
                                                           float* __restrict__ attn) {
    extern __shared__ char smem[];
    float* rowmax = (float*)smem;
    const uint32_t sbase = smem_u32(smem) + 512;
    const int tid = threadIdx.x, lane = tid & 31, wid = tid >> 5;
    const int wm = wid >> 2, wn = wid & 3;
    const int r0 = blockIdx.x * 64;
    const int sbA = g_segs[r0] & ~3;
    const int eb  = g_sege[r0 + 63];
    const int nch = (eb - sbA + 127) >> 7;
    const int ebp = min(sbA + nch * 128, NROWS);

    if (tid < 64) rowmax[tid] = 0.0f;

    const int qrow = tid >> 3, qc = tid & 7;
    const int krow0 = tid >> 3, kc0 = tid & 7;
    const int krow1 = (tid + 512) >> 3, kc1 = (tid + 512) & 7;
    const uint32_t sq  = swz(qrow, qc);
    const uint32_t sk0 = swz(krow0, kc0);
    const uint32_t sk1 = swz(krow1, kc1);

    const int arow = lane & 15, acol = lane >> 4;
    const int brow = (lane & 7) + ((lane >> 4) & 1) * 8, bcol = (lane >> 3) & 1;
    const int erow = lane >> 2, ecol = (lane & 3) * 2;
    const int row_a = r0 + wm * 16 + erow;
    const int s_a = g_segs[row_a],     e_a = g_sege[row_a];
    const int s_b = g_segs[row_a + 8], e_b = g_sege[row_a + 8];

    __syncthreads();

    for (int ch = 0; ch < nch; ch++) {
        const int kvb = sbA + ch * 128;
        if (ch > 0) __syncthreads();      // stage reuse across chunks

        float acc[4][4];
        #pragma unroll
        for (int nj = 0; nj < 4; nj++)
            #pragma unroll
            for (int c = 0; c < 4; c++) acc[nj][c] = 0.0f;

        #define AS_ISSUE(st, kt) do { \
            uint32_t sb_ = sbase + (st) * AS_STAGE; \
            int k0_ = (kt) * 64; \
            size_t gq = (size_t)(r0 + qrow) * DDIM + k0_ + qc * 8; \
            int kr0g = min(kvb + krow0, NROWS - 1); \
            int kr1g = min(kvb + krow1, NROWS - 1); \
            size_t gk0 = (size_t)kr0g * DDIM + k0_ + kc0 * 8; \
            size_t gk1 = (size_t)kr1g * DDIM + k0_ + kc1 * 8; \
            CP_ASYNC16(sb_ + sq,           qh + gq); \
            CP_ASYNC16(sb_ + 8192 + sq,    ql + gq); \
            CP_ASYNC16(sb_ + 16384 + sk0,  kh + gk0); \
            CP_ASYNC16(sb_ + 32768 + sk0,  kl + gk0); \
            CP_ASYNC16(sb_ + 16384 + sk1,  kh + gk1); \
            CP_ASYNC16(sb_ + 32768 + sk1,  kl + gk1); \
        } while (0)

        AS_ISSUE(0, 0); CP_COMMIT();
        AS_ISSUE(1, 1); CP_COMMIT();

        for (int kt = 0; kt < 8; kt++) {
            if (kt < 6) CP_WAIT(1); else CP_WAIT(0);
            __syncthreads();
            const uint32_t sb = sbase + (kt % 3) * AS_STAGE;

            #pragma unroll
            for (int ks = 0; ks < 4; ks++) {
                uint32_t fqh[4], fql[4];
                {
                    uint32_t off = swz(wm * 16 + arow, ks * 2 + acol);
                    LDMX4(fqh, sb + off);
                    LDMX4(fql, sb + 8192 + off);
                }
                #pragma unroll
                for (int njp = 0; njp < 4; njp += 2) {
                    uint32_t off = swz(wn * 32 + njp * 8 + brow, ks * 2 + bcol);
                    uint32_t fkh[4], fkl[4];
                    LDMX4(fkh, sb + 16384 + off);
                    LDMX4(fkl, sb + 32768 + off);
                    MMA16816(acc[njp],     fqh, fkh[0], fkh[1]);
                    MMA16816(acc[njp + 1], fqh, fkh[2], fkh[3]);
                    MMA16816(acc[njp],     fqh, fkl[0], fkl[1]);
                    MMA16816(acc[njp + 1], fqh, fkl[2], fkl[3]);
                    MMA16816(acc[njp],     fql, fkh[0], fkh[1]);
                    MMA16816(acc[njp + 1], fql, fkh[2], fkh[3]);
                }
            }
            if (kt + 2 < 8) { AS_ISSUE((kt + 2) % 3, kt + 2); CP_COMMIT(); }
        }
        #undef AS_ISSUE

        // masked epilogue: write dots-or-zeros, track row max
        float vm0 = 0.0f, vm1 = 0.0f;
        #pragma unroll
        for (int nj = 0; nj < 4; nj++) {
            int j = kvb + wn * 32 + nj * 8 + ecol;
            float2 w0, w1;
            w0.x = (j     >= s_a && j     < e_a) ? acc[nj][0] : 0.0f;
            w0.y = (j + 1 >= s_a && j + 1 < e_a) ? acc[nj][1] : 0.0f;
            w1.x = (j     >= s_b && j     < e_b) ? acc[nj][2] : 0.0f;
            w1.y = (j + 1 >= s_b && j + 1 < e_b) ? acc[nj][3] : 0.0f;
            if (j < NROWS) {
                *(float2*)(attn + (size_t)row_a * NROWS + j)       = w0;
                *(float2*)(attn + (size_t)(row_a + 8) * NROWS + j) = w1;
            }
            vm0 = fmaxf(vm0, fmaxf(w0.x, w0.y));
            vm1 = fmaxf(vm1, fmaxf(w1.x, w1.y));
        }
        vm0 = fmaxf(vm0, __shfl_xor_sync(0xffffffffu, vm0, 1));
        vm0 = fmaxf(vm0, __shfl_xor_sync(0xffffffffu, vm0, 2));
        vm1 = fmaxf(vm1, __shfl_xor_sync(0xffffffffu, vm1, 1));
        vm1 = fmaxf(vm1, __shfl_xor_sync(0xffffffffu, vm1, 2));
        if ((lane & 3) == 0) {
            atomicMax((int*)&rowmax[wm * 16 + erow],     __float_as_int(vm0));
            atomicMax((int*)&rowmax[wm * 16 + erow + 8], __float_as_int(vm1));
        }
    }
    __syncthreads();

    // softmax phase: warp w owns rows r0 + w*4 .. +3
    for (int rr = 0; rr < 4; rr++) {
        const int li = wid * 4 + rr;
        const int i = r0 + li;
        float m = rowmax[li];            // >= 0 (reference clamp)
        const int s = g_segs[i], e = g_sege[i];
        float* row = attn + (size_t)i * NROWS;

        // zero-fill [0, sbA) and [ebp, NROWS)  (both float4-aligned)
        const float4 z4 = make_float4(0.f, 0.f, 0.f, 0.f);
        for (int j = lane; j < (sbA >> 2); j += 32) ((float4*)row)[j] = z4;
        if (ebp < NROWS) {
            for (int j = (ebp >> 2) + lane; j < (NROWS >> 2); j += 32) ((float4*)row)[j] = z4;
        }

        float ssum = 0.0f;
        for (int j = s + lane; j < e; j += 32) {
            float ev = expf(row[j] - m);
            ssum += ev;
            row[j] = ev;
        }
        ssum = warpSum(ssum);
        float inv = 1.0f / ssum;
        for (int j = s + lane; j < e; j += 32) row[j] *= inv;
    }
}

// ================= tiled apply (unchanged) =================
#define AT_TILE  32
#define AT_SMEM  (AT_TILE * DDIM * 4)

__global__ __launch_bounds__(512) void attn_apply16(const float* __restrict__ attn,
                                                    const float* __restrict__ xc,
                                                    __nv_bfloat16* __restrict__ sh_,
                                                    __nv_bfloat16* __restrict__ sl_) {
    extern __shared__ float xtile[];
    const int tid = threadIdx.x, wid = tid >> 5, lane = tid & 31;
    const int i = blockIdx.x * 16 + wid;
    const int s = g_segs[i], e = g_sege[i];
    const int sb = g_segs[blockIdx.x * 16];
    const int eb = g_sege[blockIdx.x * 16 + 15];
    const float* row = attn + (size_t)i * NROWS;

    float4 acc[4];
    #pragma unroll
    for (int c = 0; c < 4; c++) acc[c] = make_float4(0.f, 0.f, 0.f, 0.f);

    for (int t = sb; t < eb; t += AT_TILE) {
        const int tn = min(AT_TILE, eb - t);
        __syncthreads();
        for (int idx = tid; idx < tn * 128; idx += 512) {
            int r = idx >> 7, c = idx & 127;
            *(float4*)(xtile + r * DDIM + c * 4) = *(const float4*)(xc + (size_t)(t + r) * DDIM + c * 4);
        }
        __syncthreads();
        const int j0 = max(s, t), j1 = min(e, t + tn);
        for (int j = j0; j < j1; j++) {
            float a = __ldg(row + j);
            const float* xr = xtile + (j - t) * DDIM;
            #pragma unroll
            for (int c = 0; c < 4; c++) {
                float4 v = *(const float4*)(xr + c * 128 + lane * 4);
                acc[c].x = fmaf(a, v.x, acc[c].x);
                acc[c].y = fmaf(a, v.y, acc[c].y);
                acc[c].z = fmaf(a, v.z, acc[c].z);
                acc[c].w = fmaf(a, v.w, acc[c].w);
            }
        }
    }

    size_t base = (size_t)i * DDIM;
    #pragma unroll
    for (int c = 0; c < 4; c++) {
        size_t o = base + c * 128 + lane * 4;
        __nv_bfloat16 h, l;
        split2(acc[c].x, h, l); sh_[o + 0] = h; sl_[o + 0] = l;
        split2(acc[c].y, h, l); sh_[o + 1] = h; sl_[o + 1] = l;
        split2(acc[c].z, h, l); sh_[o + 2] = h; sl_[o + 2] = l;
        split2(acc[c].w, h, l); sh_[o + 3] = h; sl_[o + 3] = l;
    }
}

// ================= launch =================
extern "C" void kernel_launch(void* const* d_in, const int* in_sizes, int n_in,
                              void* d_out, int out_size) {
    const float* x_mole  = (const float*)d_in[0];
    const float* x_conf  = (const float*)d_in[1];
    const float* W1      = (const float*)d_in[2];
    const float* W2      = (const float*)d_in[3];
    const float* phi1_w  = (const float*)d_in[4];
    const float* phi1_b  = (const float*)d_in[5];
    const float* phi2_w  = (const float*)d_in[6];
    const float* phi2_b  = (const float*)d_in[7];
    const float* rho_w1  = (const float*)d_in[8];
    const float* rho_b1  = (const float*)d_in[9];
    const float* rho_w2  = (const float*)d_in[10];
    const float* rho_b2  = (const float*)d_in[11];
    const float* rho_ln_w = (const float*)d_in[12];
    const float* rho_ln_b = (const float*)d_in[13];
    const int*   batch   = (const int*)d_in[14];

    float* out_enc  = (float*)d_out;
    float* out_attn = (float*)d_out + (size_t)NROWS * DDIM;

    float *k;
    __nv_bfloat16 *sh1, *sl1, *sh2, *sl2, *wh, *wl, *qh, *ql, *kh, *kl;
    cudaGetSymbolAddress((void**)&k,   g_k);
    cudaGetSymbolAddress((void**)&sh1, g_sh1);
    cudaGetSymbolAddress((void**)&sl1, g_sl1);
    cudaGetSymbolAddress((void**)&sh2, g_sh2);
    cudaGetSymbolAddress((void**)&sl2, g_sl2);
    cudaGetSymbolAddress((void**)&wh,  g_wh);
    cudaGetSymbolAddress((void**)&wl,  g_wl);
    cudaGetSymbolAddress((void**)&qh,  g_qh);
    cudaGetSymbolAddress((void**)&ql,  g_ql);
    cudaGetSymbolAddress((void**)&kh,  g_kh);
    cudaGetSymbolAddress((void**)&kl,  g_kl);
    const size_t WSZ = (size_t)DDIM * DDIM;

    cudaFuncSetAttribute(gemm_mma, cudaFuncAttributeMaxDynamicSharedMemorySize, GM_SMEM);
    cudaFuncSetAttribute(attn_softmax_mma, cudaFuncAttributeMaxDynamicSharedMemorySize, AS_SMEM);
    cudaFuncSetAttribute(attn_apply16, cudaFuncAttributeMaxDynamicSharedMemorySize, AT_SMEM);

    dim3 ggrid1(DDIM / 128, NROWS / 128, 1);
    dim3 ggrid2(DDIM / 128, NROWS / 128, 2);
    dim3 lgrid(NROWS / 2, 2, 1);

    // 1: weight splits + segments
    wsplit_seg<<<1024 + 32, 256>>>(W1, W2, rho_w1, rho_w2, wh, wl, batch);
    // 2: both LayerNorm+splits
    ln_split2<<<lgrid, 256>>>(x_mole, phi1_w, phi1_b, sh1, sl1,
                              x_conf, phi2_w, phi2_b, sh2, sl2);
    // 3: q + k projections -> bf16 splits (mode 3, merged z)
    gemm_mma<<<ggrid2, 512, GM_SMEM>>>(sh1, sl1, wh + 0 * WSZ, wl + 0 * WSZ, nullptr,
                                       sh2, sl2, wh + 1 * WSZ, wl + 1 * WSZ,
                                       nullptr, qh, ql, kh, kl, 3);
    // 4: tensorized masked softmax (ncu position)
    attn_softmax_mma<<<NROWS / 64, 512, AS_SMEM>>>(qh, ql, kh, kl, out_attn);
    // 5: tiled apply
    attn_apply16<<<NROWS / 16, 512, AT_SMEM>>>(out_attn, x_conf, sh1, sl1);

    // 6,7: rho MLP (epilogues fused)
    gemm_mma<<<ggrid1, 512, GM_SMEM>>>(sh1, sl1, wh + 2 * WSZ, wl + 2 * WSZ, nullptr,
                                       nullptr, nullptr, nullptr, nullptr,
                                       rho_b1, sh2, sl2, nullptr, nullptr, 1);
    gemm_mma<<<ggrid1, 512, GM_SMEM>>>(sh2, sl2, wh + 3 * WSZ, wl + 3 * WSZ, k,
                                       nullptr, nullptr, nullptr, nullptr,
                                       rho_b2, nullptr, nullptr, nullptr, nullptr, 2);

    // 8: final LayerNorm into output
    ln_kernel<<<NROWS / 2, 256>>>(k, rho_ln_w, rho_ln_b, out_enc);
}

// round 13
// speedup vs baseline: 1.3947x; 1.0944x over previous
#include <cuda_runtime.h>
#include <cuda_bf16.h>
#include <math.h>
#include <stdint.h>

#define NROWS 8192
#define DDIM  512
#define EPS   1e-5f

// ================= PTX helpers =================
__device__ __forceinline__ uint32_t smem_u32(const void* p) {
    uint32_t a;
    asm("{ .reg .u64 t; cvta.to.shared.u64 t, %1; cvt.u32.u64 %0, t; }" : "=r"(a) : "l"(p));
    return a;
}
#define CP_ASYNC16(smem, gptr) \
    asm volatile("cp.async.cg.shared.global [%0], [%1], 16;" :: "r"(smem), "l"(gptr))
#define CP_COMMIT() asm volatile("cp.async.commit_group;" ::: "memory")
#define CP_WAIT(n)  asm volatile("cp.async.wait_group %0;" :: "n"(n) : "memory")

#define LDMX4(r, addr) \
    asm volatile("ldmatrix.sync.aligned.m8n8.x4.shared.b16 {%0,%1,%2,%3}, [%4];" \
        : "=r"((r)[0]), "=r"((r)[1]), "=r"((r)[2]), "=r"((r)[3]) : "r"(addr))

#define MMA16816(d, a, b0, b1) \
    asm volatile("mma.sync.aligned.m16n8k16.row.col.f32.bf16.bf16.f32 " \
        "{%0,%1,%2,%3}, {%4,%5,%6,%7}, {%8,%9}, {%0,%1,%2,%3};" \
        : "+f"((d)[0]), "+f"((d)[1]), "+f"((d)[2]), "+f"((d)[3]) \
        : "r"((a)[0]), "r"((a)[1]), "r"((a)[2]), "r"((a)[3]), "r"(b0), "r"(b1))

// ================= scratch =================
__device__ float g_k  [NROWS * DDIM];
__device__ __nv_bfloat16 g_sh1[NROWS * DDIM];
__device__ __nv_bfloat16 g_sl1[NROWS * DDIM];
__device__ __nv_bfloat16 g_sh2[NROWS * DDIM];
__device__ __nv_bfloat16 g_sl2[NROWS * DDIM];
__device__ __nv_bfloat16 g_qh[NROWS * DDIM];
__device__ __nv_bfloat16 g_ql[NROWS * DDIM];
__device__ __nv_bfloat16 g_kh[NROWS * DDIM];
__device__ __nv_bfloat16 g_kl[NROWS * DDIM];
__device__ __nv_bfloat16 g_wh[4][DDIM * DDIM];
__device__ __nv_bfloat16 g_wl[4][DDIM * DDIM];
__device__ int   g_segs[NROWS];
__device__ int   g_sege[NROWS];

// ================= reductions =================
__device__ __forceinline__ float warpSum(float v) {
    #pragma unroll
    for (int o = 16; o > 0; o >>= 1) v += __shfl_xor_sync(0xffffffffu, v, o);
    return v;
}

// ================= split helpers =================
__device__ __forceinline__ void split2(float v, __nv_bfloat16& hi, __nv_bfloat16& lo) {
    hi = __float2bfloat16(v);
    lo = __float2bfloat16(v - __bfloat162float(hi));
}

// ================= fused weight-split + segment kernel =================
__global__ __launch_bounds__(256) void wsplit_seg(const float* __restrict__ W1,
                                                  const float* __restrict__ W2,
                                                  const float* __restrict__ W3,
                                                  const float* __restrict__ W4,
                                                  __nv_bfloat16* __restrict__ wh,
                                                  __nv_bfloat16* __restrict__ wl,
                                                  const int* __restrict__ p) {
    if (blockIdx.x < 1024) {
        int id = blockIdx.x * 256 + threadIdx.x;
        int w = id >> 16;
        int j = id & 65535;
        const float* src = (w == 0) ? W1 : (w == 1) ? W2 : (w == 2) ? W3 : W4;
        float4 v = ((const float4*)src)[j];
        __nv_bfloat16 h0, l0, h1, l1, h2, l2, h3, l3;
        split2(v.x, h0, l0); split2(v.y, h1, l1);
        split2(v.z, h2, l2); split2(v.w, h3, l3);
        size_t base = (size_t)w * DDIM * DDIM + (size_t)j * 4;
        __nv_bfloat162* ph = (__nv_bfloat162*)(wh + base);
        __nv_bfloat162* pl = (__nv_bfloat162*)(wl + base);
        ph[0] = __nv_bfloat162(h0, h1); ph[1] = __nv_bfloat162(h2, h3);
        pl[0] = __nv_bfloat162(l0, l1); pl[1] = __nv_bfloat162(l2, l3);
    } else {
        int i = (blockIdx.x - 1024) * 256 + threadIdx.x;
        if (i >= NROWS) return;
        const int is64 = (__ldg(p + (NROWS - 1)) == 0);
        #define GETB(idx) (is64 ? __ldg(p + 2 * (idx)) : __ldg(p + (idx)))
        int v = GETB(i);
        int lo = 0, hi = NROWS;
        while (lo < hi) { int mid = (lo + hi) >> 1; if (GETB(mid) < v) lo = mid + 1; else hi = mid; }
        g_segs[i] = lo;
        lo = 0; hi = NROWS;
        while (lo < hi) { int mid = (lo + hi) >> 1; if (GETB(mid) <= v) lo = mid + 1; else hi = mid; }
        g_sege[i] = lo;
        #undef GETB
    }
}

// ================= LayerNorm+split (both inputs, gridDim.y=2) =================
__global__ __launch_bounds__(256) void ln_split2(const float* __restrict__ xa,
                                                 const float* __restrict__ wa,
                                                 const float* __restrict__ ba,
                                                 __nv_bfloat16* __restrict__ sha,
                                                 __nv_bfloat16* __restrict__ sla,
                                                 const float* __restrict__ xb,
                                                 const float* __restrict__ wb,
                                                 const float* __restrict__ bb,
                                                 __nv_bfloat16* __restrict__ shb,
                                                 __nv_bfloat16* __restrict__ slb) {
    const float* x = (blockIdx.y == 0) ? xa : xb;
    const float* w = (blockIdx.y == 0) ? wa : wb;
    const float* b = (blockIdx.y == 0) ? ba : bb;
    __nv_bfloat16* sh_ = (blockIdx.y == 0) ? sha : shb;
    __nv_bfloat16* sl_ = (blockIdx.y == 0) ? sla : slb;

    __shared__ float red[2][4];
    const int half = threadIdx.x >> 7;
    const int t    = threadIdx.x & 127;
    const int lane = threadIdx.x & 31;
    const int w4   = (threadIdx.x >> 5) & 3;
    const int row  = blockIdx.x * 2 + half;
    float4 v = ((const float4*)(x + (size_t)row * DDIM))[t];
    float ps = warpSum(v.x + v.y + v.z + v.w);
    if (lane == 0) red[half][w4] = ps;
    __syncthreads();
    float mu = (red[half][0] + red[half][1] + red[half][2] + red[half][3]) * (1.0f / DDIM);
    __syncthreads();
    float dx = v.x - mu, dy = v.y - mu, dz = v.z - mu, dw = v.w - mu;
    float pv = warpSum(dx * dx + dy * dy + dz * dz + dw * dw);
    if (lane == 0) red[half][w4] = pv;
    __syncthreads();
    float var = (red[half][0] + red[half][1] + red[half][2] + red[half][3]) * (1.0f / DDIM);
    float r = rsqrtf(var + EPS);
    float4 wv = ((const float4*)w)[t];
    float4 bv = ((const float4*)b)[t];
    float y0 = dx * r * wv.x + bv.x;
    float y1 = dy * r * wv.y + bv.y;
    float y2 = dz * r * wv.z + bv.z;
    float y3 = dw * r * wv.w + bv.w;
    __nv_bfloat16 h0, l0, h1, l1, h2, l2, h3, l3;
    split2(y0, h0, l0); split2(y1, h1, l1);
    split2(y2, h2, l2); split2(y3, h3, l3);
    size_t o = (size_t)row * DDIM + t * 4;
    __nv_bfloat162* ph = (__nv_bfloat162*)(sh_ + o);
    __nv_bfloat162* pl = (__nv_bfloat162*)(sl_ + o);
    ph[0] = __nv_bfloat162(h0, h1); ph[1] = __nv_bfloat162(h2, h3);
    pl[0] = __nv_bfloat162(l0, l1); pl[1] = __nv_bfloat162(l2, l3);
}

__global__ __launch_bounds__(256) void ln_kernel(const float* __restrict__ x,
                                                 const float* __restrict__ w,
                                                 const float* __restrict__ b,
                                                 float* __restrict__ y) {
    __shared__ float red[2][4];
    const int half = threadIdx.x >> 7;
    const int t    = threadIdx.x & 127;
    const int lane = threadIdx.x & 31;
    const int w4   = (threadIdx.x >> 5) & 3;
    const int row  = blockIdx.x * 2 + half;
    float4 v = ((const float4*)(x + (size_t)row * DDIM))[t];
    float ps = warpSum(v.x + v.y + v.z + v.w);
    if (lane == 0) red[half][w4] = ps;
    __syncthreads();
    float mu = (red[half][0] + red[half][1] + red[half][2] + red[half][3]) * (1.0f / DDIM);
    __syncthreads();
    float dx = v.x - mu, dy = v.y - mu, dz = v.z - mu, dw = v.w - mu;
    float pv = warpSum(dx * dx + dy * dy + dz * dz + dw * dw);
    if (lane == 0) red[half][w4] = pv;
    __syncthreads();
    float var = (red[half][0] + red[half][1] + red[half][2] + red[half][3]) * (1.0f / DDIM);
    float r = rsqrtf(var + EPS);
    float4 wv = ((const float4*)w)[t];
    float4 bv = ((const float4*)b)[t];
    float4 o;
    o.x = dx * r * wv.x + bv.x;
    o.y = dy * r * wv.y + bv.y;
    o.z = dz * r * wv.z + bv.z;
    o.w = dw * r * wv.w + bv.w;
    ((float4*)(y + (size_t)row * DDIM))[t] = o;
}

// ================= mma.sync bf16-split GEMM (BK=64, 16 warps, merged z) =================
// modes: 0 = fp32 C. 1 = bias+SiLU -> bf16 split. 2 = bias+SiLU -> fp32.
//        3 = raw bf16 split (oh/ol; oh2/ol2 for z=1) + zero-fill tails of C (attn).
#define GM_STAGE 65536
#define GM_SMEM  (3 * GM_STAGE)

__device__ __forceinline__ uint32_t swz(int row, int c16) {
    return (uint32_t)(row * 128 + ((c16 ^ (row & 7)) << 4));
}
__device__ __forceinline__ float silu_f(float v) { return v / (1.0f + expf(-v)); }

__global__ __launch_bounds__(512, 1) void gemm_mma(const __nv_bfloat16* Ah,
                                                   const __nv_bfloat16* Al,
                                                   const __nv_bfloat16* Bh,
                                                   const __nv_bfloat16* Bl,
                                                   float* C,
                                                   const __nv_bfloat16* Ah2,
                                                   const __nv_bfloat16* Al2,
                                                   const __nv_bfloat16* Bh2,
                                                   const __nv_bfloat16* Bl2,
                                                   const float* bias,
                                                   __nv_bfloat16* oh,
                                                   __nv_bfloat16* ol,
                                                   __nv_bfloat16* oh2,
                                                   __nv_bfloat16* ol2,
                                                   int mode) {
    if (blockIdx.z == 1) { Ah = Ah2; Al = Al2; Bh = Bh2; Bl = Bl2; oh = oh2; ol = ol2; }
    extern __shared__ char smem[];
    const uint32_t sbase = smem_u32(smem);
    const int tid  = threadIdx.x;
    const int lane = tid & 31;
    const int wid  = tid >> 5;
    const int wm   = wid >> 2;
    const int wn   = wid & 3;
    const int bm   = blockIdx.y * 128;
    const int bn   = blockIdx.x * 128;

    float acc[2][4][4];
    #pragma unroll
    for (int mi = 0; mi < 2; mi++)
        #pragma unroll
        for (int nj = 0; nj < 4; nj++)
            #pragma unroll
            for (int c = 0; c < 4; c++) acc[mi][nj][c] = 0.0f;

    const int lr0 = tid >> 3,         lc0 = tid & 7;
    const int lr1 = (tid + 512) >> 3, lc1 = (tid + 512) & 7;
    const uint32_t so0 = swz(lr0, lc0), so1 = swz(lr1, lc1);

    const int arow = (lane & 15);
    const int acol = (lane >> 4);
    const int brow = (lane & 7) + ((lane >> 4) & 1) * 8;
    const int bcol = (lane >> 3) & 1;

    #define GM_ISSUE(st, kt) do { \
        uint32_t sb_ = sbase + (st) * GM_STAGE; \
        int k0_ = (kt) * 64; \
        size_t ga0 = (size_t)(bm + lr0) * DDIM + k0_ + lc0 * 8; \
        size_t gb0 = (size_t)(bn + lr0) * DDIM + k0_ + lc0 * 8; \
        size_t ga1 = (size_t)(bm + lr1) * DDIM + k0_ + lc1 * 8; \
        size_t gb1 = (size_t)(bn + lr1) * DDIM + k0_ + lc1 * 8; \
        CP_ASYNC16(sb_ + so0,          Ah + ga0); \
        CP_ASYNC16(sb_ + 16384 + so0,  Al + ga0); \
        CP_ASYNC16(sb_ + 32768 + so0,  Bh + gb0); \
        CP_ASYNC16(sb_ + 49152 + so0,  Bl + gb0); \
        CP_ASYNC16(sb_ + so1,          Ah + ga1); \
        CP_ASYNC16(sb_ + 16384 + so1,  Al + ga1); \
        CP_ASYNC16(sb_ + 32768 + so1,  Bh + gb1); \
        CP_ASYNC16(sb_ + 49152 + so1,  Bl + gb1); \
    } while (0)

    GM_ISSUE(0, 0); CP_COMMIT();
    GM_ISSUE(1, 1); CP_COMMIT();

    for (int kt = 0; kt < 8; kt++) {
        if (kt < 6) CP_WAIT(1); else CP_WAIT(0);
        __syncthreads();
        const uint32_t sb = sbase + (kt % 3) * GM_STAGE;

        #pragma unroll
        for (int ks = 0; ks < 4; ks++) {
            uint32_t fah[2][4], fal[2][4];
            #pragma unroll
            for (int mi = 0; mi < 2; mi++) {
                uint32_t off = swz(wm * 32 + mi * 16 + arow, ks * 2 + acol);
                LDMX4(fah[mi], sb + off);
                LDMX4(fal[mi], sb + 16384 + off);
            }
            #pragma unroll
            for (int njp = 0; njp < 4; njp += 2) {
                uint32_t off = swz(wn * 32 + njp * 8 + brow, ks * 2 + bcol);
                uint32_t fbh[4], fbl[4];
                LDMX4(fbh, sb + 32768 + off);
                LDMX4(fbl, sb + 49152 + off);
                #pragma unroll
                for (int mi = 0; mi < 2; mi++) {
                    MMA16816(acc[mi][njp],     fah[mi], fbh[0], fbh[1]);
                    MMA16816(acc[mi][njp + 1], fah[mi], fbh[2], fbh[3]);
                    MMA16816(acc[mi][njp],     fah[mi], fbl[0], fbl[1]);
                    MMA16816(acc[mi][njp + 1], fah[mi], fbl[2], fbl[3]);
                    MMA16816(acc[mi][njp],     fal[mi], fbh[0], fbh[1]);
                    MMA16816(acc[mi][njp + 1], fal[mi], fbh[2], fbh[3]);
                }
            }
        }
        if (kt + 2 < 8) { GM_ISSUE((kt + 2) % 3, kt + 2); CP_COMMIT(); }
    }
    #undef GM_ISSUE

    const int erow = lane >> 2;
    const int ecol = (lane & 3) * 2;
    #pragma unroll
    for (int mi = 0; mi < 2; mi++) {
        #pragma unroll
        for (int nj = 0; nj < 4; nj++) {
            int m0 = bm + wm * 32 + mi * 16 + erow;
            int n0 = bn + wn * 32 + nj * 8 + ecol;
            float2 v0 = make_float2(acc[mi][nj][0], acc[mi][nj][1]);
            float2 v1 = make_float2(acc[mi][nj][2], acc[mi][nj][3]);
            if (mode == 0) {
                *(float2*)(C + (size_t)m0 * DDIM + n0)       = v0;
                *(float2*)(C + (size_t)(m0 + 8) * DDIM + n0) = v1;
            } else if (mode == 3) {
                __nv_bfloat16 h0, l0, h1, l1;
                split2(v0.x, h0, l0); split2(v0.y, h1, l1);
                *(__nv_bfloat162*)(oh + (size_t)m0 * DDIM + n0) = __nv_bfloat162(h0, h1);
                *(__nv_bfloat162*)(ol + (size_t)m0 * DDIM + n0) = __nv_bfloat162(l0, l1);
                split2(v1.x, h0, l0); split2(v1.y, h1, l1);
                *(__nv_bfloat162*)(oh + (size_t)(m0 + 8) * DDIM + n0) = __nv_bfloat162(h0, h1);
                *(__nv_bfloat162*)(ol + (size_t)(m0 + 8) * DDIM + n0) = __nv_bfloat162(l0, l1);
            } else {
                float2 bv = *(const float2*)(bias + n0);
                v0.x = silu_f(v0.x + bv.x); v0.y = silu_f(v0.y + bv.y);
                v1.x = silu_f(v1.x + bv.x); v1.y = silu_f(v1.y + bv.y);
                if (mode == 2) {
                    *(float2*)(C + (size_t)m0 * DDIM + n0)       = v0;
                    *(float2*)(C + (size_t)(m0 + 8) * DDIM + n0) = v1;
                } else {
                    __nv_bfloat16 h0, l0, h1, l1;
                    split2(v0.x, h0, l0); split2(v0.y, h1, l1);
                    *(__nv_bfloat162*)(oh + (size_t)m0 * DDIM + n0) = __nv_bfloat162(h0, h1);
                    *(__nv_bfloat162*)(ol + (size_t)m0 * DDIM + n0) = __nv_bfloat162(l0, l1);
                    split2(v1.x, h0, l0); split2(v1.y, h1, l1);
                    *(__nv_bfloat162*)(oh + (size_t)(m0 + 8) * DDIM + n0) = __nv_bfloat162(h0, h1);
                    *(__nv_bfloat162*)(ol + (size_t)(m0 + 8) * DDIM + n0) = __nv_bfloat162(l0, l1);
                }
            }
        }
    }

    // mode 3 tail: zero-fill attn out-of-chunk tails (hidden behind other CTAs'
    // tensor work — this launch is otherwise DRAM-idle). Regions match
    // attn_softmax_mma's sbA/ebp exactly; disjoint from its writes.
    if (mode == 3 && C != nullptr) {
        int bid = (blockIdx.z * 64 + blockIdx.y) * 4 + blockIdx.x;   // 0..511
        const float4 z4 = make_float4(0.f, 0.f, 0.f, 0.f);
        for (int r = 0; r < 16; r++) {
            int i = bid * 16 + r;
            int r0 = i & ~63;
            int zs = g_segs[r0] & ~3;
            int ebm = g_sege[r0 + 63];
            int nch = (ebm - zs + 127) >> 7;
            int ze = min(zs + nch * 128, NROWS);
            float* row = C + (size_t)i * NROWS;
            for (int j = tid; j < (zs >> 2); j += 512) ((float4*)row)[j] = z4;
            if (ze < NROWS)
                for (int j = (ze >> 2) + tid; j < (NROWS >> 2); j += 512) ((float4*)row)[j] = z4;
        }
    }
}

// ================= tensorized masked softmax =================
// Block = 64 rows, 512 thr. S = q@k^T (3-term bf16-split mma) over kv chunks,
// masked epilogue -> attn, rowmax via smem atomicMax (init 0 = mask clamp),
// then exp/sum/normalize. Out-of-chunk zero tails are written by the q/k GEMM.
#define AS_STAGE 49152
#define AS_SMEM  (512 + 3 * AS_STAGE)

__global__ __launch_bounds__(512, 1) void attn_softmax_mma(const __nv_bfloat16* __restrict__ qh,
                                                           const __nv_bfloat16* __restrict__ ql,
                                                           const __nv_bfloat16* __restrict__ kh,
                                                           const __nv_bfloat16* __restrict__ kl,
                                                           float* __restrict__ attn) {
    extern __shared__ char smem[];
    float* rowmax = (float*)smem;
    const uint32_t sbase = smem_u32(smem) + 512;
    const int tid = threadIdx.x, lane = tid & 31, wid = tid >> 5;
    const int wm = wid >> 2, wn = wid & 3;
    const int r0 = blockIdx.x * 64;
    const int sbA = g_segs[r0] & ~3;
    const int eb  = g_sege[r0 + 63];
    const int nch = (eb - sbA + 127) >> 7;

    if (tid < 64) rowmax[tid] = 0.0f;

    const int qrow = tid >> 3, qc = tid & 7;
    const int krow0 = tid >> 3, kc0 = tid & 7;
    const int krow1 = (tid + 512) >> 3, kc1 = (tid + 512) & 7;
    const uint32_t sq  = swz(qrow, qc);
    const uint32_t sk0 = swz(krow0, kc0);
    const uint32_t sk1 = swz(krow1, kc1);

    const int arow = lane & 15, acol = lane >> 4;
    const int brow = (lane & 7) + ((lane >> 4) & 1) * 8, bcol = (lane >> 3) & 1;
    const int erow = lane >> 2, ecol = (lane & 3) * 2;
    const int row_a = r0 + wm * 16 + erow;
    const int s_a = g_segs[row_a],     e_a = g_sege[row_a];
    const int s_b = g_segs[row_a + 8], e_b = g_sege[row_a + 8];

    __syncthreads();

    for (int ch = 0; ch < nch; ch++) {
        const int kvb = sbA + ch * 128;
        if (ch > 0) __syncthreads();

        float acc[4][4];
        #pragma unroll
        for (int nj = 0; nj < 4; nj++)
            #pragma unroll
            for (int c = 0; c < 4; c++) acc[nj][c] = 0.0f;

        #define AS_ISSUE(st, kt) do { \
            uint32_t sb_ = sbase + (st) * AS_STAGE; \
            int k0_ = (kt) * 64; \
            size_t gq = (size_t)(r0 + qrow) * DDIM + k0_ + qc * 8; \
            int kr0g = min(kvb + krow0, NROWS - 1); \
            int kr1g = min(kvb + krow1, NROWS - 1); \
            size_t gk0 = (size_t)kr0g * DDIM + k0_ + kc0 * 8; \
            size_t gk1 = (size_t)kr1g * DDIM + k0_ + kc1 * 8; \
            CP_ASYNC16(sb_ + sq,           qh + gq); \
            CP_ASYNC16(sb_ + 8192 + sq,    ql + gq); \
            CP_ASYNC16(sb_ + 16384 + sk0,  kh + gk0); \
            CP_ASYNC16(sb_ + 32768 + sk0,  kl + gk0); \
            CP_ASYNC16(sb_ + 16384 + sk1,  kh + gk1); \
            CP_ASYNC16(sb_ + 32768 + sk1,  kl + gk1); \
        } while (0)

        AS_ISSUE(0, 0); CP_COMMIT();
        AS_ISSUE(1, 1); CP_COMMIT();

        for (int kt = 0; kt < 8; kt++) {
            if (kt < 6) CP_WAIT(1); else CP_WAIT(0);
            __syncthreads();
            const uint32_t sb = sbase + (kt % 3) * AS_STAGE;

            #pragma unroll
            for (int ks = 0; ks < 4; ks++) {
                uint32_t fqh[4], fql[4];
                {
                    uint32_t off = swz(wm * 16 + arow, ks * 2 + acol);
                    LDMX4(fqh, sb + off);
                    LDMX4(fql, sb + 8192 + off);
                }
                #pragma unroll
                for (int njp = 0; njp < 4; njp += 2) {
                    uint32_t off = swz(wn * 32 + njp * 8 + brow, ks * 2 + bcol);
                    uint32_t fkh[4], fkl[4];
                    LDMX4(fkh, sb + 16384 + off);
                    LDMX4(fkl, sb + 32768 + off);
                    MMA16816(acc[njp],     fqh, fkh[0], fkh[1]);
                    MMA16816(acc[njp + 1], fqh, fkh[2], fkh[3]);
                    MMA16816(acc[njp],     fqh, fkl[0], fkl[1]);
                    MMA16816(acc[njp + 1], fqh, fkl[2], fkl[3]);
                    MMA16816(acc[njp],     fql, fkh[0], fkh[1]);
                    MMA16816(acc[njp + 1], fql, fkh[2], fkh[3]);
                }
            }
            if (kt + 2 < 8) { AS_ISSUE((kt + 2) % 3, kt + 2); CP_COMMIT(); }
        }
        #undef AS_ISSUE

        float vm0 = 0.0f, vm1 = 0.0f;
        #pragma unroll
        for (int nj = 0; nj < 4; nj++) {
            int j = kvb + wn * 32 + nj * 8 + ecol;
            float2 w0, w1;
            w0.x = (j     >= s_a && j     < e_a) ? acc[nj][0] : 0.0f;
            w0.y = (j + 1 >= s_a && j + 1 < e_a) ? acc[nj][1] : 0.0f;
            w1.x = (j     >= s_b && j     < e_b) ? acc[nj][2] : 0.0f;
            w1.y = (j + 1 >= s_b && j + 1 < e_b) ? acc[nj][3] : 0.0f;
            if (j < NROWS) {
                *(float2*)(attn + (size_t)row_a * NROWS + j)       = w0;
                *(float2*)(attn + (size_t)(row_a + 8) * NROWS + j) = w1;
            }
            vm0 = fmaxf(vm0, fmaxf(w0.x, w0.y));
            vm1 = fmaxf(vm1, fmaxf(w1.x, w1.y));
        }
        vm0 = fmaxf(vm0, __shfl_xor_sync(0xffffffffu, vm0, 1));
        vm0 = fmaxf(vm0, __shfl_xor_sync(0xffffffffu, vm0, 2));
        vm1 = fmaxf(vm1, __shfl_xor_sync(0xffffffffu, vm1, 1));
        vm1 = fmaxf(vm1, __shfl_xor_sync(0xffffffffu, vm1, 2));
        if ((lane & 3) == 0) {
            atomicMax((int*)&rowmax[wm * 16 + erow],     __float_as_int(vm0));
            atomicMax((int*)&rowmax[wm * 16 + erow + 8], __float_as_int(vm1));
        }
    }
    __syncthreads();

    // softmax phase: warp w owns rows r0 + w*4 .. +3
    for (int rr = 0; rr < 4; rr++) {
        const int li = wid * 4 + rr;
        const int i = r0 + li;
        float m = rowmax[li];
        const int s = g_segs[i], e = g_sege[i];
        float* row = attn + (size_t)i * NROWS;

        float ssum = 0.0f;
        for (int j = s + lane; j < e; j += 32) {
            float ev = expf(row[j] - m);
            ssum += ev;
            row[j] = ev;
        }
        ssum = warpSum(ssum);
        float inv = 1.0f / ssum;
        for (int j = s + lane; j < e; j += 32) row[j] *= inv;
    }
}

// ================= column-parallel apply =================
// Block = 16 rows, 512 thr. Thread (rg = tid>>7, c4 = tid&127) owns 4 rows x
// 4 cols. Per j the block reads the xtile row ONCE (vs once per warp before)
// -> ~3x less smem crossbar traffic. attn zeros outside segments make masking
// free; per-(row,col) j-accumulation order identical to previous version.
#define AP_SMEM (32 * DDIM * 4 + 16 * 32 * 4)

__global__ __launch_bounds__(512) void attn_apply_col(const float* __restrict__ attn,
                                                      const float* __restrict__ xc,
                                                      __nv_bfloat16* __restrict__ sh_,
                                                      __nv_bfloat16* __restrict__ sl_) {
    extern __shared__ float smemf[];
    float* xtile = smemf;                       // [32][512]
    float* atile = smemf + 32 * DDIM;           // [16][32]
    const int tid = threadIdx.x;
    const int c4 = tid & 127;
    const int rg = tid >> 7;
    const int i0 = blockIdx.x * 16;
    const int sb = g_segs[i0], eb = g_sege[i0 + 15];

    float4 acc[4];
    #pragma unroll
    for (int rr = 0; rr < 4; rr++) acc[rr] = make_float4(0.f, 0.f, 0.f, 0.f);

    for (int t = sb; t < eb; t += 32) {
        const int tn = min(32, eb - t);
        __syncthreads();
        for (int idx = tid; idx < tn * 128; idx += 512) {
            int r = idx >> 7, c = idx & 127;
            ((float4*)xtile)[r * 128 + c] = *(const float4*)(xc + (size_t)(t + r) * DDIM + c * 4);
        }
        {
            int r = tid >> 5, jj = tid & 31;
            atile[r * 32 + jj] = (jj < tn) ? __ldg(attn + (size_t)(i0 + r) * NROWS + t + jj) : 0.0f;
        }
        __syncthreads();
        for (int jj = 0; jj < tn; jj++) {
            float4 xv = ((const float4*)xtile)[jj * 128 + c4];
            #pragma unroll
            for (int rr = 0; rr < 4; rr++) {
                float a = atile[(rg * 4 + rr) * 32 + jj];
                acc[rr].x = fmaf(a, xv.x, acc[rr].x);
                acc[rr].y = fmaf(a, xv.y, acc[rr].y);
                acc[rr].z = fmaf(a, xv.z, acc[rr].z);
                acc[rr].w = fmaf(a, xv.w, acc[rr].w);
            }
        }
    }

    #pragma unroll
    for (int rr = 0; rr < 4; rr++) {
        int i = i0 + rg * 4 + rr;
        size_t o = (size_t)i * DDIM + c4 * 4;
        __nv_bfloat16 h0, l0, h1, l1, h2, l2, h3, l3;
        split2(acc[rr].x, h0, l0); split2(acc[rr].y, h1, l1);
        split2(acc[rr].z, h2, l2); split2(acc[rr].w, h3, l3);
        __nv_bfloat162* ph = (__nv_bfloat162*)(sh_ + o);
        __nv_bfloat162* pl = (__nv_bfloat162*)(sl_ + o);
        ph[0] = __nv_bfloat162(h0, h1); ph[1] = __nv_bfloat162(h2, h3);
        pl[0] = __nv_bfloat162(l0, l1); pl[1] = __nv_bfloat162(l2, l3);
    }
}

// ================= launch =================
extern "C" void kernel_launch(void* const* d_in, const int* in_sizes, int n_in,
                              void* d_out, int out_size) {
    const float* x_mole  = (const float*)d_in[0];
    const float* x_conf  = (const float*)d_in[1];
    const float* W1      = (const float*)d_in[2];
    const float* W2      = (const float*)d_in[3];
    const float* phi1_w  = (const float*)d_in[4];
    const float* phi1_b  = (const float*)d_in[5];
    const float* phi2_w  = (const float*)d_in[6];
    const float* phi2_b  = (const float*)d_in[7];
    const float* rho_w1  = (const float*)d_in[8];
    const float* rho_b1  = (const float*)d_in[9];
    const float* rho_w2  = (const float*)d_in[10];
    const float* rho_b2  = (const float*)d_in[11];
    const float* rho_ln_w = (const float*)d_in[12];
    const float* rho_ln_b = (const float*)d_in[13];
    const int*   batch   = (const int*)d_in[14];

    float* out_enc  = (float*)d_out;
    float* out_attn = (float*)d_out + (size_t)NROWS * DDIM;

    float *k;
    __nv_bfloat16 *sh1, *sl1, *sh2, *sl2, *wh, *wl, *qh, *ql, *kh, *kl;
    cudaGetSymbolAddress((void**)&k,   g_k);
    cudaGetSymbolAddress((void**)&sh1, g_sh1);
    cudaGetSymbolAddress((void**)&sl1, g_sl1);
    cudaGetSymbolAddress((void**)&sh2, g_sh2);
    cudaGetSymbolAddress((void**)&sl2, g_sl2);
    cudaGetSymbolAddress((void**)&wh,  g_wh);
    cudaGetSymbolAddress((void**)&wl,  g_wl);
    cudaGetSymbolAddress((void**)&qh,  g_qh);
    cudaGetSymbolAddress((void**)&ql,  g_ql);
    cudaGetSymbolAddress((void**)&kh,  g_kh);
    cudaGetSymbolAddress((void**)&kl,  g_kl);
    const size_t WSZ = (size_t)DDIM * DDIM;

    cudaFuncSetAttribute(gemm_mma, cudaFuncAttributeMaxDynamicSharedMemorySize, GM_SMEM);
    cudaFuncSetAttribute(attn_softmax_mma, cudaFuncAttributeMaxDynamicSharedMemorySize, AS_SMEM);
    cudaFuncSetAttribute(attn_apply_col, cudaFuncAttributeMaxDynamicSharedMemorySize, AP_SMEM);

    dim3 ggrid1(DDIM / 128, NROWS / 128, 1);
    dim3 ggrid2(DDIM / 128, NROWS / 128, 2);
    dim3 lgrid(NROWS / 2, 2, 1);

    // 1: weight splits + segments
    wsplit_seg<<<1024 + 32, 256>>>(W1, W2, rho_w1, rho_w2, wh, wl, batch);
    // 2: both LayerNorm+splits
    ln_split2<<<lgrid, 256>>>(x_mole, phi1_w, phi1_b, sh1, sl1,
                              x_conf, phi2_w, phi2_b, sh2, sl2);
    // 3: q + k projections -> bf16 splits + attn tail zero-fill (mode 3)
    gemm_mma<<<ggrid2, 512, GM_SMEM>>>(sh1, sl1, wh + 0 * WSZ, wl + 0 * WSZ, out_attn,
                                       sh2, sl2, wh + 1 * WSZ, wl + 1 * WSZ,
                                       nullptr, qh, ql, kh, kl, 3);
    // 4: tensorized masked softmax
    attn_softmax_mma<<<NROWS / 64, 512, AS_SMEM>>>(qh, ql, kh, kl, out_attn);
    // 5: column-parallel apply
    attn_apply_col<<<NROWS / 16, 512, AP_SMEM>>>(out_attn, x_conf, sh1, sl1);

    // 6,7: rho MLP (epilogues fused)
    gemm_mma<<<ggrid1, 512, GM_SMEM>>>(sh1, sl1, wh + 2 * WSZ, wl + 2 * WSZ, nullptr,
                                       nullptr, nullptr, nullptr, nullptr,
                                       rho_b1, sh2, sl2, nullptr, nullptr, 1);
    gemm_mma<<<ggrid1, 512, GM_SMEM>>>(sh2, sl2, wh + 3 * WSZ, wl + 3 * WSZ, k,
                                       nullptr, nullptr, nullptr, nullptr,
                                       rho_b2, nullptr, nullptr, nullptr, nullptr, 2);

    // 8: final LayerNorm into output
    ln_kernel<<<NROWS / 2, 256>>>(k, rho_ln_w, rho_ln_b, out_enc);
}

// round 14
// speedup vs baseline: 1.4872x; 1.0663x over previous
#include <cuda_runtime.h>
#include <cuda_bf16.h>
#include <math.h>
#include <stdint.h>

#define NROWS 8192
#define DDIM  512
#define EPS   1e-5f

// ================= PTX helpers =================
__device__ __forceinline__ uint32_t smem_u32(const void* p) {
    uint32_t a;
    asm("{ .reg .u64 t; cvta.to.shared.u64 t, %1; cvt.u32.u64 %0, t; }" : "=r"(a) : "l"(p));
    return a;
}
#define CP_ASYNC16(smem, gptr) \
    asm volatile("cp.async.cg.shared.global [%0], [%1], 16;" :: "r"(smem), "l"(gptr))
#define CP_COMMIT() asm volatile("cp.async.commit_group;" ::: "memory")
#define CP_WAIT(n)  asm volatile("cp.async.wait_group %0;" :: "n"(n) : "memory")

#define LDMX4(r, addr) \
    asm volatile("ldmatrix.sync.aligned.m8n8.x4.shared.b16 {%0,%1,%2,%3}, [%4];" \
        : "=r"((r)[0]), "=r"((r)[1]), "=r"((r)[2]), "=r"((r)[3]) : "r"(addr))

#define LDMX4T(r, addr) \
    asm volatile("ldmatrix.sync.aligned.m8n8.x4.trans.shared.b16 {%0,%1,%2,%3}, [%4];" \
        : "=r"((r)[0]), "=r"((r)[1]), "=r"((r)[2]), "=r"((r)[3]) : "r"(addr))

#define MMA16816(d, a, b0, b1) \
    asm volatile("mma.sync.aligned.m16n8k16.row.col.f32.bf16.bf16.f32 " \
        "{%0,%1,%2,%3}, {%4,%5,%6,%7}, {%8,%9}, {%0,%1,%2,%3};" \
        : "+f"((d)[0]), "+f"((d)[1]), "+f"((d)[2]), "+f"((d)[3]) \
        : "r"((a)[0]), "r"((a)[1]), "r"((a)[2]), "r"((a)[3]), "r"(b0), "r"(b1))

// ================= scratch =================
__device__ float g_k  [NROWS * DDIM];
__device__ __nv_bfloat16 g_sh1[NROWS * DDIM];
__device__ __nv_bfloat16 g_sl1[NROWS * DDIM];
__device__ __nv_bfloat16 g_sh2[NROWS * DDIM];
__device__ __nv_bfloat16 g_sl2[NROWS * DDIM];
__device__ __nv_bfloat16 g_qh[NROWS * DDIM];
__device__ __nv_bfloat16 g_ql[NROWS * DDIM];
__device__ __nv_bfloat16 g_kh[NROWS * DDIM];
__device__ __nv_bfloat16 g_kl[NROWS * DDIM];
__device__ __nv_bfloat16 g_xch[NROWS * DDIM];
__device__ __nv_bfloat16 g_xcl[NROWS * DDIM];
__device__ __nv_bfloat16 g_wh[4][DDIM * DDIM];
__device__ __nv_bfloat16 g_wl[4][DDIM * DDIM];
__device__ int   g_segs[NROWS];
__device__ int   g_sege[NROWS];

// ================= reductions =================
__device__ __forceinline__ float warpSum(float v) {
    #pragma unroll
    for (int o = 16; o > 0; o >>= 1) v += __shfl_xor_sync(0xffffffffu, v, o);
    return v;
}

// ================= split helpers =================
__device__ __forceinline__ void split2(float v, __nv_bfloat16& hi, __nv_bfloat16& lo) {
    hi = __float2bfloat16(v);
    lo = __float2bfloat16(v - __bfloat162float(hi));
}

// ================= weight split =================
__global__ __launch_bounds__(256) void w_split_all(const float* __restrict__ W1,
                                                   const float* __restrict__ W2,
                                                   const float* __restrict__ W3,
                                                   const float* __restrict__ W4,
                                                   __nv_bfloat16* __restrict__ wh,
                                                   __nv_bfloat16* __restrict__ wl) {
    int id = blockIdx.x * 256 + threadIdx.x;
    int w = id >> 16;
    int j = id & 65535;
    const float* src = (w == 0) ? W1 : (w == 1) ? W2 : (w == 2) ? W3 : W4;
    float4 v = ((const float4*)src)[j];
    __nv_bfloat16 h0, l0, h1, l1, h2, l2, h3, l3;
    split2(v.x, h0, l0); split2(v.y, h1, l1);
    split2(v.z, h2, l2); split2(v.w, h3, l3);
    size_t base = (size_t)w * DDIM * DDIM + (size_t)j * 4;
    __nv_bfloat162* ph = (__nv_bfloat162*)(wh + base);
    __nv_bfloat162* pl = (__nv_bfloat162*)(wl + base);
    ph[0] = __nv_bfloat162(h0, h1); ph[1] = __nv_bfloat162(h2, h3);
    pl[0] = __nv_bfloat162(l0, l1); pl[1] = __nv_bfloat162(l2, l3);
}

// ================= segments =================
__global__ void seg_kernel(const int* __restrict__ p) {
    int i = blockIdx.x * blockDim.x + threadIdx.x;
    if (i >= NROWS) return;
    const int is64 = (__ldg(p + (NROWS - 1)) == 0);
    #define GETB(idx) (is64 ? __ldg(p + 2 * (idx)) : __ldg(p + (idx)))
    int v = GETB(i);
    int lo = 0, hi = NROWS;
    while (lo < hi) { int mid = (lo + hi) >> 1; if (GETB(mid) < v) lo = mid + 1; else hi = mid; }
    g_segs[i] = lo;
    lo = 0; hi = NROWS;
    while (lo < hi) { int mid = (lo + hi) >> 1; if (GETB(mid) <= v) lo = mid + 1; else hi = mid; }
    g_sege[i] = lo;
    #undef GETB
}

// ================= LayerNorm+split (both inputs; y==1 also emits raw xc split) =====
__global__ __launch_bounds__(256) void ln_split2(const float* __restrict__ xa,
                                                 const float* __restrict__ wa,
                                                 const float* __restrict__ ba,
                                                 __nv_bfloat16* __restrict__ sha,
                                                 __nv_bfloat16* __restrict__ sla,
                                                 const float* __restrict__ xb,
                                                 const float* __restrict__ wb,
                                                 const float* __restrict__ bb,
                                                 __nv_bfloat16* __restrict__ shb,
                                                 __nv_bfloat16* __restrict__ slb,
                                                 __nv_bfloat16* __restrict__ xch,
                                                 __nv_bfloat16* __restrict__ xcl) {
    const float* x = (blockIdx.y == 0) ? xa : xb;
    const float* w = (blockIdx.y == 0) ? wa : wb;
    const float* b = (blockIdx.y == 0) ? ba : bb;
    __nv_bfloat16* sh_ = (blockIdx.y == 0) ? sha : shb;
    __nv_bfloat16* sl_ = (blockIdx.y == 0) ? sla : slb;

    __shared__ float red[2][4];
    const int half = threadIdx.x >> 7;
    const int t    = threadIdx.x & 127;
    const int lane = threadIdx.x & 31;
    const int w4   = (threadIdx.x >> 5) & 3;
    const int row  = blockIdx.x * 2 + half;
    float4 v = ((const float4*)(x + (size_t)row * DDIM))[t];
    size_t o = (size_t)row * DDIM + t * 4;

    if (blockIdx.y == 1) {   // raw x_conf split for tensorized apply
        __nv_bfloat16 h0, l0, h1, l1, h2, l2, h3, l3;
        split2(v.x, h0, l0); split2(v.y, h1, l1);
        split2(v.z, h2, l2); split2(v.w, h3, l3);
        __nv_bfloat162* ph = (__nv_bfloat162*)(xch + o);
        __nv_bfloat162* pl = (__nv_bfloat162*)(xcl + o);
        ph[0] = __nv_bfloat162(h0, h1); ph[1] = __nv_bfloat162(h2, h3);
        pl[0] = __nv_bfloat162(l0, l1); pl[1] = __nv_bfloat162(l2, l3);
    }

    float ps = warpSum(v.x + v.y + v.z + v.w);
    if (lane == 0) red[half][w4] = ps;
    __syncthreads();
    float mu = (red[half][0] + red[half][1] + red[half][2] + red[half][3]) * (1.0f / DDIM);
    __syncthreads();
    float dx = v.x - mu, dy = v.y - mu, dz = v.z - mu, dw = v.w - mu;
    float pv = warpSum(dx * dx + dy * dy + dz * dz + dw * dw);
    if (lane == 0) red[half][w4] = pv;
    __syncthreads();
    float var = (red[half][0] + red[half][1] + red[half][2] + red[half][3]) * (1.0f / DDIM);
    float r = rsqrtf(var + EPS);
    float4 wv = ((const float4*)w)[t];
    float4 bv = ((const float4*)b)[t];
    float y0 = dx * r * wv.x + bv.x;
    float y1 = dy * r * wv.y + bv.y;
    float y2 = dz * r * wv.z + bv.z;
    float y3 = dw * r * wv.w + bv.w;
    __nv_bfloat16 h0, l0, h1, l1, h2, l2, h3, l3;
    split2(y0, h0, l0); split2(y1, h1, l1);
    split2(y2, h2, l2); split2(y3, h3, l3);
    __nv_bfloat162* ph = (__nv_bfloat162*)(sh_ + o);
    __nv_bfloat162* pl = (__nv_bfloat162*)(sl_ + o);
    ph[0] = __nv_bfloat162(h0, h1); ph[1] = __nv_bfloat162(h2, h3);
    pl[0] = __nv_bfloat162(l0, l1); pl[1] = __nv_bfloat162(l2, l3);
}

__global__ __launch_bounds__(256) void ln_kernel(const float* __restrict__ x,
                                                 const float* __restrict__ w,
                                                 const float* __restrict__ b,
                                                 float* __restrict__ y) {
    __shared__ float red[2][4];
    const int half = threadIdx.x >> 7;
    const int t    = threadIdx.x & 127;
    const int lane = threadIdx.x & 31;
    const int w4   = (threadIdx.x >> 5) & 3;
    const int row  = blockIdx.x * 2 + half;
    float4 v = ((const float4*)(x + (size_t)row * DDIM))[t];
    float ps = warpSum(v.x + v.y + v.z + v.w);
    if (lane == 0) red[half][w4] = ps;
    __syncthreads();
    float mu = (red[half][0] + red[half][1] + red[half][2] + red[half][3]) * (1.0f / DDIM);
    __syncthreads();
    float dx = v.x - mu, dy = v.y - mu, dz = v.z - mu, dw = v.w - mu;
    float pv = warpSum(dx * dx + dy * dy + dz * dz + dw * dw);
    if (lane == 0) red[half][w4] = pv;
    __syncthreads();
    float var = (red[half][0] + red[half][1] + red[half][2] + red[half][3]) * (1.0f / DDIM);
    float r = rsqrtf(var + EPS);
    float4 wv = ((const float4*)w)[t];
    float4 bv = ((const float4*)b)[t];
    float4 o;
    o.x = dx * r * wv.x + bv.x;
    o.y = dy * r * wv.y + bv.y;
    o.z = dz * r * wv.z + bv.z;
    o.w = dw * r * wv.w + bv.w;
    ((float4*)(y + (size_t)row * DDIM))[t] = o;
}

// ================= mma.sync bf16-split GEMM (BK=64, 16 warps, merged z) =================
// modes: 0 = fp32 C. 1 = bias+SiLU -> bf16 split. 2 = bias+SiLU -> fp32.
//        3 = raw bf16 split (oh/ol; oh2/ol2 for z=1) + zero-fill tails of C (attn).
#define GM_STAGE 65536
#define GM_SMEM  (3 * GM_STAGE)

__device__ __forceinline__ uint32_t swz(int row, int c16) {
    return (uint32_t)(row * 128 + ((c16 ^ (row & 7)) << 4));
}
__device__ __forceinline__ float silu_f(float v) { return v / (1.0f + expf(-v)); }

__global__ __launch_bounds__(512, 1) void gemm_mma(const __nv_bfloat16* Ah,
                                                   const __nv_bfloat16* Al,
                                                   const __nv_bfloat16* Bh,
                                                   const __nv_bfloat16* Bl,
                                                   float* C,
                                                   const __nv_bfloat16* Ah2,
                                                   const __nv_bfloat16* Al2,
                                                   const __nv_bfloat16* Bh2,
                                                   const __nv_bfloat16* Bl2,
                                                   const float* bias,
                                                   __nv_bfloat16* oh,
                                                   __nv_bfloat16* ol,
                                                   __nv_bfloat16* oh2,
                                                   __nv_bfloat16* ol2,
                                                   int mode) {
    if (blockIdx.z == 1) { Ah = Ah2; Al = Al2; Bh = Bh2; Bl = Bl2; oh = oh2; ol = ol2; }
    extern __shared__ char smem[];
    const uint32_t sbase = smem_u32(smem);
    const int tid  = threadIdx.x;
    const int lane = tid & 31;
    const int wid  = tid >> 5;
    const int wm   = wid >> 2;
    const int wn   = wid & 3;
    const int bm   = blockIdx.y * 128;
    const int bn   = blockIdx.x * 128;

    float acc[2][4][4];
    #pragma unroll
    for (int mi = 0; mi < 2; mi++)
        #pragma unroll
        for (int nj = 0; nj < 4; nj++)
            #pragma unroll
            for (int c = 0; c < 4; c++) acc[mi][nj][c] = 0.0f;

    const int lr0 = tid >> 3,         lc0 = tid & 7;
    const int lr1 = (tid + 512) >> 3, lc1 = (tid + 512) & 7;
    const uint32_t so0 = swz(lr0, lc0), so1 = swz(lr1, lc1);

    const int arow = (lane & 15);
    const int acol = (lane >> 4);
    const int brow = (lane & 7) + ((lane >> 4) & 1) * 8;
    const int bcol = (lane >> 3) & 1;

    #define GM_ISSUE(st, kt) do { \
        uint32_t sb_ = sbase + (st) * GM_STAGE; \
        int k0_ = (kt) * 64; \
        size_t ga0 = (size_t)(bm + lr0) * DDIM + k0_ + lc0 * 8; \
        size_t gb0 = (size_t)(bn + lr0) * DDIM + k0_ + lc0 * 8; \
        size_t ga1 = (size_t)(bm + lr1) * DDIM + k0_ + lc1 * 8; \
        size_t gb1 = (size_t)(bn + lr1) * DDIM + k0_ + lc1 * 8; \
        CP_ASYNC16(sb_ + so0,          Ah + ga0); \
        CP_ASYNC16(sb_ + 16384 + so0,  Al + ga0); \
        CP_ASYNC16(sb_ + 32768 + so0,  Bh + gb0); \
        CP_ASYNC16(sb_ + 49152 + so0,  Bl + gb0); \
        CP_ASYNC16(sb_ + so1,          Ah + ga1); \
        CP_ASYNC16(sb_ + 16384 + so1,  Al + ga1); \
        CP_ASYNC16(sb_ + 32768 + so1,  Bh + gb1); \
        CP_ASYNC16(sb_ + 49152 + so1,  Bl + gb1); \
    } while (0)

    GM_ISSUE(0, 0); CP_COMMIT();
    GM_ISSUE(1, 1); CP_COMMIT();

    for (int kt = 0; kt < 8; kt++) {
        if (kt < 6) CP_WAIT(1); else CP_WAIT(0);
        __syncthreads();
        const uint32_t sb = sbase + (kt % 3) * GM_STAGE;

        #pragma unroll
        for (int ks = 0; ks < 4; ks++) {
            uint32_t fah[2][4], fal[2][4];
            #pragma unroll
            for (int mi = 0; mi < 2; mi++) {
                uint32_t off = swz(wm * 32 + mi * 16 + arow, ks * 2 + acol);
                LDMX4(fah[mi], sb + off);
                LDMX4(fal[mi], sb + 16384 + off);
            }
            #pragma unroll
            for (int njp = 0; njp < 4; njp += 2) {
                uint32_t off = swz(wn * 32 + njp * 8 + brow, ks * 2 + bcol);
                uint32_t fbh[4], fbl[4];
                LDMX4(fbh, sb + 32768 + off);
                LDMX4(fbl, sb + 49152 + off);
                #pragma unroll
                for (int mi = 0; mi < 2; mi++) {
                    MMA16816(acc[mi][njp],     fah[mi], fbh[0], fbh[1]);
                    MMA16816(acc[mi][njp + 1], fah[mi], fbh[2], fbh[3]);
                    MMA16816(acc[mi][njp],     fah[mi], fbl[0], fbl[1]);
                    MMA16816(acc[mi][njp + 1], fah[mi], fbl[2], fbl[3]);
                    MMA16816(acc[mi][njp],     fal[mi], fbh[0], fbh[1]);
                    MMA16816(acc[mi][njp + 1], fal[mi], fbh[2], fbh[3]);
                }
            }
        }
        if (kt + 2 < 8) { GM_ISSUE((kt + 2) % 3, kt + 2); CP_COMMIT(); }
    }
    #undef GM_ISSUE

    const int erow = lane >> 2;
    const int ecol = (lane & 3) * 2;
    #pragma unroll
    for (int mi = 0; mi < 2; mi++) {
        #pragma unroll
        for (int nj = 0; nj < 4; nj++) {
            int m0 = bm + wm * 32 + mi * 16 + erow;
            int n0 = bn + wn * 32 + nj * 8 + ecol;
            float2 v0 = make_float2(acc[mi][nj][0], acc[mi][nj][1]);
            float2 v1 = make_float2(acc[mi][nj][2], acc[mi][nj][3]);
            if (mode == 0) {
                *(float2*)(C + (size_t)m0 * DDIM + n0)       = v0;
                *(float2*)(C + (size_t)(m0 + 8) * DDIM + n0) = v1;
            } else if (mode == 3) {
                __nv_bfloat16 h0, l0, h1, l1;
                split2(v0.x, h0, l0); split2(v0.y, h1, l1);
                *(__nv_bfloat162*)(oh + (size_t)m0 * DDIM + n0) = __nv_bfloat162(h0, h1);
                *(__nv_bfloat162*)(ol + (size_t)m0 * DDIM + n0) = __nv_bfloat162(l0, l1);
                split2(v1.x, h0, l0); split2(v1.y, h1, l1);
                *(__nv_bfloat162*)(oh + (size_t)(m0 + 8) * DDIM + n0) = __nv_bfloat162(h0, h1);
                *(__nv_bfloat162*)(ol + (size_t)(m0 + 8) * DDIM + n0) = __nv_bfloat162(l0, l1);
            } else {
                float2 bv = *(const float2*)(bias + n0);
                v0.x = silu_f(v0.x + bv.x); v0.y = silu_f(v0.y + bv.y);
                v1.x = silu_f(v1.x + bv.x); v1.y = silu_f(v1.y + bv.y);
                if (mode == 2) {
                    *(float2*)(C + (size_t)m0 * DDIM + n0)       = v0;
                    *(float2*)(C + (size_t)(m0 + 8) * DDIM + n0) = v1;
                } else {
                    __nv_bfloat16 h0, l0, h1, l1;
                    split2(v0.x, h0, l0); split2(v0.y, h1, l1);
                    *(__nv_bfloat162*)(oh + (size_t)m0 * DDIM + n0) = __nv_bfloat162(h0, h1);
                    *(__nv_bfloat162*)(ol + (size_t)m0 * DDIM + n0) = __nv_bfloat162(l0, l1);
                    split2(v1.x, h0, l0); split2(v1.y, h1, l1);
                    *(__nv_bfloat162*)(oh + (size_t)(m0 + 8) * DDIM + n0) = __nv_bfloat162(h0, h1);
                    *(__nv_bfloat162*)(ol + (size_t)(m0 + 8) * DDIM + n0) = __nv_bfloat162(l0, l1);
                }
            }
        }
    }

    // mode 3 tail: zero-fill attn out-of-chunk tails (hidden behind tensor work)
    if (mode == 3 && C != nullptr) {
        int bid = (blockIdx.z * 64 + blockIdx.y) * 4 + blockIdx.x;   // 0..511
        const float4 z4 = make_float4(0.f, 0.f, 0.f, 0.f);
        for (int r = 0; r < 16; r++) {
            int i = bid * 16 + r;
            int r0 = i & ~63;
            int zs = g_segs[r0] & ~3;
            int ebm = g_sege[r0 + 63];
            int nch = (ebm - zs + 127) >> 7;
            int ze = min(zs + nch * 128, NROWS);
            float* row = C + (size_t)i * NROWS;
            for (int j = tid; j < (zs >> 2); j += 512) ((float4*)row)[j] = z4;
            if (ze < NROWS)
                for (int j = (ze >> 2) + tid; j < (NROWS >> 2); j += 512) ((float4*)row)[j] = z4;
        }
    }
}

// ================= tensorized masked softmax =================
#define AS_STAGE 49152
#define AS_SMEM  (512 + 3 * AS_STAGE)

__global__ __launch_bounds__(512, 1) void attn_softmax_mma(const __nv_bfloat16* __restrict__ qh,
                                                           const __nv_bfloat16* __restrict__ ql,
                                                           const __nv_bfloat16* __restrict__ kh,
                                                           const __nv_bfloat16* __restrict__ kl,
                                                           float* __restrict__ attn) {
    extern __shared__ char smem[];
    float* rowmax = (float*)smem;
    const uint32_t sbase = smem_u32(smem) + 512;
    const int tid = threadIdx.x, lane = tid & 31, wid = tid >> 5;
    const int wm = wid >> 2, wn = wid & 3;
    const int r0 = blockIdx.x * 64;
    const int sbA = g_segs[r0] & ~3;
    const int eb  = g_sege[r0 + 63];
    const int nch = (eb - sbA + 127) >> 7;

    if (tid < 64) rowmax[tid] = 0.0f;

    const int qrow = tid >> 3, qc = tid & 7;
    const int krow0 = tid >> 3, kc0 = tid & 7;
    const int krow1 = (tid + 512) >> 3, kc1 = (tid + 512) & 7;
    const uint32_t sq  = swz(qrow, qc);
    const uint32_t sk0 = swz(krow0, kc0);
    const uint32_t sk1 = swz(krow1, kc1);

    const int arow = lane & 15, acol = lane >> 4;
    const int brow = (lane & 7) + ((lane >> 4) & 1) * 8, bcol = (lane >> 3) & 1;
    const int erow = lane >> 2, ecol = (lane & 3) * 2;
    const int row_a = r0 + wm * 16 + erow;
    const int s_a = g_segs[row_a],     e_a = g_sege[row_a];
    const int s_b = g_segs[row_a + 8], e_b = g_sege[row_a + 8];

    __syncthreads();

    for (int ch = 0; ch < nch; ch++) {
        const int kvb = sbA + ch * 128;
        if (ch > 0) __syncthreads();

        float acc[4][4];
        #pragma unroll
        for (int nj = 0; nj < 4; nj++)
            #pragma unroll
            for (int c = 0; c < 4; c++) acc[nj][c] = 0.0f;

        #define AS_ISSUE(st, kt) do { \
            uint32_t sb_ = sbase + (st) * AS_STAGE; \
            int k0_ = (kt) * 64; \
            size_t gq = (size_t)(r0 + qrow) * DDIM + k0_ + qc * 8; \
            int kr0g = min(kvb + krow0, NROWS - 1); \
            int kr1g = min(kvb + krow1, NROWS - 1); \
            size_t gk0 = (size_t)kr0g * DDIM + k0_ + kc0 * 8; \
            size_t gk1 = (size_t)kr1g * DDIM + k0_ + kc1 * 8; \
            CP_ASYNC16(sb_ + sq,           qh + gq); \
            CP_ASYNC16(sb_ + 8192 + sq,    ql + gq); \
            CP_ASYNC16(sb_ + 16384 + sk0,  kh + gk0); \
            CP_ASYNC16(sb_ + 32768 + sk0,  kl + gk0); \
            CP_ASYNC16(sb_ + 16384 + sk1,  kh + gk1); \
            CP_ASYNC16(sb_ + 32768 + sk1,  kl + gk1); \
        } while (0)

        AS_ISSUE(0, 0); CP_COMMIT();
        AS_ISSUE(1, 1); CP_COMMIT();

        for (int kt = 0; kt < 8; kt++) {
            if (kt < 6) CP_WAIT(1); else CP_WAIT(0);
            __syncthreads();
            const uint32_t sb = sbase + (kt % 3) * AS_STAGE;

            #pragma unroll
            for (int ks = 0; ks < 4; ks++) {
                uint32_t fqh[4], fql[4];
                {
                    uint32_t off = swz(wm * 16 + arow, ks * 2 + acol);
                    LDMX4(fqh, sb + off);
                    LDMX4(fql, sb + 8192 + off);
                }
                #pragma unroll
                for (int njp = 0; njp < 4; njp += 2) {
                    uint32_t off = swz(wn * 32 + njp * 8 + brow, ks * 2 + bcol);
                    uint32_t fkh[4], fkl[4];
                    LDMX4(fkh, sb + 16384 + off);
                    LDMX4(fkl, sb + 32768 + off);
                    MMA16816(acc[njp],     fqh, fkh[0], fkh[1]);
                    MMA16816(acc[njp + 1], fqh, fkh[2], fkh[3]);
                    MMA16816(acc[njp],     fqh, fkl[0], fkl[1]);
                    MMA16816(acc[njp + 1], fqh, fkl[2], fkl[3]);
                    MMA16816(acc[njp],     fql, fkh[0], fkh[1]);
                    MMA16816(acc[njp + 1], fql, fkh[2], fkh[3]);
                }
            }
            if (kt + 2 < 8) { AS_ISSUE((kt + 2) % 3, kt + 2); CP_COMMIT(); }
        }
        #undef AS_ISSUE

        float vm0 = 0.0f, vm1 = 0.0f;
        #pragma unroll
        for (int nj = 0; nj < 4; nj++) {
            int j = kvb + wn * 32 + nj * 8 + ecol;
            float2 w0, w1;
            w0.x = (j     >= s_a && j     < e_a) ? acc[nj][0] : 0.0f;
            w0.y = (j + 1 >= s_a && j + 1 < e_a) ? acc[nj][1] : 0.0f;
            w1.x = (j     >= s_b && j     < e_b) ? acc[nj][2] : 0.0f;
            w1.y = (j + 1 >= s_b && j + 1 < e_b) ? acc[nj][3] : 0.0f;
            if (j < NROWS) {
                *(float2*)(attn + (size_t)row_a * NROWS + j)       = w0;
                *(float2*)(attn + (size_t)(row_a + 8) * NROWS + j) = w1;
            }
            vm0 = fmaxf(vm0, fmaxf(w0.x, w0.y));
            vm1 = fmaxf(vm1, fmaxf(w1.x, w1.y));
        }
        vm0 = fmaxf(vm0, __shfl_xor_sync(0xffffffffu, vm0, 1));
        vm0 = fmaxf(vm0, __shfl_xor_sync(0xffffffffu, vm0, 2));
        vm1 = fmaxf(vm1, __shfl_xor_sync(0xffffffffu, vm1, 1));
        vm1 = fmaxf(vm1, __shfl_xor_sync(0xffffffffu, vm1, 2));
        if ((lane & 3) == 0) {
            atomicMax((int*)&rowmax[wm * 16 + erow],     __float_as_int(vm0));
            atomicMax((int*)&rowmax[wm * 16 + erow + 8], __float_as_int(vm1));
        }
    }
    __syncthreads();

    for (int rr = 0; rr < 4; rr++) {
        const int li = wid * 4 + rr;
        const int i = r0 + li;
        float m = rowmax[li];
        const int s = g_segs[i], e = g_sege[i];
        float* row = attn + (size_t)i * NROWS;

        float ssum = 0.0f;
        for (int j = s + lane; j < e; j += 32) {
            float ev = expf(row[j] - m);
            ssum += ev;
            row[j] = ev;
        }
        ssum = warpSum(ssum);
        float inv = 1.0f / ssum;
        for (int j = s + lane; j < e; j += 32) row[j] *= inv;
    }
}

// ================= tensorized apply: x_weighted = attn @ x_conf =================
// grid (128 row-tiles, 4 col-tiles), 512 thr (16 warps: wm 0..3 m16, wn 0..3 n32).
// Per kv chunk of 64: A = attn tile (LDG fp32 -> split2 -> swizzled STS bf16);
// B = xc split via cp.async; B fragments via ldmatrix.x4.trans (row-major KxN).
// attn's zeros outside segments make masking exact and free.
// smem: sAh[8K] sAl[8K] sBh[16K] sBl[16K] = 48K (single stage).
#define AP_SMEM 49152

__global__ __launch_bounds__(512, 1) void attn_apply_mma(const float* __restrict__ attn,
                                                         const __nv_bfloat16* __restrict__ xch,
                                                         const __nv_bfloat16* __restrict__ xcl,
                                                         __nv_bfloat16* __restrict__ oh,
                                                         __nv_bfloat16* __restrict__ ol) {
    extern __shared__ char smem[];
    const uint32_t sbase = smem_u32(smem);
    const int tid = threadIdx.x, lane = tid & 31, wid = tid >> 5;
    const int wm = wid >> 2, wn = wid & 3;
    const int r0 = blockIdx.x * 64;
    const int c0 = blockIdx.y * 128;
    const int sbA = g_segs[r0] & ~63;
    const int eb  = g_sege[r0 + 63];
    const int nch = (eb - sbA + 63) >> 6;

    float acc[4][4];
    #pragma unroll
    for (int nj = 0; nj < 4; nj++)
        #pragma unroll
        for (int c = 0; c < 4; c++) acc[nj][c] = 0.0f;

    // A conversion coords: row 0..63, c16 0..7 (8 x 16B-bf16 chunks per 128B row)
    const int ar = tid >> 3, ac16 = tid & 7;
    // A fragment coords
    const int farow = lane & 15, facol = lane >> 4;
    // B fragment (trans) coords
    const int bkr = (lane & 7) + ((lane >> 3) & 1) * 8;
    const int bco = (lane >> 4) & 1;

    for (int ch = 0; ch < nch; ch++) {
        const int kvb = sbA + ch * 64;
        __syncthreads();                       // smem reuse across chunks

        // B: xc split tiles [64 kv rows][128 cols] hi+lo, cp.async 16B chunks.
        // 1024 chunks per array / 512 thr = 2 each.
        #pragma unroll
        for (int i = 0; i < 2; i++) {
            int id = tid + i * 512;
            int r = id >> 4, c = id & 15;
            uint32_t dst = (uint32_t)(r * 256 + ((c ^ (r & 15)) << 4));
            size_t src = (size_t)(kvb + r) * DDIM + c0 + c * 8;
            CP_ASYNC16(sbase + 16384 + dst, xch + src);
            CP_ASYNC16(sbase + 32768 + dst, xcl + src);
        }
        CP_COMMIT();

        // A: attn fp32 -> bf16 split -> swizzled smem (row-major 64x64, 128B rows)
        {
            const float* ap = attn + (size_t)(r0 + ar) * NROWS + kvb + ac16 * 8;
            float4 v0 = *(const float4*)(ap);
            float4 v1 = *(const float4*)(ap + 4);
            __nv_bfloat162 hh[4], ll[4];
            __nv_bfloat16 h, l;
            split2(v0.x, h, l); __nv_bfloat16 h2, l2; split2(v0.y, h2, l2);
            hh[0] = __nv_bfloat162(h, h2); ll[0] = __nv_bfloat162(l, l2);
            split2(v0.z, h, l); split2(v0.w, h2, l2);
            hh[1] = __nv_bfloat162(h, h2); ll[1] = __nv_bfloat162(l, l2);
            split2(v1.x, h, l); split2(v1.y, h2, l2);
            hh[2] = __nv_bfloat162(h, h2); ll[2] = __nv_bfloat162(l, l2);
            split2(v1.z, h, l); split2(v1.w, h2, l2);
            hh[3] = __nv_bfloat162(h, h2); ll[3] = __nv_bfloat162(l, l2);
            uint32_t off = swz(ar, ac16);
            *(uint4*)(smem + off)        = *(uint4*)hh;
            *(uint4*)(smem + 8192 + off) = *(uint4*)ll;
        }
        CP_WAIT(0);
        __syncthreads();

        #pragma unroll
        for (int ks = 0; ks < 4; ks++) {
            uint32_t fah[4], fal[4];
            {
                uint32_t off = swz(wm * 16 + farow, ks * 2 + facol);
                LDMX4(fah, sbase + off);
                LDMX4(fal, sbase + 8192 + off);
            }
            #pragma unroll
            for (int half = 0; half < 2; half++) {
                int rowB = ks * 16 + bkr;
                int cB = wn * 4 + half * 2 + bco;
                uint32_t off = (uint32_t)(rowB * 256 + ((cB ^ (rowB & 15)) << 4));
                uint32_t fbh[4], fbl[4];
                LDMX4T(fbh, sbase + 16384 + off);
                LDMX4T(fbl, sbase + 32768 + off);
                MMA16816(acc[half * 2],     fah, fbh[0], fbh[1]);
                MMA16816(acc[half * 2 + 1], fah, fbh[2], fbh[3]);
                MMA16816(acc[half * 2],     fah, fbl[0], fbl[1]);
                MMA16816(acc[half * 2 + 1], fah, fbl[2], fbl[3]);
                MMA16816(acc[half * 2],     fal, fbh[0], fbh[1]);
                MMA16816(acc[half * 2 + 1], fal, fbh[2], fbh[3]);
            }
        }
    }

    const int erow = lane >> 2;
    const int ecol = (lane & 3) * 2;
    #pragma unroll
    for (int nj = 0; nj < 4; nj++) {
        int m0 = r0 + wm * 16 + erow;
        int n0 = c0 + wn * 32 + nj * 8 + ecol;
        __nv_bfloat16 h0, l0, h1, l1;
        split2(acc[nj][0], h0, l0); split2(acc[nj][1], h1, l1);
        *(__nv_bfloat162*)(oh + (size_t)m0 * DDIM + n0) = __nv_bfloat162(h0, h1);
        *(__nv_bfloat162*)(ol + (size_t)m0 * DDIM + n0) = __nv_bfloat162(l0, l1);
        split2(acc[nj][2], h0, l0); split2(acc[nj][3], h1, l1);
        *(__nv_bfloat162*)(oh + (size_t)(m0 + 8) * DDIM + n0) = __nv_bfloat162(h0, h1);
        *(__nv_bfloat162*)(ol + (size_t)(m0 + 8) * DDIM + n0) = __nv_bfloat162(l0, l1);
    }
}

// ================= launch =================
extern "C" void kernel_launch(void* const* d_in, const int* in_sizes, int n_in,
                              void* d_out, int out_size) {
    const float* x_mole  = (const float*)d_in[0];
    const float* x_conf  = (const float*)d_in[1];
    const float* W1      = (const float*)d_in[2];
    const float* W2      = (const float*)d_in[3];
    const float* phi1_w  = (const float*)d_in[4];
    const float* phi1_b  = (const float*)d_in[5];
    const float* phi2_w  = (const float*)d_in[6];
    const float* phi2_b  = (const float*)d_in[7];
    const float* rho_w1  = (const float*)d_in[8];
    const float* rho_b1  = (const float*)d_in[9];
    const float* rho_w2  = (const float*)d_in[10];
    const float* rho_b2  = (const float*)d_in[11];
    const float* rho_ln_w = (const float*)d_in[12];
    const float* rho_ln_b = (const float*)d_in[13];
    const int*   batch   = (const int*)d_in[14];

    float* out_enc  = (float*)d_out;
    float* out_attn = (float*)d_out + (size_t)NROWS * DDIM;

    float *k;
    __nv_bfloat16 *sh1, *sl1, *sh2, *sl2, *wh, *wl, *qh, *ql, *kh, *kl, *xch, *xcl;
    cudaGetSymbolAddress((void**)&k,   g_k);
    cudaGetSymbolAddress((void**)&sh1, g_sh1);
    cudaGetSymbolAddress((void**)&sl1, g_sl1);
    cudaGetSymbolAddress((void**)&sh2, g_sh2);
    cudaGetSymbolAddress((void**)&sl2, g_sl2);
    cudaGetSymbolAddress((void**)&wh,  g_wh);
    cudaGetSymbolAddress((void**)&wl,  g_wl);
    cudaGetSymbolAddress((void**)&qh,  g_qh);
    cudaGetSymbolAddress((void**)&ql,  g_ql);
    cudaGetSymbolAddress((void**)&kh,  g_kh);
    cudaGetSymbolAddress((void**)&kl,  g_kl);
    cudaGetSymbolAddress((void**)&xch, g_xch);
    cudaGetSymbolAddress((void**)&xcl, g_xcl);
    const size_t WSZ = (size_t)DDIM * DDIM;

    cudaFuncSetAttribute(gemm_mma, cudaFuncAttributeMaxDynamicSharedMemorySize, GM_SMEM);
    cudaFuncSetAttribute(attn_softmax_mma, cudaFuncAttributeMaxDynamicSharedMemorySize, AS_SMEM);
    cudaFuncSetAttribute(attn_apply_mma, cudaFuncAttributeMaxDynamicSharedMemorySize, AP_SMEM);

    dim3 ggrid1(DDIM / 128, NROWS / 128, 1);
    dim3 ggrid2(DDIM / 128, NROWS / 128, 2);
    dim3 lgrid(NROWS / 2, 2, 1);
    dim3 agrid(NROWS / 64, 4, 1);

    // 1: weight splits   2: segments   3: LN+splits (+raw xc split)
    w_split_all<<<1024, 256>>>(W1, W2, rho_w1, rho_w2, wh, wl);
    seg_kernel<<<NROWS / 256, 256>>>(batch);
    ln_split2<<<lgrid, 256>>>(x_mole, phi1_w, phi1_b, sh1, sl1,
                              x_conf, phi2_w, phi2_b, sh2, sl2, xch, xcl);
    // 4: q + k projections -> bf16 splits + attn tail zero-fill (ncu position)
    gemm_mma<<<ggrid2, 512, GM_SMEM>>>(sh1, sl1, wh + 0 * WSZ, wl + 0 * WSZ, out_attn,
                                       sh2, sl2, wh + 1 * WSZ, wl + 1 * WSZ,
                                       nullptr, qh, ql, kh, kl, 3);
    // 5: tensorized masked softmax
    attn_softmax_mma<<<NROWS / 64, 512, AS_SMEM>>>(qh, ql, kh, kl, out_attn);
    // 6: tensorized apply -> bf16 split for rho1
    attn_apply_mma<<<agrid, 512, AP_SMEM>>>(out_attn, xch, xcl, sh1, sl1);

    // 7,8: rho MLP (epilogues fused)
    gemm_mma<<<ggrid1, 512, GM_SMEM>>>(sh1, sl1, wh + 2 * WSZ, wl + 2 * WSZ, nullptr,
                                       nullptr, nullptr, nullptr, nullptr,
                                       rho_b1, sh2, sl2, nullptr, nullptr, 1);
    gemm_mma<<<ggrid1, 512, GM_SMEM>>>(sh2, sl2, wh + 3 * WSZ, wl + 3 * WSZ, k,
                                       nullptr, nullptr, nullptr, nullptr,
                                       rho_b2, nullptr, nullptr, nullptr, nullptr, 2);

    // 9: final LayerNorm into output
    ln_kernel<<<NROWS / 2, 256>>>(k, rho_ln_w, rho_ln_b, out_enc);
}

// round 15
// speedup vs baseline: 1.5179x; 1.0206x over previous
#include <cuda_runtime.h>
#include <cuda_bf16.h>
#include <math.h>
#include <stdint.h>

#define NROWS 8192
#define DDIM  512
#define EPS   1e-5f

// ================= PTX helpers =================
__device__ __forceinline__ uint32_t smem_u32(const void* p) {
    uint32_t a;
    asm("{ .reg .u64 t; cvta.to.shared.u64 t, %1; cvt.u32.u64 %0, t; }" : "=r"(a) : "l"(p));
    return a;
}
#define CP_ASYNC16(smem, gptr) \
    asm volatile("cp.async.cg.shared.global [%0], [%1], 16;" :: "r"(smem), "l"(gptr))
#define CP_COMMIT() asm volatile("cp.async.commit_group;" ::: "memory")
#define CP_WAIT(n)  asm volatile("cp.async.wait_group %0;" :: "n"(n) : "memory")

#define LDMX4(r, addr) \
    asm volatile("ldmatrix.sync.aligned.m8n8.x4.shared.b16 {%0,%1,%2,%3}, [%4];" \
        : "=r"((r)[0]), "=r"((r)[1]), "=r"((r)[2]), "=r"((r)[3]) : "r"(addr))

#define LDMX4T(r, addr) \
    asm volatile("ldmatrix.sync.aligned.m8n8.x4.trans.shared.b16 {%0,%1,%2,%3}, [%4];" \
        : "=r"((r)[0]), "=r"((r)[1]), "=r"((r)[2]), "=r"((r)[3]) : "r"(addr))

#define MMA16816(d, a, b0, b1) \
    asm volatile("mma.sync.aligned.m16n8k16.row.col.f32.bf16.bf16.f32 " \
        "{%0,%1,%2,%3}, {%4,%5,%6,%7}, {%8,%9}, {%0,%1,%2,%3};" \
        : "+f"((d)[0]), "+f"((d)[1]), "+f"((d)[2]), "+f"((d)[3]) \
        : "r"((a)[0]), "r"((a)[1]), "r"((a)[2]), "r"((a)[3]), "r"(b0), "r"(b1))

// ================= scratch =================
__device__ float g_k  [NROWS * DDIM];
__device__ __nv_bfloat16 g_sh1[NROWS * DDIM];
__device__ __nv_bfloat16 g_sl1[NROWS * DDIM];
__device__ __nv_bfloat16 g_sh2[NROWS * DDIM];
__device__ __nv_bfloat16 g_sl2[NROWS * DDIM];
__device__ __nv_bfloat16 g_qh[NROWS * DDIM];
__device__ __nv_bfloat16 g_ql[NROWS * DDIM];
__device__ __nv_bfloat16 g_kh[NROWS * DDIM];
__device__ __nv_bfloat16 g_kl[NROWS * DDIM];
__device__ __nv_bfloat16 g_xch[NROWS * DDIM];
__device__ __nv_bfloat16 g_xcl[NROWS * DDIM];
__device__ __nv_bfloat16 g_wh[4][DDIM * DDIM];
__device__ __nv_bfloat16 g_wl[4][DDIM * DDIM];
__device__ int   g_segs[NROWS];
__device__ int   g_sege[NROWS];

// ================= reductions =================
__device__ __forceinline__ float warpSum(float v) {
    #pragma unroll
    for (int o = 16; o > 0; o >>= 1) v += __shfl_xor_sync(0xffffffffu, v, o);
    return v;
}

// ================= split helpers =================
__device__ __forceinline__ void split2(float v, __nv_bfloat16& hi, __nv_bfloat16& lo) {
    hi = __float2bfloat16(v);
    lo = __float2bfloat16(v - __bfloat162float(hi));
}

// ================= weight split =================
__global__ __launch_bounds__(256) void w_split_all(const float* __restrict__ W1,
                                                   const float* __restrict__ W2,
                                                   const float* __restrict__ W3,
                                                   const float* __restrict__ W4,
                                                   __nv_bfloat16* __restrict__ wh,
                                                   __nv_bfloat16* __restrict__ wl) {
    int id = blockIdx.x * 256 + threadIdx.x;
    int w = id >> 16;
    int j = id & 65535;
    const float* src = (w == 0) ? W1 : (w == 1) ? W2 : (w == 2) ? W3 : W4;
    float4 v = ((const float4*)src)[j];
    __nv_bfloat16 h0, l0, h1, l1, h2, l2, h3, l3;
    split2(v.x, h0, l0); split2(v.y, h1, l1);
    split2(v.z, h2, l2); split2(v.w, h3, l3);
    size_t base = (size_t)w * DDIM * DDIM + (size_t)j * 4;
    __nv_bfloat162* ph = (__nv_bfloat162*)(wh + base);
    __nv_bfloat162* pl = (__nv_bfloat162*)(wl + base);
    ph[0] = __nv_bfloat162(h0, h1); ph[1] = __nv_bfloat162(h2, h3);
    pl[0] = __nv_bfloat162(l0, l1); pl[1] = __nv_bfloat162(l2, l3);
}

// ================= segments =================
__global__ void seg_kernel(const int* __restrict__ p) {
    int i = blockIdx.x * blockDim.x + threadIdx.x;
    if (i >= NROWS) return;
    const int is64 = (__ldg(p + (NROWS - 1)) == 0);
    #define GETB(idx) (is64 ? __ldg(p + 2 * (idx)) : __ldg(p + (idx)))
    int v = GETB(i);
    int lo = 0, hi = NROWS;
    while (lo < hi) { int mid = (lo + hi) >> 1; if (GETB(mid) < v) lo = mid + 1; else hi = mid; }
    g_segs[i] = lo;
    lo = 0; hi = NROWS;
    while (lo < hi) { int mid = (lo + hi) >> 1; if (GETB(mid) <= v) lo = mid + 1; else hi = mid; }
    g_sege[i] = lo;
    #undef GETB
}

// ================= LayerNorm+split (both inputs; y==1 also emits raw xc split) =====
__global__ __launch_bounds__(256) void ln_split2(const float* __restrict__ xa,
                                                 const float* __restrict__ wa,
                                                 const float* __restrict__ ba,
                                                 __nv_bfloat16* __restrict__ sha,
                                                 __nv_bfloat16* __restrict__ sla,
                                                 const float* __restrict__ xb,
                                                 const float* __restrict__ wb,
                                                 const float* __restrict__ bb,
                                                 __nv_bfloat16* __restrict__ shb,
                                                 __nv_bfloat16* __restrict__ slb,
                                                 __nv_bfloat16* __restrict__ xch,
                                                 __nv_bfloat16* __restrict__ xcl) {
    const float* x = (blockIdx.y == 0) ? xa : xb;
    const float* w = (blockIdx.y == 0) ? wa : wb;
    const float* b = (blockIdx.y == 0) ? ba : bb;
    __nv_bfloat16* sh_ = (blockIdx.y == 0) ? sha : shb;
    __nv_bfloat16* sl_ = (blockIdx.y == 0) ? sla : slb;

    __shared__ float red[2][4];
    const int half = threadIdx.x >> 7;
    const int t    = threadIdx.x & 127;
    const int lane = threadIdx.x & 31;
    const int w4   = (threadIdx.x >> 5) & 3;
    const int row  = blockIdx.x * 2 + half;
    float4 v = ((const float4*)(x + (size_t)row * DDIM))[t];
    size_t o = (size_t)row * DDIM + t * 4;

    if (blockIdx.y == 1) {
        __nv_bfloat16 h0, l0, h1, l1, h2, l2, h3, l3;
        split2(v.x, h0, l0); split2(v.y, h1, l1);
        split2(v.z, h2, l2); split2(v.w, h3, l3);
        __nv_bfloat162* ph = (__nv_bfloat162*)(xch + o);
        __nv_bfloat162* pl = (__nv_bfloat162*)(xcl + o);
        ph[0] = __nv_bfloat162(h0, h1); ph[1] = __nv_bfloat162(h2, h3);
        pl[0] = __nv_bfloat162(l0, l1); pl[1] = __nv_bfloat162(l2, l3);
    }

    float ps = warpSum(v.x + v.y + v.z + v.w);
    if (lane == 0) red[half][w4] = ps;
    __syncthreads();
    float mu = (red[half][0] + red[half][1] + red[half][2] + red[half][3]) * (1.0f / DDIM);
    __syncthreads();
    float dx = v.x - mu, dy = v.y - mu, dz = v.z - mu, dw = v.w - mu;
    float pv = warpSum(dx * dx + dy * dy + dz * dz + dw * dw);
    if (lane == 0) red[half][w4] = pv;
    __syncthreads();
    float var = (red[half][0] + red[half][1] + red[half][2] + red[half][3]) * (1.0f / DDIM);
    float r = rsqrtf(var + EPS);
    float4 wv = ((const float4*)w)[t];
    float4 bv = ((const float4*)b)[t];
    float y0 = dx * r * wv.x + bv.x;
    float y1 = dy * r * wv.y + bv.y;
    float y2 = dz * r * wv.z + bv.z;
    float y3 = dw * r * wv.w + bv.w;
    __nv_bfloat16 h0, l0, h1, l1, h2, l2, h3, l3;
    split2(y0, h0, l0); split2(y1, h1, l1);
    split2(y2, h2, l2); split2(y3, h3, l3);
    __nv_bfloat162* ph = (__nv_bfloat162*)(sh_ + o);
    __nv_bfloat162* pl = (__nv_bfloat162*)(sl_ + o);
    ph[0] = __nv_bfloat162(h0, h1); ph[1] = __nv_bfloat162(h2, h3);
    pl[0] = __nv_bfloat162(l0, l1); pl[1] = __nv_bfloat162(l2, l3);
}

__global__ __launch_bounds__(256) void ln_kernel(const float* __restrict__ x,
                                                 const float* __restrict__ w,
                                                 const float* __restrict__ b,
                                                 float* __restrict__ y) {
    __shared__ float red[2][4];
    const int half = threadIdx.x >> 7;
    const int t    = threadIdx.x & 127;
    const int lane = threadIdx.x & 31;
    const int w4   = (threadIdx.x >> 5) & 3;
    const int row  = blockIdx.x * 2 + half;
    float4 v = ((const float4*)(x + (size_t)row * DDIM))[t];
    float ps = warpSum(v.x + v.y + v.z + v.w);
    if (lane == 0) red[half][w4] = ps;
    __syncthreads();
    float mu = (red[half][0] + red[half][1] + red[half][2] + red[half][3]) * (1.0f / DDIM);
    __syncthreads();
    float dx = v.x - mu, dy = v.y - mu, dz = v.z - mu, dw = v.w - mu;
    float pv = warpSum(dx * dx + dy * dy + dz * dz + dw * dw);
    if (lane == 0) red[half][w4] = pv;
    __syncthreads();
    float var = (red[half][0] + red[half][1] + red[half][2] + red[half][3]) * (1.0f / DDIM);
    float r = rsqrtf(var + EPS);
    float4 wv = ((const float4*)w)[t];
    float4 bv = ((const float4*)b)[t];
    float4 o;
    o.x = dx * r * wv.x + bv.x;
    o.y = dy * r * wv.y + bv.y;
    o.z = dz * r * wv.z + bv.z;
    o.w = dw * r * wv.w + bv.w;
    ((float4*)(y + (size_t)row * DDIM))[t] = o;
}

// ================= mma.sync bf16-split GEMM (BK=64, 16 warps, merged z) =================
// modes: 0 = fp32 C. 1 = bias+SiLU -> bf16 split. 2 = bias+SiLU -> fp32.
//        3 = raw bf16 split + attn zero-fill INTERLEAVED into the mainloop
//            (2 rows per k-chunk; stores drain on the idle DRAM path).
#define GM_STAGE 65536
#define GM_SMEM  (3 * GM_STAGE)

__device__ __forceinline__ uint32_t swz(int row, int c16) {
    return (uint32_t)(row * 128 + ((c16 ^ (row & 7)) << 4));
}
__device__ __forceinline__ float silu_f(float v) { return v / (1.0f + expf(-v)); }

__global__ __launch_bounds__(512, 1) void gemm_mma(const __nv_bfloat16* Ah,
                                                   const __nv_bfloat16* Al,
                                                   const __nv_bfloat16* Bh,
                                                   const __nv_bfloat16* Bl,
                                                   float* C,
                                                   const __nv_bfloat16* Ah2,
                                                   const __nv_bfloat16* Al2,
                                                   const __nv_bfloat16* Bh2,
                                                   const __nv_bfloat16* Bl2,
                                                   const float* bias,
                                                   __nv_bfloat16* oh,
                                                   __nv_bfloat16* ol,
                                                   __nv_bfloat16* oh2,
                                                   __nv_bfloat16* ol2,
                                                   int mode) {
    if (blockIdx.z == 1) { Ah = Ah2; Al = Al2; Bh = Bh2; Bl = Bl2; oh = oh2; ol = ol2; }
    extern __shared__ char smem[];
    const uint32_t sbase = smem_u32(smem);
    const int tid  = threadIdx.x;
    const int lane = tid & 31;
    const int wid  = tid >> 5;
    const int wm   = wid >> 2;
    const int wn   = wid & 3;
    const int bm   = blockIdx.y * 128;
    const int bn   = blockIdx.x * 128;
    const int bid  = (blockIdx.z * 64 + blockIdx.y) * 4 + blockIdx.x;  // mode-3 zf partition

    float acc[2][4][4];
    #pragma unroll
    for (int mi = 0; mi < 2; mi++)
        #pragma unroll
        for (int nj = 0; nj < 4; nj++)
            #pragma unroll
            for (int c = 0; c < 4; c++) acc[mi][nj][c] = 0.0f;

    const int lr0 = tid >> 3,         lc0 = tid & 7;
    const int lr1 = (tid + 512) >> 3, lc1 = (tid + 512) & 7;
    const uint32_t so0 = swz(lr0, lc0), so1 = swz(lr1, lc1);

    const int arow = (lane & 15);
    const int acol = (lane >> 4);
    const int brow = (lane & 7) + ((lane >> 4) & 1) * 8;
    const int bcol = (lane >> 3) & 1;

    #define GM_ISSUE(st, kt) do { \
        uint32_t sb_ = sbase + (st) * GM_STAGE; \
        int k0_ = (kt) * 64; \
        size_t ga0 = (size_t)(bm + lr0) * DDIM + k0_ + lc0 * 8; \
        size_t gb0 = (size_t)(bn + lr0) * DDIM + k0_ + lc0 * 8; \
        size_t ga1 = (size_t)(bm + lr1) * DDIM + k0_ + lc1 * 8; \
        size_t gb1 = (size_t)(bn + lr1) * DDIM + k0_ + lc1 * 8; \
        CP_ASYNC16(sb_ + so0,          Ah + ga0); \
        CP_ASYNC16(sb_ + 16384 + so0,  Al + ga0); \
        CP_ASYNC16(sb_ + 32768 + so0,  Bh + gb0); \
        CP_ASYNC16(sb_ + 49152 + so0,  Bl + gb0); \
        CP_ASYNC16(sb_ + so1,          Ah + ga1); \
        CP_ASYNC16(sb_ + 16384 + so1,  Al + ga1); \
        CP_ASYNC16(sb_ + 32768 + so1,  Bh + gb1); \
        CP_ASYNC16(sb_ + 49152 + so1,  Bl + gb1); \
    } while (0)

    GM_ISSUE(0, 0); CP_COMMIT();
    GM_ISSUE(1, 1); CP_COMMIT();

    for (int kt = 0; kt < 8; kt++) {
        if (kt < 6) CP_WAIT(1); else CP_WAIT(0);
        __syncthreads();
        const uint32_t sb = sbase + (kt % 3) * GM_STAGE;

        #pragma unroll
        for (int ks = 0; ks < 4; ks++) {
            uint32_t fah[2][4], fal[2][4];
            #pragma unroll
            for (int mi = 0; mi < 2; mi++) {
                uint32_t off = swz(wm * 32 + mi * 16 + arow, ks * 2 + acol);
                LDMX4(fah[mi], sb + off);
                LDMX4(fal[mi], sb + 16384 + off);
            }
            #pragma unroll
            for (int njp = 0; njp < 4; njp += 2) {
                uint32_t off = swz(wn * 32 + njp * 8 + brow, ks * 2 + bcol);
                uint32_t fbh[4], fbl[4];
                LDMX4(fbh, sb + 32768 + off);
                LDMX4(fbl, sb + 49152 + off);
                // distance-4 reorder: per-acc order stays hh, hl, lh (bit-identical)
                #pragma unroll
                for (int mi = 0; mi < 2; mi++) {
                    MMA16816(acc[mi][njp],     fah[mi], fbh[0], fbh[1]);
                    MMA16816(acc[mi][njp + 1], fah[mi], fbh[2], fbh[3]);
                }
                #pragma unroll
                for (int mi = 0; mi < 2; mi++) {
                    MMA16816(acc[mi][njp],     fah[mi], fbl[0], fbl[1]);
                    MMA16816(acc[mi][njp + 1], fah[mi], fbl[2], fbl[3]);
                }
                #pragma unroll
                for (int mi = 0; mi < 2; mi++) {
                    MMA16816(acc[mi][njp],     fal[mi], fbh[0], fbh[1]);
                    MMA16816(acc[mi][njp + 1], fal[mi], fbh[2], fbh[3]);
                }
            }
        }
        if (kt + 2 < 8) { GM_ISSUE((kt + 2) % 3, kt + 2); CP_COMMIT(); }

        // mode-3: interleaved attn zero-fill (2 rows per kt => 16 rows total).
        // Disjoint from softmax's written region; overlaps DRAM with tensor work.
        if (mode == 3 && C != nullptr) {
            const float4 z4 = make_float4(0.f, 0.f, 0.f, 0.f);
            #pragma unroll 1
            for (int rr = 0; rr < 2; rr++) {
                int i = bid * 16 + kt * 2 + rr;
                int r0z = i & ~63;
                int zs = g_segs[r0z] & ~3;
                int ebm = g_sege[r0z + 63];
                int nchz = (ebm - zs + 127) >> 7;
                int ze = min(zs + nchz * 128, NROWS);
                float* row = C + (size_t)i * NROWS;
                for (int j = tid; j < (zs >> 2); j += 512) ((float4*)row)[j] = z4;
                if (ze < NROWS)
                    for (int j = (ze >> 2) + tid; j < (NROWS >> 2); j += 512) ((float4*)row)[j] = z4;
            }
        }
    }
    #undef GM_ISSUE

    const int erow = lane >> 2;
    const int ecol = (lane & 3) * 2;
    #pragma unroll
    for (int mi = 0; mi < 2; mi++) {
        #pragma unroll
        for (int nj = 0; nj < 4; nj++) {
            int m0 = bm + wm * 32 + mi * 16 + erow;
            int n0 = bn + wn * 32 + nj * 8 + ecol;
            float2 v0 = make_float2(acc[mi][nj][0], acc[mi][nj][1]);
            float2 v1 = make_float2(acc[mi][nj][2], acc[mi][nj][3]);
            if (mode == 0) {
                *(float2*)(C + (size_t)m0 * DDIM + n0)       = v0;
                *(float2*)(C + (size_t)(m0 + 8) * DDIM + n0) = v1;
            } else if (mode == 3) {
                __nv_bfloat16 h0, l0, h1, l1;
                split2(v0.x, h0, l0); split2(v0.y, h1, l1);
                *(__nv_bfloat162*)(oh + (size_t)m0 * DDIM + n0) = __nv_bfloat162(h0, h1);
                *(__nv_bfloat162*)(ol + (size_t)m0 * DDIM + n0) = __nv_bfloat162(l0, l1);
                split2(v1.x, h0, l0); split2(v1.y, h1, l1);
                *(__nv_bfloat162*)(oh + (size_t)(m0 + 8) * DDIM + n0) = __nv_bfloat162(h0, h1);
                *(__nv_bfloat162*)(ol + (size_t)(m0 + 8) * DDIM + n0) = __nv_bfloat162(l0, l1);
            } else {
                float2 bv = *(const float2*)(bias + n0);
                v0.x = silu_f(v0.x + bv.x); v0.y = silu_f(v0.y + bv.y);
                v1.x = silu_f(v1.x + bv.x); v1.y = silu_f(v1.y + bv.y);
                if (mode == 2) {
                    *(float2*)(C + (size_t)m0 * DDIM + n0)       = v0;
                    *(float2*)(C + (size_t)(m0 + 8) * DDIM + n0) = v1;
                } else {
                    __nv_bfloat16 h0, l0, h1, l1;
                    split2(v0.x, h0, l0); split2(v0.y, h1, l1);
                    *(__nv_bfloat162*)(oh + (size_t)m0 * DDIM + n0) = __nv_bfloat162(h0, h1);
                    *(__nv_bfloat162*)(ol + (size_t)m0 * DDIM + n0) = __nv_bfloat162(l0, l1);
                    split2(v1.x, h0, l0); split2(v1.y, h1, l1);
                    *(__nv_bfloat162*)(oh + (size_t)(m0 + 8) * DDIM + n0) = __nv_bfloat162(h0, h1);
                    *(__nv_bfloat162*)(ol + (size_t)(m0 + 8) * DDIM + n0) = __nv_bfloat162(l0, l1);
                }
            }
        }
    }
}

// ================= tensorized masked softmax =================
#define AS_STAGE 49152
#define AS_SMEM  (512 + 3 * AS_STAGE)

__global__ __launch_bounds__(512, 1) void attn_softmax_mma(const __nv_bfloat16* __restrict__ qh,
                                                           const __nv_bfloat16* __restrict__ ql,
                                                           const __nv_bfloat16* __restrict__ kh,
                                                           const __nv_bfloat16* __restrict__ kl,
                                                           float* __restrict__ attn) {
    extern __shared__ char smem[];
    float* rowmax = (float*)smem;
    const uint32_t sbase = smem_u32(smem) + 512;
    const int tid = threadIdx.x, lane = tid & 31, wid = tid >> 5;
    const int wm = wid >> 2, wn = wid & 3;
    const int r0 = blockIdx.x * 64;
    const int sbA = g_segs[r0] & ~3;
    const int eb  = g_sege[r0 + 63];
    const int nch = (eb - sbA + 127) >> 7;

    if (tid < 64) rowmax[tid] = 0.0f;

    const int qrow = tid >> 3, qc = tid & 7;
    const int krow0 = tid >> 3, kc0 = tid & 7;
    const int krow1 = (tid + 512) >> 3, kc1 = (tid + 512) & 7;
    const uint32_t sq  = swz(qrow, qc);
    const uint32_t sk0 = swz(krow0, kc0);
    const uint32_t sk1 = swz(krow1, kc1);

    const int arow = lane & 15, acol = lane >> 4;
    const int brow = (lane & 7) + ((lane >> 4) & 1) * 8, bcol = (lane >> 3) & 1;
    const int erow = lane >> 2, ecol = (lane & 3) * 2;
    const int row_a = r0 + wm * 16 + erow;
    const int s_a = g_segs[row_a],     e_a = g_sege[row_a];
    const int s_b = g_segs[row_a + 8], e_b = g_sege[row_a + 8];

    __syncthreads();

    for (int ch = 0; ch < nch; ch++) {
        const int kvb = sbA + ch * 128;
        if (ch > 0) __syncthreads();

        float acc[4][4];
        #pragma unroll
        for (int nj = 0; nj < 4; nj++)
            #pragma unroll
            for (int c = 0; c < 4; c++) acc[nj][c] = 0.0f;

        #define AS_ISSUE(st, kt) do { \
            uint32_t sb_ = sbase + (st) * AS_STAGE; \
            int k0_ = (kt) * 64; \
            size_t gq = (size_t)(r0 + qrow) * DDIM + k0_ + qc * 8; \
            int kr0g = min(kvb + krow0, NROWS - 1); \
            int kr1g = min(kvb + krow1, NROWS - 1); \
            size_t gk0 = (size_t)kr0g * DDIM + k0_ + kc0 * 8; \
            size_t gk1 = (size_t)kr1g * DDIM + k0_ + kc1 * 8; \
            CP_ASYNC16(sb_ + sq,           qh + gq); \
            CP_ASYNC16(sb_ + 8192 + sq,    ql + gq); \
            CP_ASYNC16(sb_ + 16384 + sk0,  kh + gk0); \
            CP_ASYNC16(sb_ + 32768 + sk0,  kl + gk0); \
            CP_ASYNC16(sb_ + 16384 + sk1,  kh + gk1); \
            CP_ASYNC16(sb_ + 32768 + sk1,  kl + gk1); \
        } while (0)

        AS_ISSUE(0, 0); CP_COMMIT();
        AS_ISSUE(1, 1); CP_COMMIT();

        for (int kt = 0; kt < 8; kt++) {
            if (kt < 6) CP_WAIT(1); else CP_WAIT(0);
            __syncthreads();
            const uint32_t sb = sbase + (kt % 3) * AS_STAGE;

            #pragma unroll
            for (int ks = 0; ks < 4; ks++) {
                uint32_t fqh[4], fql[4], fkh[2][4], fkl[2][4];
                {
                    uint32_t off = swz(wm * 16 + arow, ks * 2 + acol);
                    LDMX4(fqh, sb + off);
                    LDMX4(fql, sb + 8192 + off);
                }
                #pragma unroll
                for (int p = 0; p < 2; p++) {
                    uint32_t off = swz(wn * 32 + p * 16 + brow, ks * 2 + bcol);
                    LDMX4(fkh[p], sb + 16384 + off);
                    LDMX4(fkl[p], sb + 32768 + off);
                }
                // distance-8 reorder; per-acc order hh, hl, lh (bit-identical)
                #pragma unroll
                for (int p = 0; p < 2; p++) {
                    MMA16816(acc[p * 2],     fqh, fkh[p][0], fkh[p][1]);
                    MMA16816(acc[p * 2 + 1], fqh, fkh[p][2], fkh[p][3]);
                }
                #pragma unroll
                for (int p = 0; p < 2; p++) {
                    MMA16816(acc[p * 2],     fqh, fkl[p][0], fkl[p][1]);
                    MMA16816(acc[p * 2 + 1], fqh, fkl[p][2], fkl[p][3]);
                }
                #pragma unroll
                for (int p = 0; p < 2; p++) {
                    MMA16816(acc[p * 2],     fql, fkh[p][0], fkh[p][1]);
                    MMA16816(acc[p * 2 + 1], fql, fkh[p][2], fkh[p][3]);
                }
            }
            if (kt + 2 < 8) { AS_ISSUE((kt + 2) % 3, kt + 2); CP_COMMIT(); }
        }
        #undef AS_ISSUE

        float vm0 = 0.0f, vm1 = 0.0f;
        #pragma unroll
        for (int nj = 0; nj < 4; nj++) {
            int j = kvb + wn * 32 + nj * 8 + ecol;
            float2 w0, w1;
            w0.x = (j     >= s_a && j     < e_a) ? acc[nj][0] : 0.0f;
            w0.y = (j + 1 >= s_a && j + 1 < e_a) ? acc[nj][1] : 0.0f;
            w1.x = (j     >= s_b && j     < e_b) ? acc[nj][2] : 0.0f;
            w1.y = (j + 1 >= s_b && j + 1 < e_b) ? acc[nj][3] : 0.0f;
            if (j < NROWS) {
                *(float2*)(attn + (size_t)row_a * NROWS + j)       = w0;
                *(float2*)(attn + (size_t)(row_a + 8) * NROWS + j) = w1;
            }
            vm0 = fmaxf(vm0, fmaxf(w0.x, w0.y));
            vm1 = fmaxf(vm1, fmaxf(w1.x, w1.y));
        }
        vm0 = fmaxf(vm0, __shfl_xor_sync(0xffffffffu, vm0, 1));
        vm0 = fmaxf(vm0, __shfl_xor_sync(0xffffffffu, vm0, 2));
        vm1 = fmaxf(vm1, __shfl_xor_sync(0xffffffffu, vm1, 1));
        vm1 = fmaxf(vm1, __shfl_xor_sync(0xffffffffu, vm1, 2));
        if ((lane & 3) == 0) {
            atomicMax((int*)&rowmax[wm * 16 + erow],     __float_as_int(vm0));
            atomicMax((int*)&rowmax[wm * 16 + erow + 8], __float_as_int(vm1));
        }
    }
    __syncthreads();

    for (int rr = 0; rr < 4; rr++) {
        const int li = wid * 4 + rr;
        const int i = r0 + li;
        float m = rowmax[li];
        const int s = g_segs[i], e = g_sege[i];
        float* row = attn + (size_t)i * NROWS;

        float ssum = 0.0f;
        for (int j = s + lane; j < e; j += 32) {
            float ev = expf(row[j] - m);
            ssum += ev;
            row[j] = ev;
        }
        ssum = warpSum(ssum);
        float inv = 1.0f / ssum;
        for (int j = s + lane; j < e; j += 32) row[j] *= inv;
    }
}

// ================= tensorized apply: x_weighted = attn @ x_conf =================
#define AP_SMEM 49152

__global__ __launch_bounds__(512, 1) void attn_apply_mma(const float* __restrict__ attn,
                                                         const __nv_bfloat16* __restrict__ xch,
                                                         const __nv_bfloat16* __restrict__ xcl,
                                                         __nv_bfloat16* __restrict__ oh,
                                                         __nv_bfloat16* __restrict__ ol) {
    extern __shared__ char smem[];
    const uint32_t sbase = smem_u32(smem);
    const int tid = threadIdx.x, lane = tid & 31, wid = tid >> 5;
    const int wm = wid >> 2, wn = wid & 3;
    const int r0 = blockIdx.x * 64;
    const int c0 = blockIdx.y * 128;
    const int sbA = g_segs[r0] & ~63;
    const int eb  = g_sege[r0 + 63];
    const int nch = (eb - sbA + 63) >> 6;

    float acc[4][4];
    #pragma unroll
    for (int nj = 0; nj < 4; nj++)
        #pragma unroll
        for (int c = 0; c < 4; c++) acc[nj][c] = 0.0f;

    const int ar = tid >> 3, ac16 = tid & 7;
    const int farow = lane & 15, facol = lane >> 4;
    const int bkr = (lane & 7) + ((lane >> 3) & 1) * 8;
    const int bco = (lane >> 4) & 1;

    for (int ch = 0; ch < nch; ch++) {
        const int kvb = sbA + ch * 64;
        __syncthreads();

        #pragma unroll
        for (int i = 0; i < 2; i++) {
            int id = tid + i * 512;
            int r = id >> 4, c = id & 15;
            uint32_t dst = (uint32_t)(r * 256 + ((c ^ (r & 15)) << 4));
            size_t src = (size_t)(kvb + r) * DDIM + c0 + c * 8;
            CP_ASYNC16(sbase + 16384 + dst, xch + src);
            CP_ASYNC16(sbase + 32768 + dst, xcl + src);
        }
        CP_COMMIT();

        {
            const float* ap = attn + (size_t)(r0 + ar) * NROWS + kvb + ac16 * 8;
            float4 v0 = *(const float4*)(ap);
            float4 v1 = *(const float4*)(ap + 4);
            __nv_bfloat162 hh[4], ll[4];
            __nv_bfloat16 h, l;
            split2(v0.x, h, l); __nv_bfloat16 h2, l2; split2(v0.y, h2, l2);
            hh[0] = __nv_bfloat162(h, h2); ll[0] = __nv_bfloat162(l, l2);
            split2(v0.z, h, l); split2(v0.w, h2, l2);
            hh[1] = __nv_bfloat162(h, h2); ll[1] = __nv_bfloat162(l, l2);
            split2(v1.x, h, l); split2(v1.y, h2, l2);
            hh[2] = __nv_bfloat162(h, h2); ll[2] = __nv_bfloat162(l, l2);
            split2(v1.z, h, l); split2(v1.w, h2, l2);
            hh[3] = __nv_bfloat162(h, h2); ll[3] = __nv_bfloat162(l, l2);
            uint32_t off = swz(ar, ac16);
            *(uint4*)(smem + off)        = *(uint4*)hh;
            *(uint4*)(smem + 8192 + off) = *(uint4*)ll;
        }
        CP_WAIT(0);
        __syncthreads();

        #pragma unroll
        for (int ks = 0; ks < 4; ks++) {
            uint32_t fah[4], fal[4];
            {
                uint32_t off = swz(wm * 16 + farow, ks * 2 + facol);
                LDMX4(fah, sbase + off);
                LDMX4(fal, sbase + 8192 + off);
            }
            #pragma unroll
            for (int half = 0; half < 2; half++) {
                int rowB = ks * 16 + bkr;
                int cB = wn * 4 + half * 2 + bco;
                uint32_t off = (uint32_t)(rowB * 256 + ((cB ^ (rowB & 15)) << 4));
                uint32_t fbh[4], fbl[4];
                LDMX4T(fbh, sbase + 16384 + off);
                LDMX4T(fbl, sbase + 32768 + off);
                MMA16816(acc[half * 2],     fah, fbh[0], fbh[1]);
                MMA16816(acc[half * 2 + 1], fah, fbh[2], fbh[3]);
                MMA16816(acc[half * 2],     fah, fbl[0], fbl[1]);
                MMA16816(acc[half * 2 + 1], fah, fbl[2], fbl[3]);
                MMA16816(acc[half * 2],     fal, fbh[0], fbh[1]);
                MMA16816(acc[half * 2 + 1], fal, fbh[2], fbh[3]);
            }
        }
    }

    const int erow = lane >> 2;
    const int ecol = (lane & 3) * 2;
    #pragma unroll
    for (int nj = 0; nj < 4; nj++) {
        int m0 = r0 + wm * 16 + erow;
        int n0 = c0 + wn * 32 + nj * 8 + ecol;
        __nv_bfloat16 h0, l0, h1, l1;
        split2(acc[nj][0], h0, l0); split2(acc[nj][1], h1, l1);
        *(__nv_bfloat162*)(oh + (size_t)m0 * DDIM + n0) = __nv_bfloat162(h0, h1);
        *(__nv_bfloat162*)(ol + (size_t)m0 * DDIM + n0) = __nv_bfloat162(l0, l1);
        split2(acc[nj][2], h0, l0); split2(acc[nj][3], h1, l1);
        *(__nv_bfloat162*)(oh + (size_t)(m0 + 8) * DDIM + n0) = __nv_bfloat162(h0, h1);
        *(__nv_bfloat162*)(ol + (size_t)(m0 + 8) * DDIM + n0) = __nv_bfloat162(l0, l1);
    }
}

// ================= launch =================
extern "C" void kernel_launch(void* const* d_in, const int* in_sizes, int n_in,
                              void* d_out, int out_size) {
    const float* x_mole  = (const float*)d_in[0];
    const float* x_conf  = (const float*)d_in[1];
    const float* W1      = (const float*)d_in[2];
    const float* W2      = (const float*)d_in[3];
    const float* phi1_w  = (const float*)d_in[4];
    const float* phi1_b  = (const float*)d_in[5];
    const float* phi2_w  = (const float*)d_in[6];
    const float* phi2_b  = (const float*)d_in[7];
    const float* rho_w1  = (const float*)d_in[8];
    const float* rho_b1  = (const float*)d_in[9];
    const float* rho_w2  = (const float*)d_in[10];
    const float* rho_b2  = (const float*)d_in[11];
    const float* rho_ln_w = (const float*)d_in[12];
    const float* rho_ln_b = (const float*)d_in[13];
    const int*   batch   = (const int*)d_in[14];

    float* out_enc  = (float*)d_out;
    float* out_attn = (float*)d_out + (size_t)NROWS * DDIM;

    float *k;
    __nv_bfloat16 *sh1, *sl1, *sh2, *sl2, *wh, *wl, *qh, *ql, *kh, *kl, *xch, *xcl;
    cudaGetSymbolAddress((void**)&k,   g_k);
    cudaGetSymbolAddress((void**)&sh1, g_sh1);
    cudaGetSymbolAddress((void**)&sl1, g_sl1);
    cudaGetSymbolAddress((void**)&sh2, g_sh2);
    cudaGetSymbolAddress((void**)&sl2, g_sl2);
    cudaGetSymbolAddress((void**)&wh,  g_wh);
    cudaGetSymbolAddress((void**)&wl,  g_wl);
    cudaGetSymbolAddress((void**)&qh,  g_qh);
    cudaGetSymbolAddress((void**)&ql,  g_ql);
    cudaGetSymbolAddress((void**)&kh,  g_kh);
    cudaGetSymbolAddress((void**)&kl,  g_kl);
    cudaGetSymbolAddress((void**)&xch, g_xch);
    cudaGetSymbolAddress((void**)&xcl, g_xcl);
    const size_t WSZ = (size_t)DDIM * DDIM;

    cudaFuncSetAttribute(gemm_mma, cudaFuncAttributeMaxDynamicSharedMemorySize, GM_SMEM);
    cudaFuncSetAttribute(attn_softmax_mma, cudaFuncAttributeMaxDynamicSharedMemorySize, AS_SMEM);
    cudaFuncSetAttribute(attn_apply_mma, cudaFuncAttributeMaxDynamicSharedMemorySize, AP_SMEM);

    dim3 ggrid1(DDIM / 128, NROWS / 128, 1);
    dim3 ggrid2(DDIM / 128, NROWS / 128, 2);
    dim3 lgrid(NROWS / 2, 2, 1);
    dim3 agrid(NROWS / 64, 4, 1);

    // 1: weight splits   2: segments   3: LN+splits (+raw xc split)
    w_split_all<<<1024, 256>>>(W1, W2, rho_w1, rho_w2, wh, wl);
    seg_kernel<<<NROWS / 256, 256>>>(batch);
    ln_split2<<<lgrid, 256>>>(x_mole, phi1_w, phi1_b, sh1, sl1,
                              x_conf, phi2_w, phi2_b, sh2, sl2, xch, xcl);
    // 4: q + k projections -> bf16 splits + interleaved attn zero-fill (ncu position)
    gemm_mma<<<ggrid2, 512, GM_SMEM>>>(sh1, sl1, wh + 0 * WSZ, wl + 0 * WSZ, out_attn,
                                       sh2, sl2, wh + 1 * WSZ, wl + 1 * WSZ,
                                       nullptr, qh, ql, kh, kl, 3);
    // 5: tensorized masked softmax
    attn_softmax_mma<<<NROWS / 64, 512, AS_SMEM>>>(qh, ql, kh, kl, out_attn);
    // 6: tensorized apply -> bf16 split for rho1
    attn_apply_mma<<<agrid, 512, AP_SMEM>>>(out_attn, xch, xcl, sh1, sl1);

    // 7,8: rho MLP (epilogues fused)
    gemm_mma<<<ggrid1, 512, GM_SMEM>>>(sh1, sl1, wh + 2 * WSZ, wl + 2 * WSZ, nullptr,
                                       nullptr, nullptr, nullptr, nullptr,
                                       rho_b1, sh2, sl2, nullptr, nullptr, 1);
    gemm_mma<<<ggrid1, 512, GM_SMEM>>>(sh2, sl2, wh + 3 * WSZ, wl + 3 * WSZ, k,
                                       nullptr, nullptr, nullptr, nullptr,
                                       rho_b2, nullptr, nullptr, nullptr, nullptr, 2);

    // 9: final LayerNorm into output
    ln_kernel<<<NROWS / 2, 256>>>(k, rho_ln_w, rho_ln_b, out_enc);
}

// round 16
// speedup vs baseline: 1.6096x; 1.0605x over previous
#include <cuda_runtime.h>
#include <cuda_bf16.h>
#include <math.h>
#include <stdint.h>

#define NROWS 8192
#define DDIM  512
#define EPS   1e-5f

// ================= PTX helpers =================
__device__ __forceinline__ uint32_t smem_u32(const void* p) {
    uint32_t a;
    asm("{ .reg .u64 t; cvta.to.shared.u64 t, %1; cvt.u32.u64 %0, t; }" : "=r"(a) : "l"(p));
    return a;
}
#define CP_ASYNC16(smem, gptr) \
    asm volatile("cp.async.cg.shared.global [%0], [%1], 16;" :: "r"(smem), "l"(gptr))
#define CP_COMMIT() asm volatile("cp.async.commit_group;" ::: "memory")
#define CP_WAIT(n)  asm volatile("cp.async.wait_group %0;" :: "n"(n) : "memory")

#define LDMX4(r, addr) \
    asm volatile("ldmatrix.sync.aligned.m8n8.x4.shared.b16 {%0,%1,%2,%3}, [%4];" \
        : "=r"((r)[0]), "=r"((r)[1]), "=r"((r)[2]), "=r"((r)[3]) : "r"(addr))

#define LDMX4T(r, addr) \
    asm volatile("ldmatrix.sync.aligned.m8n8.x4.trans.shared.b16 {%0,%1,%2,%3}, [%4];" \
        : "=r"((r)[0]), "=r"((r)[1]), "=r"((r)[2]), "=r"((r)[3]) : "r"(addr))

#define MMA16816(d, a, b0, b1) \
    asm volatile("mma.sync.aligned.m16n8k16.row.col.f32.bf16.bf16.f32 " \
        "{%0,%1,%2,%3}, {%4,%5,%6,%7}, {%8,%9}, {%0,%1,%2,%3};" \
        : "+f"((d)[0]), "+f"((d)[1]), "+f"((d)[2]), "+f"((d)[3]) \
        : "r"((a)[0]), "r"((a)[1]), "r"((a)[2]), "r"((a)[3]), "r"(b0), "r"(b1))

// ================= scratch =================
__device__ float g_k  [NROWS * DDIM];
__device__ __nv_bfloat16 g_sh1[NROWS * DDIM];
__device__ __nv_bfloat16 g_sl1[NROWS * DDIM];
__device__ __nv_bfloat16 g_sh2[NROWS * DDIM];
__device__ __nv_bfloat16 g_sl2[NROWS * DDIM];
__device__ __nv_bfloat16 g_qh[NROWS * DDIM];
__device__ __nv_bfloat16 g_ql[NROWS * DDIM];
__device__ __nv_bfloat16 g_kh[NROWS * DDIM];
__device__ __nv_bfloat16 g_kl[NROWS * DDIM];
__device__ __nv_bfloat16 g_xch[NROWS * DDIM];
__device__ __nv_bfloat16 g_xcl[NROWS * DDIM];
__device__ __nv_bfloat16 g_wh[4][DDIM * DDIM];
__device__ __nv_bfloat16 g_wl[4][DDIM * DDIM];
__device__ int   g_segs[NROWS];
__device__ int   g_sege[NROWS];

// ================= reductions =================
__device__ __forceinline__ float warpSum(float v) {
    #pragma unroll
    for (int o = 16; o > 0; o >>= 1) v += __shfl_xor_sync(0xffffffffu, v, o);
    return v;
}

// ================= split helpers =================
__device__ __forceinline__ void split2(float v, __nv_bfloat16& hi, __nv_bfloat16& lo) {
    hi = __float2bfloat16(v);
    lo = __float2bfloat16(v - __bfloat162float(hi));
}

// ================= weight split =================
__global__ __launch_bounds__(256) void w_split_all(const float* __restrict__ W1,
                                                   const float* __restrict__ W2,
                                                   const float* __restrict__ W3,
                                                   const float* __restrict__ W4,
                                                   __nv_bfloat16* __restrict__ wh,
                                                   __nv_bfloat16* __restrict__ wl) {
    int id = blockIdx.x * 256 + threadIdx.x;
    int w = id >> 16;
    int j = id & 65535;
    const float* src = (w == 0) ? W1 : (w == 1) ? W2 : (w == 2) ? W3 : W4;
    float4 v = ((const float4*)src)[j];
    __nv_bfloat16 h0, l0, h1, l1, h2, l2, h3, l3;
    split2(v.x, h0, l0); split2(v.y, h1, l1);
    split2(v.z, h2, l2); split2(v.w, h3, l3);
    size_t base = (size_t)w * DDIM * DDIM + (size_t)j * 4;
    __nv_bfloat162* ph = (__nv_bfloat162*)(wh + base);
    __nv_bfloat162* pl = (__nv_bfloat162*)(wl + base);
    ph[0] = __nv_bfloat162(h0, h1); ph[1] = __nv_bfloat162(h2, h3);
    pl[0] = __nv_bfloat162(l0, l1); pl[1] = __nv_bfloat162(l2, l3);
}

// ================= segments =================
__global__ void seg_kernel(const int* __restrict__ p) {
    int i = blockIdx.x * blockDim.x + threadIdx.x;
    if (i >= NROWS) return;
    const int is64 = (__ldg(p + (NROWS - 1)) == 0);
    #define GETB(idx) (is64 ? __ldg(p + 2 * (idx)) : __ldg(p + (idx)))
    int v = GETB(i);
    int lo = 0, hi = NROWS;
    while (lo < hi) { int mid = (lo + hi) >> 1; if (GETB(mid) < v) lo = mid + 1; else hi = mid; }
    g_segs[i] = lo;
    lo = 0; hi = NROWS;
    while (lo < hi) { int mid = (lo + hi) >> 1; if (GETB(mid) <= v) lo = mid + 1; else hi = mid; }
    g_sege[i] = lo;
    #undef GETB
}

// ================= LayerNorm+split (both inputs; y==1 also emits raw xc split) =====
__global__ __launch_bounds__(256) void ln_split2(const float* __restrict__ xa,
                                                 const float* __restrict__ wa,
                                                 const float* __restrict__ ba,
                                                 __nv_bfloat16* __restrict__ sha,
                                                 __nv_bfloat16* __restrict__ sla,
                                                 const float* __restrict__ xb,
                                                 const float* __restrict__ wb,
                                                 const float* __restrict__ bb,
                                                 __nv_bfloat16* __restrict__ shb,
                                                 __nv_bfloat16* __restrict__ slb,
                                                 __nv_bfloat16* __restrict__ xch,
                                                 __nv_bfloat16* __restrict__ xcl) {
    const float* x = (blockIdx.y == 0) ? xa : xb;
    const float* w = (blockIdx.y == 0) ? wa : wb;
    const float* b = (blockIdx.y == 0) ? ba : bb;
    __nv_bfloat16* sh_ = (blockIdx.y == 0) ? sha : shb;
    __nv_bfloat16* sl_ = (blockIdx.y == 0) ? sla : slb;

    __shared__ float red[2][4];
    const int half = threadIdx.x >> 7;
    const int t    = threadIdx.x & 127;
    const int lane = threadIdx.x & 31;
    const int w4   = (threadIdx.x >> 5) & 3;
    const int row  = blockIdx.x * 2 + half;
    float4 v = ((const float4*)(x + (size_t)row * DDIM))[t];
    size_t o = (size_t)row * DDIM + t * 4;

    if (blockIdx.y == 1) {
        __nv_bfloat16 h0, l0, h1, l1, h2, l2, h3, l3;
        split2(v.x, h0, l0); split2(v.y, h1, l1);
        split2(v.z, h2, l2); split2(v.w, h3, l3);
        __nv_bfloat162* ph = (__nv_bfloat162*)(xch + o);
        __nv_bfloat162* pl = (__nv_bfloat162*)(xcl + o);
        ph[0] = __nv_bfloat162(h0, h1); ph[1] = __nv_bfloat162(h2, h3);
        pl[0] = __nv_bfloat162(l0, l1); pl[1] = __nv_bfloat162(l2, l3);
    }

    float ps = warpSum(v.x + v.y + v.z + v.w);
    if (lane == 0) red[half][w4] = ps;
    __syncthreads();
    float mu = (red[half][0] + red[half][1] + red[half][2] + red[half][3]) * (1.0f / DDIM);
    __syncthreads();
    float dx = v.x - mu, dy = v.y - mu, dz = v.z - mu, dw = v.w - mu;
    float pv = warpSum(dx * dx + dy * dy + dz * dz + dw * dw);
    if (lane == 0) red[half][w4] = pv;
    __syncthreads();
    float var = (red[half][0] + red[half][1] + red[half][2] + red[half][3]) * (1.0f / DDIM);
    float r = rsqrtf(var + EPS);
    float4 wv = ((const float4*)w)[t];
    float4 bv = ((const float4*)b)[t];
    float y0 = dx * r * wv.x + bv.x;
    float y1 = dy * r * wv.y + bv.y;
    float y2 = dz * r * wv.z + bv.z;
    float y3 = dw * r * wv.w + bv.w;
    __nv_bfloat16 h0, l0, h1, l1, h2, l2, h3, l3;
    split2(y0, h0, l0); split2(y1, h1, l1);
    split2(y2, h2, l2); split2(y3, h3, l3);
    __nv_bfloat162* ph = (__nv_bfloat162*)(sh_ + o);
    __nv_bfloat162* pl = (__nv_bfloat162*)(sl_ + o);
    ph[0] = __nv_bfloat162(h0, h1); ph[1] = __nv_bfloat162(h2, h3);
    pl[0] = __nv_bfloat162(l0, l1); pl[1] = __nv_bfloat162(l2, l3);
}

__global__ __launch_bounds__(256) void ln_kernel(const float* __restrict__ x,
                                                 const float* __restrict__ w,
                                                 const float* __restrict__ b,
                                                 float* __restrict__ y) {
    __shared__ float red[2][4];
    const int half = threadIdx.x >> 7;
    const int t    = threadIdx.x & 127;
    const int lane = threadIdx.x & 31;
    const int w4   = (threadIdx.x >> 5) & 3;
    const int row  = blockIdx.x * 2 + half;
    float4 v = ((const float4*)(x + (size_t)row * DDIM))[t];
    float ps = warpSum(v.x + v.y + v.z + v.w);
    if (lane == 0) red[half][w4] = ps;
    __syncthreads();
    float mu = (red[half][0] + red[half][1] + red[half][2] + red[half][3]) * (1.0f / DDIM);
    __syncthreads();
    float dx = v.x - mu, dy = v.y - mu, dz = v.z - mu, dw = v.w - mu;
    float pv = warpSum(dx * dx + dy * dy + dz * dz + dw * dw);
    if (lane == 0) red[half][w4] = pv;
    __syncthreads();
    float var = (red[half][0] + red[half][1] + red[half][2] + red[half][3]) * (1.0f / DDIM);
    float r = rsqrtf(var + EPS);
    float4 wv = ((const float4*)w)[t];
    float4 bv = ((const float4*)b)[t];
    float4 o;
    o.x = dx * r * wv.x + bv.x;
    o.y = dy * r * wv.y + bv.y;
    o.z = dz * r * wv.z + bv.z;
    o.w = dw * r * wv.w + bv.w;
    ((float4*)(y + (size_t)row * DDIM))[t] = o;
}

// ================= mma.sync bf16-split GEMM (BK=64, 16 warps, merged z) =================
// modes: 0 = fp32 C. 1 = bias+SiLU -> bf16 split. 2 = bias+SiLU -> fp32.
//        3 = raw bf16 split + attn zero-fill interleaved. Zf bounds are loaded
//            ONCE before the mainloop (all 16 rows share one 64-aligned group),
//            so the per-kt zf loop is pure STG with register bounds.
#define GM_STAGE 65536
#define GM_SMEM  (3 * GM_STAGE)

__device__ __forceinline__ uint32_t swz(int row, int c16) {
    return (uint32_t)(row * 128 + ((c16 ^ (row & 7)) << 4));
}
__device__ __forceinline__ float silu_f(float v) { return v / (1.0f + expf(-v)); }

__global__ __launch_bounds__(512, 1) void gemm_mma(const __nv_bfloat16* Ah,
                                                   const __nv_bfloat16* Al,
                                                   const __nv_bfloat16* Bh,
                                                   const __nv_bfloat16* Bl,
                                                   float* C,
                                                   const __nv_bfloat16* Ah2,
                                                   const __nv_bfloat16* Al2,
                                                   const __nv_bfloat16* Bh2,
                                                   const __nv_bfloat16* Bl2,
                                                   const float* bias,
                                                   __nv_bfloat16* oh,
                                                   __nv_bfloat16* ol,
                                                   __nv_bfloat16* oh2,
                                                   __nv_bfloat16* ol2,
                                                   int mode) {
    if (blockIdx.z == 1) { Ah = Ah2; Al = Al2; Bh = Bh2; Bl = Bl2; oh = oh2; ol = ol2; }
    extern __shared__ char smem[];
    const uint32_t sbase = smem_u32(smem);
    const int tid  = threadIdx.x;
    const int lane = tid & 31;
    const int wid  = tid >> 5;
    const int wm   = wid >> 2;
    const int wn   = wid & 3;
    const int bm   = blockIdx.y * 128;
    const int bn   = blockIdx.x * 128;
    const int bid  = (blockIdx.z * 64 + blockIdx.y) * 4 + blockIdx.x;

    // mode-3 zero-fill bounds: one (zs4, ze4) pair serves all 16 rows
    // (bid*16..bid*16+15 never crosses a 64-row group). Loaded BEFORE the
    // mainloop so the per-kt zf loop has register-only bounds (no LDG stalls).
    int zs4 = 0, ze4 = NROWS >> 2;
    if (mode == 3 && C != nullptr) {
        int r0z = (bid * 16) & ~63;
        int zs = __ldg(&g_segs[r0z]) & ~3;
        int ebm = __ldg(&g_sege[r0z + 63]);
        int nchz = (ebm - zs + 127) >> 7;
        int ze = min(zs + nchz * 128, NROWS);
        zs4 = zs >> 2;
        ze4 = ze >> 2;
    }

    float acc[2][4][4];
    #pragma unroll
    for (int mi = 0; mi < 2; mi++)
        #pragma unroll
        for (int nj = 0; nj < 4; nj++)
            #pragma unroll
            for (int c = 0; c < 4; c++) acc[mi][nj][c] = 0.0f;

    const int lr0 = tid >> 3,         lc0 = tid & 7;
    const int lr1 = (tid + 512) >> 3, lc1 = (tid + 512) & 7;
    const uint32_t so0 = swz(lr0, lc0), so1 = swz(lr1, lc1);

    const int arow = (lane & 15);
    const int acol = (lane >> 4);
    const int brow = (lane & 7) + ((lane >> 4) & 1) * 8;
    const int bcol = (lane >> 3) & 1;

    #define GM_ISSUE(st, kt) do { \
        uint32_t sb_ = sbase + (st) * GM_STAGE; \
        int k0_ = (kt) * 64; \
        size_t ga0 = (size_t)(bm + lr0) * DDIM + k0_ + lc0 * 8; \
        size_t gb0 = (size_t)(bn + lr0) * DDIM + k0_ + lc0 * 8; \
        size_t ga1 = (size_t)(bm + lr1) * DDIM + k0_ + lc1 * 8; \
        size_t gb1 = (size_t)(bn + lr1) * DDIM + k0_ + lc1 * 8; \
        CP_ASYNC16(sb_ + so0,          Ah + ga0); \
        CP_ASYNC16(sb_ + 16384 + so0,  Al + ga0); \
        CP_ASYNC16(sb_ + 32768 + so0,  Bh + gb0); \
        CP_ASYNC16(sb_ + 49152 + so0,  Bl + gb0); \
        CP_ASYNC16(sb_ + so1,          Ah + ga1); \
        CP_ASYNC16(sb_ + 16384 + so1,  Al + ga1); \
        CP_ASYNC16(sb_ + 32768 + so1,  Bh + gb1); \
        CP_ASYNC16(sb_ + 49152 + so1,  Bl + gb1); \
    } while (0)

    GM_ISSUE(0, 0); CP_COMMIT();
    GM_ISSUE(1, 1); CP_COMMIT();

    for (int kt = 0; kt < 8; kt++) {
        if (kt < 6) CP_WAIT(1); else CP_WAIT(0);
        __syncthreads();
        const uint32_t sb = sbase + (kt % 3) * GM_STAGE;

        #pragma unroll
        for (int ks = 0; ks < 4; ks++) {
            uint32_t fah[2][4], fal[2][4];
            #pragma unroll
            for (int mi = 0; mi < 2; mi++) {
                uint32_t off = swz(wm * 32 + mi * 16 + arow, ks * 2 + acol);
                LDMX4(fah[mi], sb + off);
                LDMX4(fal[mi], sb + 16384 + off);
            }
            #pragma unroll
            for (int njp = 0; njp < 4; njp += 2) {
                uint32_t off = swz(wn * 32 + njp * 8 + brow, ks * 2 + bcol);
                uint32_t fbh[4], fbl[4];
                LDMX4(fbh, sb + 32768 + off);
                LDMX4(fbl, sb + 49152 + off);
                #pragma unroll
                for (int mi = 0; mi < 2; mi++) {
                    MMA16816(acc[mi][njp],     fah[mi], fbh[0], fbh[1]);
                    MMA16816(acc[mi][njp + 1], fah[mi], fbh[2], fbh[3]);
                }
                #pragma unroll
                for (int mi = 0; mi < 2; mi++) {
                    MMA16816(acc[mi][njp],     fah[mi], fbl[0], fbl[1]);
                    MMA16816(acc[mi][njp + 1], fah[mi], fbl[2], fbl[3]);
                }
                #pragma unroll
                for (int mi = 0; mi < 2; mi++) {
                    MMA16816(acc[mi][njp],     fal[mi], fbh[0], fbh[1]);
                    MMA16816(acc[mi][njp + 1], fal[mi], fbh[2], fbh[3]);
                }
            }
        }
        if (kt + 2 < 8) { GM_ISSUE((kt + 2) % 3, kt + 2); CP_COMMIT(); }

        // mode-3: interleaved attn zero-fill (2 rows per kt), register bounds.
        if (mode == 3 && C != nullptr) {
            const float4 z4 = make_float4(0.f, 0.f, 0.f, 0.f);
            #pragma unroll 1
            for (int rr = 0; rr < 2; rr++) {
                float* row = C + (size_t)(bid * 16 + kt * 2 + rr) * NROWS;
                for (int j = tid; j < zs4; j += 512) ((float4*)row)[j] = z4;
                for (int j = ze4 + tid; j < (NROWS >> 2); j += 512) ((float4*)row)[j] = z4;
            }
        }
    }
    #undef GM_ISSUE

    const int erow = lane >> 2;
    const int ecol = (lane & 3) * 2;
    #pragma unroll
    for (int mi = 0; mi < 2; mi++) {
        #pragma unroll
        for (int nj = 0; nj < 4; nj++) {
            int m0 = bm + wm * 32 + mi * 16 + erow;
            int n0 = bn + wn * 32 + nj * 8 + ecol;
            float2 v0 = make_float2(acc[mi][nj][0], acc[mi][nj][1]);
            float2 v1 = make_float2(acc[mi][nj][2], acc[mi][nj][3]);
            if (mode == 0) {
                *(float2*)(C + (size_t)m0 * DDIM + n0)       = v0;
                *(float2*)(C + (size_t)(m0 + 8) * DDIM + n0) = v1;
            } else if (mode == 3) {
                __nv_bfloat16 h0, l0, h1, l1;
                split2(v0.x, h0, l0); split2(v0.y, h1, l1);
                *(__nv_bfloat162*)(oh + (size_t)m0 * DDIM + n0) = __nv_bfloat162(h0, h1);
                *(__nv_bfloat162*)(ol + (size_t)m0 * DDIM + n0) = __nv_bfloat162(l0, l1);
                split2(v1.x, h0, l0); split2(v1.y, h1, l1);
                *(__nv_bfloat162*)(oh + (size_t)(m0 + 8) * DDIM + n0) = __nv_bfloat162(h0, h1);
                *(__nv_bfloat162*)(ol + (size_t)(m0 + 8) * DDIM + n0) = __nv_bfloat162(l0, l1);
            } else {
                float2 bv = *(const float2*)(bias + n0);
                v0.x = silu_f(v0.x + bv.x); v0.y = silu_f(v0.y + bv.y);
                v1.x = silu_f(v1.x + bv.x); v1.y = silu_f(v1.y + bv.y);
                if (mode == 2) {
                    *(float2*)(C + (size_t)m0 * DDIM + n0)       = v0;
                    *(float2*)(C + (size_t)(m0 + 8) * DDIM + n0) = v1;
                } else {
                    __nv_bfloat16 h0, l0, h1, l1;
                    split2(v0.x, h0, l0); split2(v0.y, h1, l1);
                    *(__nv_bfloat162*)(oh + (size_t)m0 * DDIM + n0) = __nv_bfloat162(h0, h1);
                    *(__nv_bfloat162*)(ol + (size_t)m0 * DDIM + n0) = __nv_bfloat162(l0, l1);
                    split2(v1.x, h0, l0); split2(v1.y, h1, l1);
                    *(__nv_bfloat162*)(oh + (size_t)(m0 + 8) * DDIM + n0) = __nv_bfloat162(h0, h1);
                    *(__nv_bfloat162*)(ol + (size_t)(m0 + 8) * DDIM + n0) = __nv_bfloat162(l0, l1);
                }
            }
        }
    }
}

// ================= tensorized masked softmax =================
#define AS_STAGE 49152
#define AS_SMEM  (512 + 3 * AS_STAGE)

__global__ __launch_bounds__(512, 1) void attn_softmax_mma(const __nv_bfloat16* __restrict__ qh,
                                                           const __nv_bfloat16* __restrict__ ql,
                                                           const __nv_bfloat16* __restrict__ kh,
                                                           const __nv_bfloat16* __restrict__ kl,
                                                           float* __restrict__ attn) {
    extern __shared__ char smem[];
    float* rowmax = (float*)smem;
    const uint32_t sbase = smem_u32(smem) + 512;
    const int tid = threadIdx.x, lane = tid & 31, wid = tid >> 5;
    const int wm = wid >> 2, wn = wid & 3;
    const int r0 = blockIdx.x * 64;
    const int sbA = g_segs[r0] & ~3;
    const int eb  = g_sege[r0 + 63];
    const int nch = (eb - sbA + 127) >> 7;

    if (tid < 64) rowmax[tid] = 0.0f;

    const int qrow = tid >> 3, qc = tid & 7;
    const int krow0 = tid >> 3, kc0 = tid & 7;
    const int krow1 = (tid + 512) >> 3, kc1 = (tid + 512) & 7;
    const uint32_t sq  = swz(qrow, qc);
    const uint32_t sk0 = swz(krow0, kc0);
    const uint32_t sk1 = swz(krow1, kc1);

    const int arow = lane & 15, acol = lane >> 4;
    const int brow = (lane & 7) + ((lane >> 4) & 1) * 8, bcol = (lane >> 3) & 1;
    const int erow = lane >> 2, ecol = (lane & 3) * 2;
    const int row_a = r0 + wm * 16 + erow;
    const int s_a = g_segs[row_a],     e_a = g_sege[row_a];
    const int s_b = g_segs[row_a + 8], e_b = g_sege[row_a + 8];

    __syncthreads();

    for (int ch = 0; ch < nch; ch++) {
        const int kvb = sbA + ch * 128;
        if (ch > 0) __syncthreads();

        float acc[4][4];
        #pragma unroll
        for (int nj = 0; nj < 4; nj++)
            #pragma unroll
            for (int c = 0; c < 4; c++) acc[nj][c] = 0.0f;

        #define AS_ISSUE(st, kt) do { \
            uint32_t sb_ = sbase + (st) * AS_STAGE; \
            int k0_ = (kt) * 64; \
            size_t gq = (size_t)(r0 + qrow) * DDIM + k0_ + qc * 8; \
            int kr0g = min(kvb + krow0, NROWS - 1); \
            int kr1g = min(kvb + krow1, NROWS - 1); \
            size_t gk0 = (size_t)kr0g * DDIM + k0_ + kc0 * 8; \
            size_t gk1 = (size_t)kr1g * DDIM + k0_ + kc1 * 8; \
            CP_ASYNC16(sb_ + sq,           qh + gq); \
            CP_ASYNC16(sb_ + 8192 + sq,    ql + gq); \
            CP_ASYNC16(sb_ + 16384 + sk0,  kh + gk0); \
            CP_ASYNC16(sb_ + 32768 + sk0,  kl + gk0); \
            CP_ASYNC16(sb_ + 16384 + sk1,  kh + gk1); \
            CP_ASYNC16(sb_ + 32768 + sk1,  kl + gk1); \
        } while (0)

        AS_ISSUE(0, 0); CP_COMMIT();
        AS_ISSUE(1, 1); CP_COMMIT();

        for (int kt = 0; kt < 8; kt++) {
            if (kt < 6) CP_WAIT(1); else CP_WAIT(0);
            __syncthreads();
            const uint32_t sb = sbase + (kt % 3) * AS_STAGE;

            #pragma unroll
            for (int ks = 0; ks < 4; ks++) {
                uint32_t fqh[4], fql[4], fkh[2][4], fkl[2][4];
                {
                    uint32_t off = swz(wm * 16 + arow, ks * 2 + acol);
                    LDMX4(fqh, sb + off);
                    LDMX4(fql, sb + 8192 + off);
                }
                #pragma unroll
                for (int p = 0; p < 2; p++) {
                    uint32_t off = swz(wn * 32 + p * 16 + brow, ks * 2 + bcol);
                    LDMX4(fkh[p], sb + 16384 + off);
                    LDMX4(fkl[p], sb + 32768 + off);
                }
                #pragma unroll
                for (int p = 0; p < 2; p++) {
                    MMA16816(acc[p * 2],     fqh, fkh[p][0], fkh[p][1]);
                    MMA16816(acc[p * 2 + 1], fqh, fkh[p][2], fkh[p][3]);
                }
                #pragma unroll
                for (int p = 0; p < 2; p++) {
                    MMA16816(acc[p * 2],     fqh, fkl[p][0], fkl[p][1]);
                    MMA16816(acc[p * 2 + 1], fqh, fkl[p][2], fkl[p][3]);
                }
                #pragma unroll
                for (int p = 0; p < 2; p++) {
                    MMA16816(acc[p * 2],     fql, fkh[p][0], fkh[p][1]);
                    MMA16816(acc[p * 2 + 1], fql, fkh[p][2], fkh[p][3]);
                }
            }
            if (kt + 2 < 8) { AS_ISSUE((kt + 2) % 3, kt + 2); CP_COMMIT(); }
        }
        #undef AS_ISSUE

        float vm0 = 0.0f, vm1 = 0.0f;
        #pragma unroll
        for (int nj = 0; nj < 4; nj++) {
            int j = kvb + wn * 32 + nj * 8 + ecol;
            float2 w0, w1;
            w0.x = (j     >= s_a && j     < e_a) ? acc[nj][0] : 0.0f;
            w0.y = (j + 1 >= s_a && j + 1 < e_a) ? acc[nj][1] : 0.0f;
            w1.x = (j     >= s_b && j     < e_b) ? acc[nj][2] : 0.0f;
            w1.y = (j + 1 >= s_b && j + 1 < e_b) ? acc[nj][3] : 0.0f;
            if (j < NROWS) {
                *(float2*)(attn + (size_t)row_a * NROWS + j)       = w0;
                *(float2*)(attn + (size_t)(row_a + 8) * NROWS + j) = w1;
            }
            vm0 = fmaxf(vm0, fmaxf(w0.x, w0.y));
            vm1 = fmaxf(vm1, fmaxf(w1.x, w1.y));
        }
        vm0 = fmaxf(vm0, __shfl_xor_sync(0xffffffffu, vm0, 1));
        vm0 = fmaxf(vm0, __shfl_xor_sync(0xffffffffu, vm0, 2));
        vm1 = fmaxf(vm1, __shfl_xor_sync(0xffffffffu, vm1, 1));
        vm1 = fmaxf(vm1, __shfl_xor_sync(0xffffffffu, vm1, 2));
        if ((lane & 3) == 0) {
            atomicMax((int*)&rowmax[wm * 16 + erow],     __float_as_int(vm0));
            atomicMax((int*)&rowmax[wm * 16 + erow + 8], __float_as_int(vm1));
        }
    }
    __syncthreads();

    for (int rr = 0; rr < 4; rr++) {
        const int li = wid * 4 + rr;
        const int i = r0 + li;
        float m = rowmax[li];
        const int s = g_segs[i], e = g_sege[i];
        float* row = attn + (size_t)i * NROWS;

        float ssum = 0.0f;
        for (int j = s + lane; j < e; j += 32) {
            float ev = expf(row[j] - m);
            ssum += ev;
            row[j] = ev;
        }
        ssum = warpSum(ssum);
        float inv = 1.0f / ssum;
        for (int j = s + lane; j < e; j += 32) row[j] *= inv;
    }
}

// ================= tensorized apply: x_weighted = attn @ x_conf =================
#define AP_SMEM 49152

__global__ __launch_bounds__(512, 1) void attn_apply_mma(const float* __restrict__ attn,
                                                         const __nv_bfloat16* __restrict__ xch,
                                                         const __nv_bfloat16* __restrict__ xcl,
                                                         __nv_bfloat16* __restrict__ oh,
                                                         __nv_bfloat16* __restrict__ ol) {
    extern __shared__ char smem[];
    const uint32_t sbase = smem_u32(smem);
    const int tid = threadIdx.x, lane = tid & 31, wid = tid >> 5;
    const int wm = wid >> 2, wn = wid & 3;
    const int r0 = blockIdx.x * 64;
    const int c0 = blockIdx.y * 128;
    const int sbA = g_segs[r0] & ~63;
    const int eb  = g_sege[r0 + 63];
    const int nch = (eb - sbA + 63) >> 6;

    float acc[4][4];
    #pragma unroll
    for (int nj = 0; nj < 4; nj++)
        #pragma unroll
        for (int c = 0; c < 4; c++) acc[nj][c] = 0.0f;

    const int ar = tid >> 3, ac16 = tid & 7;
    const int farow = lane & 15, facol = lane >> 4;
    const int bkr = (lane & 7) + ((lane >> 3) & 1) * 8;
    const int bco = (lane >> 4) & 1;

    for (int ch = 0; ch < nch; ch++) {
        const int kvb = sbA + ch * 64;
        __syncthreads();

        #pragma unroll
        for (int i = 0; i < 2; i++) {
            int id = tid + i * 512;
            int r = id >> 4, c = id & 15;
            uint32_t dst = (uint32_t)(r * 256 + ((c ^ (r & 15)) << 4));
            size_t src = (size_t)(kvb + r) * DDIM + c0 + c * 8;
            CP_ASYNC16(sbase + 16384 + dst, xch + src);
            CP_ASYNC16(sbase + 32768 + dst, xcl + src);
        }
        CP_COMMIT();

        {
            const float* ap = attn + (size_t)(r0 + ar) * NROWS + kvb + ac16 * 8;
            float4 v0 = *(const float4*)(ap);
            float4 v1 = *(const float4*)(ap + 4);
            __nv_bfloat162 hh[4], ll[4];
            __nv_bfloat16 h, l;
            split2(v0.x, h, l); __nv_bfloat16 h2, l2; split2(v0.y, h2, l2);
            hh[0] = __nv_bfloat162(h, h2); ll[0] = __nv_bfloat162(l, l2);
            split2(v0.z, h, l); split2(v0.w, h2, l2);
            hh[1] = __nv_bfloat162(h, h2); ll[1] = __nv_bfloat162(l, l2);
            split2(v1.x, h, l); split2(v1.y, h2, l2);
            hh[2] = __nv_bfloat162(h, h2); ll[2] = __nv_bfloat162(l, l2);
            split2(v1.z, h, l); split2(v1.w, h2, l2);
            hh[3] = __nv_bfloat162(h, h2); ll[3] = __nv_bfloat162(l, l2);
            uint32_t off = swz(ar, ac16);
            *(uint4*)(smem + off)        = *(uint4*)hh;
            *(uint4*)(smem + 8192 + off) = *(uint4*)ll;
        }
        CP_WAIT(0);
        __syncthreads();

        #pragma unroll
        for (int ks = 0; ks < 4; ks++) {
            uint32_t fah[4], fal[4];
            {
                uint32_t off = swz(wm * 16 + farow, ks * 2 + facol);
                LDMX4(fah, sbase + off);
                LDMX4(fal, sbase + 8192 + off);
            }
            #pragma unroll
            for (int half = 0; half < 2; half++) {
                int rowB = ks * 16 + bkr;
                int cB = wn * 4 + half * 2 + bco;
                uint32_t off = (uint32_t)(rowB * 256 + ((cB ^ (rowB & 15)) << 4));
                uint32_t fbh[4], fbl[4];
                LDMX4T(fbh, sbase + 16384 + off);
                LDMX4T(fbl, sbase + 32768 + off);
                MMA16816(acc[half * 2],     fah, fbh[0], fbh[1]);
                MMA16816(acc[half * 2 + 1], fah, fbh[2], fbh[3]);
                MMA16816(acc[half * 2],     fah, fbl[0], fbl[1]);
                MMA16816(acc[half * 2 + 1], fah, fbl[2], fbl[3]);
                MMA16816(acc[half * 2],     fal, fbh[0], fbh[1]);
                MMA16816(acc[half * 2 + 1], fal, fbh[2], fbh[3]);
            }
        }
    }

    const int erow = lane >> 2;
    const int ecol = (lane & 3) * 2;
    #pragma unroll
    for (int nj = 0; nj < 4; nj++) {
        int m0 = r0 + wm * 16 + erow;
        int n0 = c0 + wn * 32 + nj * 8 + ecol;
        __nv_bfloat16 h0, l0, h1, l1;
        split2(acc[nj][0], h0, l0); split2(acc[nj][1], h1, l1);
        *(__nv_bfloat162*)(oh + (size_t)m0 * DDIM + n0) = __nv_bfloat162(h0, h1);
        *(__nv_bfloat162*)(ol + (size_t)m0 * DDIM + n0) = __nv_bfloat162(l0, l1);
        split2(acc[nj][2], h0, l0); split2(acc[nj][3], h1, l1);
        *(__nv_bfloat162*)(oh + (size_t)(m0 + 8) * DDIM + n0) = __nv_bfloat162(h0, h1);
        *(__nv_bfloat162*)(ol + (size_t)(m0 + 8) * DDIM + n0) = __nv_bfloat162(l0, l1);
    }
}

// ================= launch =================
extern "C" void kernel_launch(void* const* d_in, const int* in_sizes, int n_in,
                              void* d_out, int out_size) {
    const float* x_mole  = (const float*)d_in[0];
    const float* x_conf  = (const float*)d_in[1];
    const float* W1      = (const float*)d_in[2];
    const float* W2      = (const float*)d_in[3];
    const float* phi1_w  = (const float*)d_in[4];
    const float* phi1_b  = (const float*)d_in[5];
    const float* phi2_w  = (const float*)d_in[6];
    const float* phi2_b  = (const float*)d_in[7];
    const float* rho_w1  = (const float*)d_in[8];
    const float* rho_b1  = (const float*)d_in[9];
    const float* rho_w2  = (const float*)d_in[10];
    const float* rho_b2  = (const float*)d_in[11];
    const float* rho_ln_w = (const float*)d_in[12];
    const float* rho_ln_b = (const float*)d_in[13];
    const int*   batch   = (const int*)d_in[14];

    float* out_enc  = (float*)d_out;
    float* out_attn = (float*)d_out + (size_t)NROWS * DDIM;

    float *k;
    __nv_bfloat16 *sh1, *sl1, *sh2, *sl2, *wh, *wl, *qh, *ql, *kh, *kl, *xch, *xcl;
    cudaGetSymbolAddress((void**)&k,   g_k);
    cudaGetSymbolAddress((void**)&sh1, g_sh1);
    cudaGetSymbolAddress((void**)&sl1, g_sl1);
    cudaGetSymbolAddress((void**)&sh2, g_sh2);
    cudaGetSymbolAddress((void**)&sl2, g_sl2);
    cudaGetSymbolAddress((void**)&wh,  g_wh);
    cudaGetSymbolAddress((void**)&wl,  g_wl);
    cudaGetSymbolAddress((void**)&qh,  g_qh);
    cudaGetSymbolAddress((void**)&ql,  g_ql);
    cudaGetSymbolAddress((void**)&kh,  g_kh);
    cudaGetSymbolAddress((void**)&kl,  g_kl);
    cudaGetSymbolAddress((void**)&xch, g_xch);
    cudaGetSymbolAddress((void**)&xcl, g_xcl);
    const size_t WSZ = (size_t)DDIM * DDIM;

    cudaFuncSetAttribute(gemm_mma, cudaFuncAttributeMaxDynamicSharedMemorySize, GM_SMEM);
    cudaFuncSetAttribute(attn_softmax_mma, cudaFuncAttributeMaxDynamicSharedMemorySize, AS_SMEM);
    cudaFuncSetAttribute(attn_apply_mma, cudaFuncAttributeMaxDynamicSharedMemorySize, AP_SMEM);

    dim3 ggrid1(DDIM / 128, NROWS / 128, 1);
    dim3 ggrid2(DDIM / 128, NROWS / 128, 2);
    dim3 lgrid(NROWS / 2, 2, 1);
    dim3 agrid(NROWS / 64, 4, 1);

    // 1: weight splits   2: segments   3: LN+splits (+raw xc split)
    w_split_all<<<1024, 256>>>(W1, W2, rho_w1, rho_w2, wh, wl);
    seg_kernel<<<NROWS / 256, 256>>>(batch);
    ln_split2<<<lgrid, 256>>>(x_mole, phi1_w, phi1_b, sh1, sl1,
                              x_conf, phi2_w, phi2_b, sh2, sl2, xch, xcl);
    // 4: q + k projections + interleaved attn zero-fill (ncu position)
    gemm_mma<<<ggrid2, 512, GM_SMEM>>>(sh1, sl1, wh + 0 * WSZ, wl + 0 * WSZ, out_attn,
                                       sh2, sl2, wh + 1 * WSZ, wl + 1 * WSZ,
                                       nullptr, qh, ql, kh, kl, 3);
    // 5: tensorized masked softmax
    attn_softmax_mma<<<NROWS / 64, 512, AS_SMEM>>>(qh, ql, kh, kl, out_attn);
    // 6: tensorized apply -> bf16 split for rho1
    attn_apply_mma<<<agrid, 512, AP_SMEM>>>(out_attn, xch, xcl, sh1, sl1);

    // 7,8: rho MLP (epilogues fused)
    gemm_mma<<<ggrid1, 512, GM_SMEM>>>(sh1, sl1, wh + 2 * WSZ, wl + 2 * WSZ, nullptr,
                                       nullptr, nullptr, nullptr, nullptr,
                                       rho_b1, sh2, sl2, nullptr, nullptr, 1);
    gemm_mma<<<ggrid1, 512, GM_SMEM>>>(sh2, sl2, wh + 3 * WSZ, wl + 3 * WSZ, k,
                                       nullptr, nullptr, nullptr, nullptr,
                                       rho_b2, nullptr, nullptr, nullptr, nullptr, 2);

    // 9: final LayerNorm into output
    ln_kernel<<<NROWS / 2, 256>>>(k, rho_ln_w, rho_ln_b, out_enc);
}